// round 1
// baseline (speedup 1.0000x reference)
#include <cuda_runtime.h>
#include <cuda_bf16.h>
#include <math.h>

// ---------------- problem constants ----------------
#define BB 2
#define LL 512
#define HH 2048
#define DI 4096
#define NN 16
#define KC 4
#define RR 128
#define TT (BB*LL)           // 1024 tokens
#define E2 (2*DI)            // 8192

// ---------------- scratch (device globals; no allocs allowed) ----------------
__device__ float g_proj[TT * E2];     // in_proj output [T, 8192] (h | gate)
__device__ float g_h[TT * DI];        // post conv+silu [T, 4096]
__device__ float g_ssm[TT * (RR + 2*NN)]; // x_proj output [T, 160]
__device__ float g_dtin[TT * RR];     // rmsnorm'd dt_in [T, 128]
__device__ float g_Bn[TT * NN];       // rmsnorm'd B [T, 16]
__device__ float g_Cn[TT * NN];       // rmsnorm'd C [T, 16]
__device__ float g_dt[TT * DI];       // dt after proj (+bias, softplus) [T, 4096]
__device__ float g_y[TT * DI];        // scan output, gated [T, 4096]

// ---------------- generic NT SGEMM: C[M,Nn] = A[M,Kk] * W[Nn,Kk]^T ----------------
template<int BM, int BN, int BK, int TM, int TN>
__global__ void sgemm_nt(const float* __restrict__ A, const float* __restrict__ W,
                         float* __restrict__ C, int M, int Nn, int Kk) {
    constexpr int THREADS = (BM / TM) * (BN / TN);
    __shared__ __align__(16) float As[BK][BM];
    __shared__ __align__(16) float Ws[BK][BN];

    const int bm = blockIdx.y * BM;
    const int bn = blockIdx.x * BN;
    const int tid = threadIdx.x;
    const int tx = tid % (BN / TN);
    const int ty = tid / (BN / TN);

    float acc[TM][TN];
    #pragma unroll
    for (int i = 0; i < TM; i++)
        #pragma unroll
        for (int j = 0; j < TN; j++) acc[i][j] = 0.f;

    for (int k0 = 0; k0 < Kk; k0 += BK) {
        // load A tile (BM x BK) as float4, store transposed As[k][m]
        #pragma unroll
        for (int i = tid; i < BM * BK / 4; i += THREADS) {
            int row = i / (BK / 4);
            int kq  = i % (BK / 4);
            float4 v = *(const float4*)&A[(size_t)(bm + row) * Kk + k0 + kq * 4];
            As[kq*4+0][row] = v.x; As[kq*4+1][row] = v.y;
            As[kq*4+2][row] = v.z; As[kq*4+3][row] = v.w;
        }
        // load W tile (BN x BK)
        #pragma unroll
        for (int i = tid; i < BN * BK / 4; i += THREADS) {
            int row = i / (BK / 4);
            int kq  = i % (BK / 4);
            float4 v;
            if (bn + row < Nn) v = *(const float4*)&W[(size_t)(bn + row) * Kk + k0 + kq * 4];
            else v = make_float4(0.f, 0.f, 0.f, 0.f);
            Ws[kq*4+0][row] = v.x; Ws[kq*4+1][row] = v.y;
            Ws[kq*4+2][row] = v.z; Ws[kq*4+3][row] = v.w;
        }
        __syncthreads();

        #pragma unroll
        for (int k = 0; k < BK; k++) {
            float a[TM], w[TN];
            #pragma unroll
            for (int v = 0; v < TM; v += 4)
                *(float4*)&a[v] = *(const float4*)&As[k][ty * TM + v];
            #pragma unroll
            for (int v = 0; v < TN; v += 4)
                *(float4*)&w[v] = *(const float4*)&Ws[k][tx * TN + v];
            #pragma unroll
            for (int i = 0; i < TM; i++)
                #pragma unroll
                for (int j = 0; j < TN; j++)
                    acc[i][j] = fmaf(a[i], w[j], acc[i][j]);
        }
        __syncthreads();
    }

    #pragma unroll
    for (int i = 0; i < TM; i++) {
        int m = bm + ty * TM + i;
        #pragma unroll
        for (int j = 0; j < TN; j++) {
            int n = bn + tx * TN + j;
            if (n < Nn) C[(size_t)m * Nn + n] = acc[i][j];
        }
    }
}

// ---------------- depthwise causal conv(K=4) + bias + SiLU ----------------
__global__ void conv_silu_kernel(const float* __restrict__ cw, const float* __restrict__ cb) {
    int i = blockIdx.x * blockDim.x + threadIdx.x;
    if (i >= TT * DI) return;
    int d = i & (DI - 1);
    int t = i >> 12;               // DI = 4096 = 2^12
    int l = t & (LL - 1);
    int b = t >> 9;                // LL = 512 = 2^9
    float acc = cb[d];
    #pragma unroll
    for (int k = 0; k < KC; k++) {
        int li = l - (KC - 1) + k;
        if (li >= 0)
            acc = fmaf(g_proj[(size_t)(b * LL + li) * E2 + d], cw[d * KC + k], acc);
    }
    g_h[i] = acc / (1.f + __expf(-acc));   // silu
}

// ---------------- RMSNorm for dt_in(128), B(16), C(16) per token ----------------
__global__ void rmsnorm_kernel(const float* __restrict__ dt_w,
                               const float* __restrict__ b_w,
                               const float* __restrict__ c_w) {
    int t = blockIdx.x;
    int tid = threadIdx.x;              // 128 threads
    const float* row = g_ssm + (size_t)t * (RR + 2 * NN);

    float x = row[tid];
    float ss = x * x;
    #pragma unroll
    for (int o = 16; o > 0; o >>= 1) ss += __shfl_xor_sync(0xffffffffu, ss, o);
    __shared__ float wsum[4];
    if ((tid & 31) == 0) wsum[tid >> 5] = ss;
    __syncthreads();
    float tot = wsum[0] + wsum[1] + wsum[2] + wsum[3];
    float scale = rsqrtf(tot * (1.f / RR) + 1e-6f);
    g_dtin[(size_t)t * RR + tid] = x * scale * dt_w[tid];

    if (tid < 32) {
        int grp = tid >> 4;             // 0 = B, 1 = C
        int n = tid & 15;
        float v = row[RR + grp * NN + n];
        float vs = v * v;
        #pragma unroll
        for (int o = 8; o > 0; o >>= 1) vs += __shfl_xor_sync(0xffffffffu, vs, o);
        float sc = rsqrtf(vs * (1.f / NN) + 1e-6f);
        float w = grp ? c_w[n] : b_w[n];
        float outv = v * sc * w;
        if (grp == 0) g_Bn[(size_t)t * NN + n] = outv;
        else          g_Cn[(size_t)t * NN + n] = outv;
    }
}

// ---------------- dt bias + softplus (in place on g_dt) ----------------
__global__ void softplus_kernel(const float* __restrict__ bias) {
    int i = blockIdx.x * blockDim.x + threadIdx.x;
    if (i >= TT * DI) return;
    float x = g_dt[i] + bias[i & (DI - 1)];
    g_dt[i] = (x > 20.f) ? x : log1pf(__expf(x));
}

// ---------------- selective scan over L, fused with D-skip and gate SiLU ----------------
__global__ void scan_kernel(const float* __restrict__ A_log,
                            const float* __restrict__ D_param) {
    int b  = blockIdx.x >> 5;                 // 32 blocks per batch (DI/128)
    int d0 = (blockIdx.x & 31) * 128;
    int d  = d0 + threadIdx.x;

    float Av[NN];
    #pragma unroll
    for (int n = 0; n < NN; n++) Av[n] = -__expf(A_log[d * NN + n]);
    float state[NN];
    #pragma unroll
    for (int n = 0; n < NN; n++) state[n] = 0.f;
    float Dv = D_param[d];

    __shared__ float sB[NN], sC[NN];

    for (int l = 0; l < LL; l++) {
        int t = b * LL + l;
        __syncthreads();      // protect previous-iteration reads of sB/sC
        if (threadIdx.x < NN)            sB[threadIdx.x]      = g_Bn[(size_t)t * NN + threadIdx.x];
        else if (threadIdx.x < 2 * NN)   sC[threadIdx.x - NN] = g_Cn[(size_t)t * NN + threadIdx.x - NN];
        __syncthreads();

        float dtv = g_dt[(size_t)t * DI + d];
        float hv  = g_h [(size_t)t * DI + d];
        float dh  = dtv * hv;
        float yv = 0.f;
        #pragma unroll
        for (int n = 0; n < NN; n++) {
            float dA = __expf(dtv * Av[n]);
            state[n] = fmaf(state[n], dA, dh * sB[n]);
            yv = fmaf(state[n], sC[n], yv);
        }
        float g  = g_proj[(size_t)t * E2 + DI + d];      // gate half
        float sg = g / (1.f + __expf(-g));               // silu(gate)
        g_y[(size_t)t * DI + d] = (yv + hv * Dv) * sg;
    }
}

// ---------------- launch ----------------
extern "C" void kernel_launch(void* const* d_in, const int* in_sizes, int n_in,
                              void* d_out, int out_size) {
    const float* hs        = (const float*)d_in[0];   // [B,L,H]
    const float* in_proj_w = (const float*)d_in[1];   // [8192, 2048]
    const float* conv_w    = (const float*)d_in[2];   // [4096, 4]
    const float* conv_b    = (const float*)d_in[3];   // [4096]
    const float* x_proj_w  = (const float*)d_in[4];   // [160, 4096]
    const float* dt_ln_w   = (const float*)d_in[5];   // [128]
    const float* b_ln_w    = (const float*)d_in[6];   // [16]
    const float* c_ln_w    = (const float*)d_in[7];   // [16]
    const float* dt_proj_w = (const float*)d_in[8];   // [4096, 128]
    const float* dt_proj_b = (const float*)d_in[9];   // [4096]
    const float* A_log     = (const float*)d_in[10];  // [4096, 16]
    const float* D_param   = (const float*)d_in[11];  // [4096]
    const float* out_proj_w= (const float*)d_in[12];  // [2048, 4096]
    float* out = (float*)d_out;

    float *p_proj, *p_h, *p_ssm, *p_dtin, *p_dt, *p_y;
    cudaGetSymbolAddress((void**)&p_proj, g_proj);
    cudaGetSymbolAddress((void**)&p_h,    g_h);
    cudaGetSymbolAddress((void**)&p_ssm,  g_ssm);
    cudaGetSymbolAddress((void**)&p_dtin, g_dtin);
    cudaGetSymbolAddress((void**)&p_dt,   g_dt);
    cudaGetSymbolAddress((void**)&p_y,    g_y);

    // 1) in_proj: [1024,2048] x [8192,2048]^T -> [1024,8192]
    sgemm_nt<128,128,8,8,8><<<dim3(E2/128, TT/128), 256>>>(hs, in_proj_w, p_proj, TT, E2, HH);

    // 2) depthwise conv + silu -> g_h
    conv_silu_kernel<<<(TT*DI + 255)/256, 256>>>(conv_w, conv_b);

    // 3) x_proj: [1024,4096] x [160,4096]^T -> [1024,160]
    sgemm_nt<64,64,8,4,4><<<dim3((RR+2*NN+63)/64, TT/64), 256>>>(p_h, x_proj_w, p_ssm, TT, RR+2*NN, DI);

    // 4) rmsnorms -> g_dtin, g_Bn, g_Cn
    rmsnorm_kernel<<<TT, 128>>>(dt_ln_w, b_ln_w, c_ln_w);

    // 5) dt_proj: [1024,128] x [4096,128]^T -> [1024,4096], then bias+softplus
    sgemm_nt<128,128,8,8,8><<<dim3(DI/128, TT/128), 256>>>(p_dtin, dt_proj_w, p_dt, TT, DI, RR);
    softplus_kernel<<<(TT*DI + 255)/256, 256>>>(dt_proj_b);

    // 6) selective scan + D skip + gate silu -> g_y
    scan_kernel<<<BB * (DI/128), 128>>>(A_log, D_param);

    // 7) out_proj: [1024,4096] x [2048,4096]^T -> [1024,2048]
    sgemm_nt<128,128,8,8,8><<<dim3(HH/128, TT/128), 256>>>(p_y, out_proj_w, out, TT, HH, DI);
}

// round 2
// speedup vs baseline: 1.7668x; 1.7668x over previous
#include <cuda_runtime.h>
#include <cuda_bf16.h>
#include <math.h>
#include <stdint.h>

// ---------------- problem constants ----------------
#define BB 2
#define LL 512
#define HH 2048
#define DI 4096
#define NN 16
#define KC 4
#define RR 128
#define TT (BB*LL)           // 1024 tokens
#define E2 (2*DI)            // 8192

// ---------------- scratch (device globals; no allocs allowed) ----------------
__device__ float g_proj[TT * E2];     // in_proj output [T, 8192] (h | gate)
__device__ float g_h[TT * DI];        // post conv+silu [T, 4096]
__device__ float g_ssm[TT * (RR + 2*NN)]; // x_proj output [T, 160]
__device__ float g_dtin[TT * RR];     // rmsnorm'd dt_in [T, 128]
__device__ float g_Bn[TT * NN];       // rmsnorm'd B [T, 16]
__device__ float g_Cn[TT * NN];       // rmsnorm'd C [T, 16]
__device__ float g_dt[TT * DI];       // dt after proj (+bias, softplus) [T, 4096]
__device__ float g_y[TT * DI];        // scan output, gated [T, 4096]

// ================= bf16-split tensor-core NT GEMM =================
// C[M,Nn] = A[M,Kk] * W[Nn,Kk]^T in ~fp32 precision via
// A ~= Ah + Al (bf16 each), product = Ah*Bh + Ah*Bl + Al*Bh.
// Tiles: BM=BN=128, BK=32; 256 threads = 8 warps, warp tile 64x32.
#define GBM 128
#define GBN 128
#define GBK 32
#define KST 40   // smem row stride in bf16 elems (32 + 8 pad -> conflict-free frags)

#define MMA_BF16(d, a, b)                                                     \
  asm volatile("mma.sync.aligned.m16n8k16.row.col.f32.bf16.bf16.f32 "        \
               "{%0,%1,%2,%3}, {%4,%5,%6,%7}, {%8,%9}, {%0,%1,%2,%3};"       \
               : "+f"(d[0]), "+f"(d[1]), "+f"(d[2]), "+f"(d[3])              \
               : "r"(a[0]), "r"(a[1]), "r"(a[2]), "r"(a[3]),                 \
                 "r"(b[0]), "r"(b[1]))

__device__ __forceinline__ void cvt_split4(float4 v, uint2& hi, uint2& lo) {
    float f[4] = {v.x, v.y, v.z, v.w};
    unsigned short h[4], l[4];
#pragma unroll
    for (int j = 0; j < 4; j++) {
        __nv_bfloat16 hb = __float2bfloat16(f[j]);
        __nv_bfloat16 lb = __float2bfloat16(f[j] - __bfloat162float(hb));
        h[j] = __bfloat16_as_ushort(hb);
        l[j] = __bfloat16_as_ushort(lb);
    }
    hi.x = (uint32_t)h[0] | ((uint32_t)h[1] << 16);
    hi.y = (uint32_t)h[2] | ((uint32_t)h[3] << 16);
    lo.x = (uint32_t)l[0] | ((uint32_t)l[1] << 16);
    lo.y = (uint32_t)l[2] | ((uint32_t)l[3] << 16);
}

__global__ __launch_bounds__(256, 1)
void mma_gemm_nt(const float* __restrict__ A, const float* __restrict__ W,
                 float* __restrict__ C, int M, int Nn, int Kk) {
    __shared__ __nv_bfloat16 Ah[GBM * KST], Al[GBM * KST];
    __shared__ __nv_bfloat16 Bh[GBN * KST], Bl[GBN * KST];

    const int tid = threadIdx.x;
    const int bm = blockIdx.y * GBM;
    const int bn = blockIdx.x * GBN;

    // gmem staging: each thread loads 4 float4 of A and of W per BK step
    const int ldr = tid >> 3;            // 0..31
    const int ldk = (tid & 7) * 4;       // 0..28
    float4 ra[4], rb[4];

    // warp/fragment geometry
    const int lane = tid & 31;
    const int wid = tid >> 5;
    const int wm = (wid >> 2) * 64;      // warp m offset
    const int wn = (wid & 3) * 32;       // warp n offset
    const int qk = (lane & 3) * 2;       // k pair offset within frag
    const int lr = lane >> 2;            // 0..7

    float acc[4][4][4];
#pragma unroll
    for (int mt = 0; mt < 4; mt++)
#pragma unroll
        for (int nt = 0; nt < 4; nt++)
#pragma unroll
            for (int j = 0; j < 4; j++) acc[mt][nt][j] = 0.f;

    // prologue load
    {
        const int k0 = 0;
#pragma unroll
        for (int i = 0; i < 4; i++) {
            int row = ldr + 32 * i;
            ra[i] = *(const float4*)&A[(size_t)(bm + row) * Kk + k0 + ldk];
            int n = bn + row;
            rb[i] = (n < Nn) ? *(const float4*)&W[(size_t)n * Kk + k0 + ldk]
                             : make_float4(0.f, 0.f, 0.f, 0.f);
        }
    }

    for (int k0 = 0; k0 < Kk; k0 += GBK) {
        // convert + store staged tile to smem
#pragma unroll
        for (int i = 0; i < 4; i++) {
            int row = ldr + 32 * i;
            uint2 hi, lo;
            cvt_split4(ra[i], hi, lo);
            *(uint2*)&Ah[row * KST + ldk] = hi;
            *(uint2*)&Al[row * KST + ldk] = lo;
            cvt_split4(rb[i], hi, lo);
            *(uint2*)&Bh[row * KST + ldk] = hi;
            *(uint2*)&Bl[row * KST + ldk] = lo;
        }
        __syncthreads();

        // prefetch next tile while computing
        if (k0 + GBK < Kk) {
            int kn = k0 + GBK;
#pragma unroll
            for (int i = 0; i < 4; i++) {
                int row = ldr + 32 * i;
                ra[i] = *(const float4*)&A[(size_t)(bm + row) * Kk + kn + ldk];
                int n = bn + row;
                rb[i] = (n < Nn) ? *(const float4*)&W[(size_t)n * Kk + kn + ldk]
                                 : make_float4(0.f, 0.f, 0.f, 0.f);
            }
        }

        // compute: 2 k16 substeps
#pragma unroll
        for (int ks = 0; ks < 2; ks++) {
            const int kb = ks * 16 + qk;
            uint32_t ahi[4][4], alo[4][4], bhi[4][2], blo[4][2];
#pragma unroll
            for (int mt = 0; mt < 4; mt++) {
                int r = wm + mt * 16 + lr;
                ahi[mt][0] = *(const uint32_t*)&Ah[r * KST + kb];
                ahi[mt][1] = *(const uint32_t*)&Ah[(r + 8) * KST + kb];
                ahi[mt][2] = *(const uint32_t*)&Ah[r * KST + kb + 8];
                ahi[mt][3] = *(const uint32_t*)&Ah[(r + 8) * KST + kb + 8];
                alo[mt][0] = *(const uint32_t*)&Al[r * KST + kb];
                alo[mt][1] = *(const uint32_t*)&Al[(r + 8) * KST + kb];
                alo[mt][2] = *(const uint32_t*)&Al[r * KST + kb + 8];
                alo[mt][3] = *(const uint32_t*)&Al[(r + 8) * KST + kb + 8];
            }
#pragma unroll
            for (int nt = 0; nt < 4; nt++) {
                int cc = wn + nt * 8 + lr;
                bhi[nt][0] = *(const uint32_t*)&Bh[cc * KST + kb];
                bhi[nt][1] = *(const uint32_t*)&Bh[cc * KST + kb + 8];
                blo[nt][0] = *(const uint32_t*)&Bl[cc * KST + kb];
                blo[nt][1] = *(const uint32_t*)&Bl[cc * KST + kb + 8];
            }
#pragma unroll
            for (int mt = 0; mt < 4; mt++)
#pragma unroll
                for (int nt = 0; nt < 4; nt++) {
                    MMA_BF16(acc[mt][nt], ahi[mt], bhi[nt]);
                    MMA_BF16(acc[mt][nt], ahi[mt], blo[nt]);
                    MMA_BF16(acc[mt][nt], alo[mt], bhi[nt]);
                }
        }
        __syncthreads();
    }

    // epilogue
#pragma unroll
    for (int mt = 0; mt < 4; mt++) {
        int r = bm + wm + mt * 16 + lr;
#pragma unroll
        for (int nt = 0; nt < 4; nt++) {
            int c = bn + wn + nt * 8 + qk;
            if (c < Nn) {
                *(float2*)&C[(size_t)r * Nn + c] =
                    make_float2(acc[mt][nt][0], acc[mt][nt][1]);
                *(float2*)&C[(size_t)(r + 8) * Nn + c] =
                    make_float2(acc[mt][nt][2], acc[mt][nt][3]);
            }
        }
    }
}

// ---------------- depthwise causal conv(K=4) + bias + SiLU ----------------
__global__ void conv_silu_kernel(const float* __restrict__ cw, const float* __restrict__ cb) {
    int i = blockIdx.x * blockDim.x + threadIdx.x;
    if (i >= TT * DI) return;
    int d = i & (DI - 1);
    int t = i >> 12;
    int l = t & (LL - 1);
    int b = t >> 9;
    float acc = cb[d];
#pragma unroll
    for (int k = 0; k < KC; k++) {
        int li = l - (KC - 1) + k;
        if (li >= 0)
            acc = fmaf(g_proj[(size_t)(b * LL + li) * E2 + d], cw[d * KC + k], acc);
    }
    g_h[i] = acc / (1.f + __expf(-acc));
}

// ---------------- RMSNorm for dt_in(128), B(16), C(16) per token ----------------
__global__ void rmsnorm_kernel(const float* __restrict__ dt_w,
                               const float* __restrict__ b_w,
                               const float* __restrict__ c_w) {
    int t = blockIdx.x;
    int tid = threadIdx.x;              // 128 threads
    const float* row = g_ssm + (size_t)t * (RR + 2 * NN);

    float x = row[tid];
    float ss = x * x;
#pragma unroll
    for (int o = 16; o > 0; o >>= 1) ss += __shfl_xor_sync(0xffffffffu, ss, o);
    __shared__ float wsum[4];
    if ((tid & 31) == 0) wsum[tid >> 5] = ss;
    __syncthreads();
    float tot = wsum[0] + wsum[1] + wsum[2] + wsum[3];
    float scale = rsqrtf(tot * (1.f / RR) + 1e-6f);
    g_dtin[(size_t)t * RR + tid] = x * scale * dt_w[tid];

    if (tid < 32) {
        int grp = tid >> 4;
        int n = tid & 15;
        float v = row[RR + grp * NN + n];
        float vs = v * v;
#pragma unroll
        for (int o = 8; o > 0; o >>= 1) vs += __shfl_xor_sync(0xffffffffu, vs, o);
        float sc = rsqrtf(vs * (1.f / NN) + 1e-6f);
        float w = grp ? c_w[n] : b_w[n];
        float outv = v * sc * w;
        if (grp == 0) g_Bn[(size_t)t * NN + n] = outv;
        else          g_Cn[(size_t)t * NN + n] = outv;
    }
}

// ---------------- dt bias + softplus (in place on g_dt) ----------------
__global__ void softplus_kernel(const float* __restrict__ bias) {
    int i = blockIdx.x * blockDim.x + threadIdx.x;
    if (i >= TT * DI) return;
    float x = g_dt[i] + bias[i & (DI - 1)];
    g_dt[i] = (x > 20.f) ? x : log1pf(__expf(x));
}

// ---------------- selective scan, depth-2 prefetch, 64 threads/block ----------------
__global__ void scan_kernel(const float* __restrict__ A_log,
                            const float* __restrict__ D_param) {
    const int b  = blockIdx.x >> 6;              // 64 blocks per batch (DI/64)
    const int d  = (blockIdx.x & 63) * 64 + threadIdx.x;
    const int tid = threadIdx.x;

    float Av[NN];
#pragma unroll
    for (int n = 0; n < NN; n++) Av[n] = -__expf(A_log[d * NN + n]);
    float state[NN];
#pragma unroll
    for (int n = 0; n < NN; n++) state[n] = 0.f;
    const float Dv = D_param[d];

    __shared__ float sBC[2][2 * NN];   // [buf][ B(0..15) | C(16..31) ]

    float dtv[2], hv[2], gv[2], bc[2];

    auto issue = [&](int slot, int l) {
        int t = b * LL + l;
        dtv[slot] = g_dt[(size_t)t * DI + d];
        hv[slot]  = g_h [(size_t)t * DI + d];
        gv[slot]  = g_proj[(size_t)t * E2 + DI + d];
        if (tid < 32)
            bc[slot] = (tid < NN) ? g_Bn[(size_t)t * NN + tid]
                                  : g_Cn[(size_t)t * NN + (tid - NN)];
    };

    issue(0, 0);
    issue(1, 1);
    if (tid < 32) { sBC[0][tid] = bc[0]; sBC[1][tid] = bc[1]; }
    __syncthreads();

    for (int l = 0; l < LL; l++) {
        const int s = l & 1;
        const float cdt = dtv[s], ch = hv[s], cg = gv[s];
        const bool pf = (l + 2 < LL);
        if (pf) issue(s, l + 2);

        const float dh = cdt * ch;
        float yv = 0.f;
#pragma unroll
        for (int n = 0; n < NN; n++) {
            float dA = __expf(cdt * Av[n]);
            state[n] = fmaf(state[n], dA, dh * sBC[s][n]);
            yv = fmaf(state[n], sBC[s][NN + n], yv);
        }
        float sg = cg / (1.f + __expf(-cg));
        int t = b * LL + l;
        g_y[(size_t)t * DI + d] = (yv + ch * Dv) * sg;

        __syncthreads();
        if (pf && tid < 32) sBC[s][tid] = bc[s];
    }
}

// ---------------- launch ----------------
extern "C" void kernel_launch(void* const* d_in, const int* in_sizes, int n_in,
                              void* d_out, int out_size) {
    const float* hs        = (const float*)d_in[0];
    const float* in_proj_w = (const float*)d_in[1];
    const float* conv_w    = (const float*)d_in[2];
    const float* conv_b    = (const float*)d_in[3];
    const float* x_proj_w  = (const float*)d_in[4];
    const float* dt_ln_w   = (const float*)d_in[5];
    const float* b_ln_w    = (const float*)d_in[6];
    const float* c_ln_w    = (const float*)d_in[7];
    const float* dt_proj_w = (const float*)d_in[8];
    const float* dt_proj_b = (const float*)d_in[9];
    const float* A_log     = (const float*)d_in[10];
    const float* D_param   = (const float*)d_in[11];
    const float* out_proj_w= (const float*)d_in[12];
    float* out = (float*)d_out;

    float *p_proj, *p_h, *p_ssm, *p_dtin, *p_dt, *p_y;
    cudaGetSymbolAddress((void**)&p_proj, g_proj);
    cudaGetSymbolAddress((void**)&p_h,    g_h);
    cudaGetSymbolAddress((void**)&p_ssm,  g_ssm);
    cudaGetSymbolAddress((void**)&p_dtin, g_dtin);
    cudaGetSymbolAddress((void**)&p_dt,   g_dt);
    cudaGetSymbolAddress((void**)&p_y,    g_y);

    // 1) in_proj: [1024,2048] x [8192,2048]^T -> [1024,8192]
    mma_gemm_nt<<<dim3(E2/GBN, TT/GBM), 256>>>(hs, in_proj_w, p_proj, TT, E2, HH);

    // 2) depthwise conv + silu -> g_h
    conv_silu_kernel<<<(TT*DI + 255)/256, 256>>>(conv_w, conv_b);

    // 3) x_proj: [1024,4096] x [160,4096]^T -> [1024,160]
    mma_gemm_nt<<<dim3((RR + 2*NN + GBN - 1)/GBN, TT/GBM), 256>>>(p_h, x_proj_w, p_ssm, TT, RR + 2*NN, DI);

    // 4) rmsnorms -> g_dtin, g_Bn, g_Cn
    rmsnorm_kernel<<<TT, 128>>>(dt_ln_w, b_ln_w, c_ln_w);

    // 5) dt_proj: [1024,128] x [4096,128]^T -> [1024,4096], then bias+softplus
    mma_gemm_nt<<<dim3(DI/GBN, TT/GBM), 256>>>(p_dtin, dt_proj_w, p_dt, TT, DI, RR);
    softplus_kernel<<<(TT*DI + 255)/256, 256>>>(dt_proj_b);

    // 6) selective scan + D skip + gate silu -> g_y
    scan_kernel<<<BB * (DI/64), 64>>>(A_log, D_param);

    // 7) out_proj: [1024,4096] x [2048,4096]^T -> [1024,2048]
    mma_gemm_nt<<<dim3(HH/GBN, TT/GBM), 256>>>(p_y, out_proj_w, out, TT, HH, DI);
}

// round 4
// speedup vs baseline: 1.9256x; 1.0899x over previous
#include <cuda_runtime.h>
#include <cuda_bf16.h>
#include <math.h>
#include <stdint.h>

// ---------------- problem constants ----------------
#define BB 2
#define LL 512
#define HH 2048
#define DI 4096
#define NN 16
#define KC 4
#define RR 128
#define TT (BB*LL)           // 1024 tokens
#define E2 (2*DI)            // 8192
#define NSSM (RR + 2*NN)     // 160

// ---------------- fp32 scratch ----------------
__device__ float g_proj[TT * E2];     // in_proj output [T, 8192] (h | gate)
__device__ float g_h[TT * DI];        // post conv+silu fp32 (for scan)
__device__ float g_ssm[TT * NSSM];    // x_proj output [T, 160]
__device__ float g_Bn[TT * NN];
__device__ float g_Cn[TT * NN];
__device__ float g_dt[TT * DI];       // dt after proj (+bias, softplus)

// ---------------- bf16 hi/lo split operands ----------------
__device__ __nv_bfloat16 c_hs_h[TT * HH],  c_hs_l[TT * HH];
__device__ __nv_bfloat16 c_inw_h[E2 * HH], c_inw_l[E2 * HH];
__device__ __nv_bfloat16 c_h_h[TT * DI],   c_h_l[TT * DI];
__device__ __nv_bfloat16 c_xw_h[NSSM * DI], c_xw_l[NSSM * DI];
__device__ __nv_bfloat16 c_dtin_h[TT * RR], c_dtin_l[TT * RR];
__device__ __nv_bfloat16 c_dtw_h[DI * RR],  c_dtw_l[DI * RR];
__device__ __nv_bfloat16 c_y_h[TT * DI],    c_y_l[TT * DI];
__device__ __nv_bfloat16 c_ow_h[HH * DI],   c_ow_l[HH * DI];

// ---------------- helpers ----------------
__device__ __forceinline__ uint32_t smem_u32(const void* p) {
    uint32_t a;
    asm("{ .reg .u64 t; cvta.to.shared.u64 t, %1; cvt.u32.u64 %0, t; }" : "=r"(a) : "l"(p));
    return a;
}
__device__ __forceinline__ void split1(float f, __nv_bfloat16& h, __nv_bfloat16& l) {
    h = __float2bfloat16(f);
    l = __float2bfloat16(f - __bfloat162float(h));
}
__device__ __forceinline__ void cp16(uint32_t dst, const void* src, bool pred) {
    int sz = pred ? 16 : 0;
    asm volatile("cp.async.cg.shared.global [%0], [%1], 16, %2;"
                 :: "r"(dst), "l"(src), "r"(sz) : "memory");
}
__device__ __forceinline__ void cp_commit() {
    asm volatile("cp.async.commit_group;" ::: "memory");
}
__device__ __forceinline__ void cp_wait2() {
    asm volatile("cp.async.wait_group 2;" ::: "memory");
}

#define MMA_BF16(d, a, b)                                                     \
  asm volatile("mma.sync.aligned.m16n8k16.row.col.f32.bf16.bf16.f32 "        \
               "{%0,%1,%2,%3}, {%4,%5,%6,%7}, {%8,%9}, {%0,%1,%2,%3};"       \
               : "+f"(d[0]), "+f"(d[1]), "+f"(d[2]), "+f"(d[3])              \
               : "r"(a[0]), "r"(a[1]), "r"(a[2]), "r"(a[3]),                 \
                 "r"(b[0]), "r"(b[1]))

#define LDSM4(r0, r1, r2, r3, addr)                                           \
  asm volatile("ldmatrix.sync.aligned.m8n8.x4.shared.b16 {%0,%1,%2,%3}, [%4];"\
               : "=r"(r0), "=r"(r1), "=r"(r2), "=r"(r3) : "r"(addr))

__device__ __forceinline__ uint32_t swz64(uint32_t off) {
    return off ^ ((off >> 3) & 0x30);   // SW64: conflict-free 64B rows
}

// ---------------- fp32 -> bf16 hi/lo conversion ----------------
__global__ void cvt_split_kernel(const float* __restrict__ src,
                                 __nv_bfloat16* __restrict__ hi,
                                 __nv_bfloat16* __restrict__ lo, int n4) {
    int i = blockIdx.x * blockDim.x + threadIdx.x;
    if (i >= n4) return;
    float4 v = ((const float4*)src)[i];
    __nv_bfloat16 h[4], l[4];
    split1(v.x, h[0], l[0]); split1(v.y, h[1], l[1]);
    split1(v.z, h[2], l[2]); split1(v.w, h[3], l[3]);
    ((uint2*)hi)[i] = *(uint2*)h;
    ((uint2*)lo)[i] = *(uint2*)l;
}

// ================= mma.sync NT GEMM with cp.async + ldmatrix =================
// C[M,Nn] = A[M,Kk] * W[Nn,Kk]^T, operands pre-split bf16 hi/lo.
// 3-term: AhBh + AhBl + AlBh. Tile 128x128xBK32, 8 warps (64x32 warp tiles),
// 3-stage cp.async pipeline, SW64 swizzled smem, ldmatrix.x4 fragment loads.
#define OPB (128 * 64)          // bytes per operand per stage (128 rows x 64B)
#define STG (4 * OPB)           // Ah|Al|Bh|Bl = 32 KB
#define NSTAGE 3
#define GEMM_SMEM (NSTAGE * STG)

__global__ __launch_bounds__(256)
void tc_gemm(const __nv_bfloat16* __restrict__ Ah, const __nv_bfloat16* __restrict__ Al,
             const __nv_bfloat16* __restrict__ Wh, const __nv_bfloat16* __restrict__ Wl,
             float* __restrict__ C, int Nn, int Kk) {
    extern __shared__ __align__(1024) char dsm[];
    const uint32_t sbase = smem_u32(dsm);

    const int tid = threadIdx.x;
    const int lane = tid & 31;
    const int wid = tid >> 5;
    const int bm = blockIdx.y * 128;
    const int bn = blockIdx.x * 128;
    const int wm = (wid >> 2) * 64;
    const int wn = (wid & 3) * 32;
    const int qk = (lane & 3) * 2;
    const int lr = lane >> 2;

    const __nv_bfloat16* srcs[4] = { Ah, Al, Wh, Wl };

    auto load_stage = [&](int s, int kc) {
        const int k0 = kc * 32;
        const uint32_t stg = sbase + s * STG;
#pragma unroll
        for (int t = 0; t < 4; t++) {
            const __nv_bfloat16* sp = srcs[t];
            const int r0 = (t < 2) ? bm : bn;
            const bool isB = (t >= 2);
#pragma unroll
            for (int i = 0; i < 2; i++) {
                int idx = i * 256 + tid;         // 0..511
                int row = idx >> 2, c = idx & 3;
                int gr = r0 + row;
                bool ok = (!isB) || (gr < Nn);
                uint32_t dst = stg + t * OPB + swz64((uint32_t)(row * 64 + c * 16));
                cp16(dst, sp + (size_t)gr * Kk + k0 + c * 8, ok);
            }
        }
    };

    float acc[4][4][4];
#pragma unroll
    for (int mt = 0; mt < 4; mt++)
#pragma unroll
        for (int nt = 0; nt < 4; nt++)
#pragma unroll
            for (int j = 0; j < 4; j++) acc[mt][nt][j] = 0.f;

    const int nk = Kk / 32;

    // prologue: fill 3 stages
#pragma unroll
    for (int s = 0; s < NSTAGE; s++) { load_stage(s, s); cp_commit(); }

    const int rA = lane & 15;           // ldmatrix row within 16
    const int cHi = lane >> 4;          // ldmatrix chunk select

    for (int kc = 0; kc < nk; kc++) {
        const int s = kc % NSTAGE;
        cp_wait2();
        __syncthreads();

        const uint32_t stg = sbase + s * STG;
#pragma unroll
        for (int ks = 0; ks < 2; ks++) {
            const int c0 = ks * 2 + cHi;
            uint32_t ah[4][4], al[4][4], bh[4][2], bl[4][2];
#pragma unroll
            for (int mt = 0; mt < 4; mt++) {
                uint32_t off = swz64((uint32_t)((wm + mt * 16 + rA) * 64 + c0 * 16));
                LDSM4(ah[mt][0], ah[mt][1], ah[mt][2], ah[mt][3], stg + off);
                LDSM4(al[mt][0], al[mt][1], al[mt][2], al[mt][3], stg + OPB + off);
            }
#pragma unroll
            for (int p = 0; p < 2; p++) {
                uint32_t off = swz64((uint32_t)((wn + p * 16 + rA) * 64 + c0 * 16));
                uint32_t r0, r1, r2, r3;
                LDSM4(r0, r1, r2, r3, stg + 2 * OPB + off);
                bh[2*p][0] = r0; bh[2*p+1][0] = r1; bh[2*p][1] = r2; bh[2*p+1][1] = r3;
                LDSM4(r0, r1, r2, r3, stg + 3 * OPB + off);
                bl[2*p][0] = r0; bl[2*p+1][0] = r1; bl[2*p][1] = r2; bl[2*p+1][1] = r3;
            }
#pragma unroll
            for (int mt = 0; mt < 4; mt++)
#pragma unroll
                for (int nt = 0; nt < 4; nt++) {
                    MMA_BF16(acc[mt][nt], ah[mt], bh[nt]);
                    MMA_BF16(acc[mt][nt], ah[mt], bl[nt]);
                    MMA_BF16(acc[mt][nt], al[mt], bh[nt]);
                }
        }
        __syncthreads();
        int kn = kc + NSTAGE;
        if (kn < nk) load_stage(s, kn);
        cp_commit();
    }

    // epilogue
#pragma unroll
    for (int mt = 0; mt < 4; mt++) {
        int r = bm + wm + mt * 16 + lr;
#pragma unroll
        for (int nt = 0; nt < 4; nt++) {
            int c = bn + wn + nt * 8 + qk;
            if (c < Nn) {
                *(float2*)&C[(size_t)r * Nn + c] =
                    make_float2(acc[mt][nt][0], acc[mt][nt][1]);
                *(float2*)&C[(size_t)(r + 8) * Nn + c] =
                    make_float2(acc[mt][nt][2], acc[mt][nt][3]);
            }
        }
    }
}

// ---------------- depthwise causal conv(K=4) + bias + SiLU (+ bf16 split out) ------
__global__ void conv_silu_kernel(const float* __restrict__ cw, const float* __restrict__ cb) {
    int i = blockIdx.x * blockDim.x + threadIdx.x;
    if (i >= TT * DI) return;
    int d = i & (DI - 1);
    int t = i >> 12;
    int l = t & (LL - 1);
    int b = t >> 9;
    float acc = cb[d];
#pragma unroll
    for (int k = 0; k < KC; k++) {
        int li = l - (KC - 1) + k;
        if (li >= 0)
            acc = fmaf(g_proj[(size_t)(b * LL + li) * E2 + d], cw[d * KC + k], acc);
    }
    float s = acc / (1.f + __expf(-acc));
    g_h[i] = s;
    __nv_bfloat16 h, lo2; split1(s, h, lo2);
    c_h_h[i] = h; c_h_l[i] = lo2;
}

// ---------------- RMSNorm for dt_in(128), B(16), C(16) per token ----------------
__global__ void rmsnorm_kernel(const float* __restrict__ dt_w,
                               const float* __restrict__ b_w,
                               const float* __restrict__ c_w) {
    int t = blockIdx.x;
    int tid = threadIdx.x;              // 128 threads
    const float* row = g_ssm + (size_t)t * NSSM;

    float x = row[tid];
    float ss = x * x;
#pragma unroll
    for (int o = 16; o > 0; o >>= 1) ss += __shfl_xor_sync(0xffffffffu, ss, o);
    __shared__ float wsum[4];
    if ((tid & 31) == 0) wsum[tid >> 5] = ss;
    __syncthreads();
    float tot = wsum[0] + wsum[1] + wsum[2] + wsum[3];
    float scale = rsqrtf(tot * (1.f / RR) + 1e-6f);
    float o1 = x * scale * dt_w[tid];
    __nv_bfloat16 h, lo2; split1(o1, h, lo2);
    c_dtin_h[(size_t)t * RR + tid] = h;
    c_dtin_l[(size_t)t * RR + tid] = lo2;

    if (tid < 32) {
        int grp = tid >> 4;
        int n = tid & 15;
        float v = row[RR + grp * NN + n];
        float vs = v * v;
#pragma unroll
        for (int o = 8; o > 0; o >>= 1) vs += __shfl_xor_sync(0xffffffffu, vs, o);
        float sc = rsqrtf(vs * (1.f / NN) + 1e-6f);
        float w = grp ? c_w[n] : b_w[n];
        float outv = v * sc * w;
        if (grp == 0) g_Bn[(size_t)t * NN + n] = outv;
        else          g_Cn[(size_t)t * NN + n] = outv;
    }
}

// ---------------- dt bias + softplus (in place on g_dt) ----------------
__global__ void softplus_kernel(const float* __restrict__ bias) {
    int i = blockIdx.x * blockDim.x + threadIdx.x;
    if (i >= TT * DI) return;
    float x = g_dt[i] + bias[i & (DI - 1)];
    g_dt[i] = (x > 20.f) ? x : log1pf(__expf(x));
}

// ---------------- selective scan, depth-2 prefetch ----------------
__global__ void scan_kernel(const float* __restrict__ A_log,
                            const float* __restrict__ D_param) {
    const int b  = blockIdx.x >> 6;              // 64 blocks per batch (DI/64)
    const int d  = (blockIdx.x & 63) * 64 + threadIdx.x;
    const int tid = threadIdx.x;

    float Av[NN];
#pragma unroll
    for (int n = 0; n < NN; n++) Av[n] = -__expf(A_log[d * NN + n]);
    float state[NN];
#pragma unroll
    for (int n = 0; n < NN; n++) state[n] = 0.f;
    const float Dv = D_param[d];

    __shared__ float sBC[2][2 * NN];

    float dtv[2], hv[2], gv[2], bc[2];

    auto issue = [&](int slot, int l) {
        int t = b * LL + l;
        dtv[slot] = g_dt[(size_t)t * DI + d];
        hv[slot]  = g_h [(size_t)t * DI + d];
        gv[slot]  = g_proj[(size_t)t * E2 + DI + d];
        if (tid < 32)
            bc[slot] = (tid < NN) ? g_Bn[(size_t)t * NN + tid]
                                  : g_Cn[(size_t)t * NN + (tid - NN)];
    };

    issue(0, 0);
    issue(1, 1);
    if (tid < 32) { sBC[0][tid] = bc[0]; sBC[1][tid] = bc[1]; }
    __syncthreads();

    for (int l = 0; l < LL; l++) {
        const int s = l & 1;
        const float cdt = dtv[s], ch = hv[s], cg = gv[s];
        const bool pf = (l + 2 < LL);
        if (pf) issue(s, l + 2);

        const float dh = cdt * ch;
        float yv = 0.f;
#pragma unroll
        for (int n = 0; n < NN; n++) {
            float dA = __expf(cdt * Av[n]);
            state[n] = fmaf(state[n], dA, dh * sBC[s][n]);
            yv = fmaf(state[n], sBC[s][NN + n], yv);
        }
        float sg = cg / (1.f + __expf(-cg));
        int t = b * LL + l;
        float yo = (yv + ch * Dv) * sg;
        __nv_bfloat16 h, lo2; split1(yo, h, lo2);
        c_y_h[(size_t)t * DI + d] = h;
        c_y_l[(size_t)t * DI + d] = lo2;

        __syncthreads();
        if (pf && tid < 32) sBC[s][tid] = bc[s];
    }
}

// ---------------- launch ----------------
extern "C" void kernel_launch(void* const* d_in, const int* in_sizes, int n_in,
                              void* d_out, int out_size) {
    const float* hs        = (const float*)d_in[0];
    const float* in_proj_w = (const float*)d_in[1];
    const float* conv_w    = (const float*)d_in[2];
    const float* conv_b    = (const float*)d_in[3];
    const float* x_proj_w  = (const float*)d_in[4];
    const float* dt_ln_w   = (const float*)d_in[5];
    const float* b_ln_w    = (const float*)d_in[6];
    const float* c_ln_w    = (const float*)d_in[7];
    const float* dt_proj_w = (const float*)d_in[8];
    const float* dt_proj_b = (const float*)d_in[9];
    const float* A_log     = (const float*)d_in[10];
    const float* D_param   = (const float*)d_in[11];
    const float* out_proj_w= (const float*)d_in[12];
    float* out = (float*)d_out;

    cudaFuncSetAttribute(tc_gemm, cudaFuncAttributeMaxDynamicSharedMemorySize, GEMM_SMEM);

    float *p_proj, *p_ssm, *p_dt;
    cudaGetSymbolAddress((void**)&p_proj, g_proj);
    cudaGetSymbolAddress((void**)&p_ssm,  g_ssm);
    cudaGetSymbolAddress((void**)&p_dt,   g_dt);
    __nv_bfloat16 *hs_h, *hs_l, *inw_h, *inw_l, *h_h, *h_l, *xw_h, *xw_l;
    __nv_bfloat16 *dtin_h, *dtin_l, *dtw_h, *dtw_l, *y_h, *y_l, *ow_h, *ow_l;
    cudaGetSymbolAddress((void**)&hs_h, c_hs_h);   cudaGetSymbolAddress((void**)&hs_l, c_hs_l);
    cudaGetSymbolAddress((void**)&inw_h, c_inw_h); cudaGetSymbolAddress((void**)&inw_l, c_inw_l);
    cudaGetSymbolAddress((void**)&h_h, c_h_h);     cudaGetSymbolAddress((void**)&h_l, c_h_l);
    cudaGetSymbolAddress((void**)&xw_h, c_xw_h);   cudaGetSymbolAddress((void**)&xw_l, c_xw_l);
    cudaGetSymbolAddress((void**)&dtin_h, c_dtin_h); cudaGetSymbolAddress((void**)&dtin_l, c_dtin_l);
    cudaGetSymbolAddress((void**)&dtw_h, c_dtw_h); cudaGetSymbolAddress((void**)&dtw_l, c_dtw_l);
    cudaGetSymbolAddress((void**)&y_h, c_y_h);     cudaGetSymbolAddress((void**)&y_l, c_y_l);
    cudaGetSymbolAddress((void**)&ow_h, c_ow_h);   cudaGetSymbolAddress((void**)&ow_l, c_ow_l);

    // 0) split fp32 inputs to bf16 hi/lo (weights + hidden_states)
    cvt_split_kernel<<<(TT*HH/4 + 255)/256, 256>>>(hs, hs_h, hs_l, TT*HH/4);
    cvt_split_kernel<<<((size_t)E2*HH/4 + 255)/256, 256>>>(in_proj_w, inw_h, inw_l, E2*HH/4);
    cvt_split_kernel<<<(NSSM*DI/4 + 255)/256, 256>>>(x_proj_w, xw_h, xw_l, NSSM*DI/4);
    cvt_split_kernel<<<(DI*RR/4 + 255)/256, 256>>>(dt_proj_w, dtw_h, dtw_l, DI*RR/4);
    cvt_split_kernel<<<((size_t)HH*DI/4 + 255)/256, 256>>>(out_proj_w, ow_h, ow_l, HH*DI/4);

    // 1) in_proj: [1024,2048] x [8192,2048]^T -> g_proj
    tc_gemm<<<dim3(E2/128, TT/128), 256, GEMM_SMEM>>>(hs_h, hs_l, inw_h, inw_l, p_proj, E2, HH);

    // 2) depthwise conv + silu -> g_h (+ split)
    conv_silu_kernel<<<(TT*DI + 255)/256, 256>>>(conv_w, conv_b);

    // 3) x_proj: [1024,4096] x [160,4096]^T -> g_ssm
    tc_gemm<<<dim3((NSSM + 127)/128, TT/128), 256, GEMM_SMEM>>>(h_h, h_l, xw_h, xw_l, p_ssm, NSSM, DI);

    // 4) rmsnorms -> c_dtin (split), g_Bn, g_Cn
    rmsnorm_kernel<<<TT, 128>>>(dt_ln_w, b_ln_w, c_ln_w);

    // 5) dt_proj: [1024,128] x [4096,128]^T -> g_dt, then bias+softplus
    tc_gemm<<<dim3(DI/128, TT/128), 256, GEMM_SMEM>>>(dtin_h, dtin_l, dtw_h, dtw_l, p_dt, DI, RR);
    softplus_kernel<<<(TT*DI + 255)/256, 256>>>(dt_proj_b);

    // 6) selective scan + D skip + gate silu -> c_y (split)
    scan_kernel<<<BB * (DI/64), 64>>>(A_log, D_param);

    // 7) out_proj: [1024,4096] x [2048,4096]^T -> out
    tc_gemm<<<dim3(HH/128, TT/128), 256, GEMM_SMEM>>>(y_h, y_l, ow_h, ow_l, out, HH, DI);
}

// round 5
// speedup vs baseline: 2.1115x; 1.0965x over previous
#include <cuda_runtime.h>
#include <cuda_bf16.h>
#include <math.h>
#include <stdint.h>

// ---------------- problem constants ----------------
#define BB 2
#define LL 512
#define HH 2048
#define DI 4096
#define NN 16
#define KC 4
#define RR 128
#define TT (BB*LL)           // 1024 tokens
#define E2 (2*DI)            // 8192
#define NSSM (RR + 2*NN)     // 160
#define XSPLIT 8             // split-K chunks for x_proj

// ---------------- fp32 scratch ----------------
__device__ float g_proj[TT * E2];     // in_proj output [T, 8192] (h | gate)
__device__ float g_h[TT * DI];        // post conv+silu fp32 (for scan)
__device__ float g_ssm[TT * NSSM];    // x_proj output [T, 160]
__device__ float g_ssm_part[XSPLIT * TT * NSSM];
__device__ float g_Bn[TT * NN];
__device__ float g_Cn[TT * NN];
__device__ float g_dt[TT * DI];       // dt after proj (+bias, softplus)

// ---------------- bf16 hi/lo split operands ----------------
__device__ __nv_bfloat16 c_hs_h[TT * HH],  c_hs_l[TT * HH];
__device__ __nv_bfloat16 c_inw_h[E2 * HH], c_inw_l[E2 * HH];
__device__ __nv_bfloat16 c_h_h[TT * DI],   c_h_l[TT * DI];
__device__ __nv_bfloat16 c_xw_h[NSSM * DI], c_xw_l[NSSM * DI];
__device__ __nv_bfloat16 c_dtin_h[TT * RR], c_dtin_l[TT * RR];
__device__ __nv_bfloat16 c_dtw_h[DI * RR],  c_dtw_l[DI * RR];
__device__ __nv_bfloat16 c_y_h[TT * DI],    c_y_l[TT * DI];
__device__ __nv_bfloat16 c_ow_h[HH * DI],   c_ow_l[HH * DI];

// ---------------- helpers ----------------
__device__ __forceinline__ uint32_t smem_u32(const void* p) {
    uint32_t a;
    asm("{ .reg .u64 t; cvta.to.shared.u64 t, %1; cvt.u32.u64 %0, t; }" : "=r"(a) : "l"(p));
    return a;
}
__device__ __forceinline__ void split1(float f, __nv_bfloat16& h, __nv_bfloat16& l) {
    h = __float2bfloat16(f);
    l = __float2bfloat16(f - __bfloat162float(h));
}
__device__ __forceinline__ void cp16(uint32_t dst, const void* src, bool pred) {
    int sz = pred ? 16 : 0;
    asm volatile("cp.async.cg.shared.global [%0], [%1], 16, %2;"
                 :: "r"(dst), "l"(src), "r"(sz) : "memory");
}
__device__ __forceinline__ void cp_commit() {
    asm volatile("cp.async.commit_group;" ::: "memory");
}
__device__ __forceinline__ void cp_wait2() {
    asm volatile("cp.async.wait_group 2;" ::: "memory");
}

#define MMA_BF16(d, a, b)                                                     \
  asm volatile("mma.sync.aligned.m16n8k16.row.col.f32.bf16.bf16.f32 "        \
               "{%0,%1,%2,%3}, {%4,%5,%6,%7}, {%8,%9}, {%0,%1,%2,%3};"       \
               : "+f"(d[0]), "+f"(d[1]), "+f"(d[2]), "+f"(d[3])              \
               : "r"(a[0]), "r"(a[1]), "r"(a[2]), "r"(a[3]),                 \
                 "r"(b[0]), "r"(b[1]))

#define LDSM4(r0, r1, r2, r3, addr)                                           \
  asm volatile("ldmatrix.sync.aligned.m8n8.x4.shared.b16 {%0,%1,%2,%3}, [%4];"\
               : "=r"(r0), "=r"(r1), "=r"(r2), "=r"(r3) : "r"(addr))

__device__ __forceinline__ uint32_t swz64(uint32_t off) {
    return off ^ ((off >> 3) & 0x30);   // SW64: conflict-free 64B rows
}

// ---------------- fp32 -> bf16 hi/lo conversion ----------------
__global__ void cvt_split_kernel(const float* __restrict__ src,
                                 __nv_bfloat16* __restrict__ hi,
                                 __nv_bfloat16* __restrict__ lo, int n4) {
    int i = blockIdx.x * blockDim.x + threadIdx.x;
    if (i >= n4) return;
    float4 v = ((const float4*)src)[i];
    __nv_bfloat16 h[4], l[4];
    split1(v.x, h[0], l[0]); split1(v.y, h[1], l[1]);
    split1(v.z, h[2], l[2]); split1(v.w, h[3], l[3]);
    ((uint2*)hi)[i] = *(uint2*)h;
    ((uint2*)lo)[i] = *(uint2*)l;
}

// ================= mma.sync NT GEMM with cp.async + ldmatrix =================
// C[M,Nn] = A[M,Kk] * W[Nn,Kk]^T, operands pre-split bf16 hi/lo.
// 3-term: AhBh + AhBl + AlBh, issued TERM-MAJOR so consecutive MMAs never share
// an accumulator (16 independent MMAs between revisits).
// Optional split-K over blockIdx.z: each chunk writes C + z*zstride.
#define OPB (128 * 64)          // bytes per operand per stage (128 rows x 64B)
#define STG (4 * OPB)           // Ah|Al|Bh|Bl = 32 KB
#define NSTAGE 3
#define GEMM_SMEM (NSTAGE * STG)

__global__ __launch_bounds__(256)
void tc_gemm(const __nv_bfloat16* __restrict__ Ah, const __nv_bfloat16* __restrict__ Al,
             const __nv_bfloat16* __restrict__ Wh, const __nv_bfloat16* __restrict__ Wl,
             float* __restrict__ C, int Nn, int Kk, int nchunk, size_t zstride) {
    extern __shared__ __align__(1024) char dsm[];
    const uint32_t sbase = smem_u32(dsm);

    const int tid = threadIdx.x;
    const int lane = tid & 31;
    const int wid = tid >> 5;
    const int bm = blockIdx.y * 128;
    const int bn = blockIdx.x * 128;
    const int wm = (wid >> 2) * 64;
    const int wn = (wid & 3) * 32;
    const int qk = (lane & 3) * 2;
    const int lr = lane >> 2;

    const int chunkK = Kk / nchunk;
    const int kbase = blockIdx.z * chunkK;
    C += (size_t)blockIdx.z * zstride;

    const __nv_bfloat16* srcs[4] = { Ah, Al, Wh, Wl };

    auto load_stage = [&](int s, int kc) {
        const int k0 = kbase + kc * 32;
        const uint32_t stg = sbase + s * STG;
#pragma unroll
        for (int t = 0; t < 4; t++) {
            const __nv_bfloat16* sp = srcs[t];
            const int r0 = (t < 2) ? bm : bn;
            const bool isB = (t >= 2);
#pragma unroll
            for (int i = 0; i < 2; i++) {
                int idx = i * 256 + tid;         // 0..511
                int row = idx >> 2, c = idx & 3;
                int gr = r0 + row;
                bool ok = (!isB) || (gr < Nn);
                uint32_t dst = stg + t * OPB + swz64((uint32_t)(row * 64 + c * 16));
                cp16(dst, sp + (size_t)gr * Kk + k0 + c * 8, ok);
            }
        }
    };

    float acc[4][4][4];
#pragma unroll
    for (int mt = 0; mt < 4; mt++)
#pragma unroll
        for (int nt = 0; nt < 4; nt++)
#pragma unroll
            for (int j = 0; j < 4; j++) acc[mt][nt][j] = 0.f;

    const int nk = chunkK / 32;

    // prologue: fill 3 stages
#pragma unroll
    for (int s = 0; s < NSTAGE; s++) { load_stage(s, s); cp_commit(); }

    const int rA = lane & 15;           // ldmatrix row within 16
    const int cHi = lane >> 4;          // ldmatrix chunk select

    for (int kc = 0; kc < nk; kc++) {
        const int s = kc % NSTAGE;
        cp_wait2();
        __syncthreads();

        const uint32_t stg = sbase + s * STG;
#pragma unroll
        for (int ks = 0; ks < 2; ks++) {
            const int c0 = ks * 2 + cHi;
            uint32_t ah[4][4], al[4][4], bh[4][2], bl[4][2];
#pragma unroll
            for (int mt = 0; mt < 4; mt++) {
                uint32_t off = swz64((uint32_t)((wm + mt * 16 + rA) * 64 + c0 * 16));
                LDSM4(ah[mt][0], ah[mt][1], ah[mt][2], ah[mt][3], stg + off);
                LDSM4(al[mt][0], al[mt][1], al[mt][2], al[mt][3], stg + OPB + off);
            }
#pragma unroll
            for (int p = 0; p < 2; p++) {
                uint32_t off = swz64((uint32_t)((wn + p * 16 + rA) * 64 + c0 * 16));
                uint32_t r0, r1, r2, r3;
                LDSM4(r0, r1, r2, r3, stg + 2 * OPB + off);
                bh[2*p][0] = r0; bh[2*p+1][0] = r1; bh[2*p][1] = r2; bh[2*p+1][1] = r3;
                LDSM4(r0, r1, r2, r3, stg + 3 * OPB + off);
                bl[2*p][0] = r0; bl[2*p+1][0] = r1; bl[2*p][1] = r2; bl[2*p+1][1] = r3;
            }
            // TERM-MAJOR: all 16 (mt,nt) pairs per term -> no dependent HMMA chains
#pragma unroll
            for (int mt = 0; mt < 4; mt++)
#pragma unroll
                for (int nt = 0; nt < 4; nt++)
                    MMA_BF16(acc[mt][nt], ah[mt], bh[nt]);
#pragma unroll
            for (int mt = 0; mt < 4; mt++)
#pragma unroll
                for (int nt = 0; nt < 4; nt++)
                    MMA_BF16(acc[mt][nt], ah[mt], bl[nt]);
#pragma unroll
            for (int mt = 0; mt < 4; mt++)
#pragma unroll
                for (int nt = 0; nt < 4; nt++)
                    MMA_BF16(acc[mt][nt], al[mt], bh[nt]);
        }
        __syncthreads();
        int kn = kc + NSTAGE;
        if (kn < nk) load_stage(s, kn);
        cp_commit();
    }

    // epilogue
#pragma unroll
    for (int mt = 0; mt < 4; mt++) {
        int r = bm + wm + mt * 16 + lr;
#pragma unroll
        for (int nt = 0; nt < 4; nt++) {
            int c = bn + wn + nt * 8 + qk;
            if (c < Nn) {
                *(float2*)&C[(size_t)r * Nn + c] =
                    make_float2(acc[mt][nt][0], acc[mt][nt][1]);
                *(float2*)&C[(size_t)(r + 8) * Nn + c] =
                    make_float2(acc[mt][nt][2], acc[mt][nt][3]);
            }
        }
    }
}

// ---------------- split-K reduction for x_proj ----------------
__global__ void reduce_ssm_kernel() {
    int i = blockIdx.x * blockDim.x + threadIdx.x;
    if (i >= TT * NSSM) return;
    float s = 0.f;
#pragma unroll
    for (int z = 0; z < XSPLIT; z++) s += g_ssm_part[(size_t)z * TT * NSSM + i];
    g_ssm[i] = s;
}

// ---------------- depthwise causal conv(K=4) + bias + SiLU (+ bf16 split out) ------
__global__ void conv_silu_kernel(const float* __restrict__ cw, const float* __restrict__ cb) {
    int i = blockIdx.x * blockDim.x + threadIdx.x;
    if (i >= TT * DI) return;
    int d = i & (DI - 1);
    int t = i >> 12;
    int l = t & (LL - 1);
    int b = t >> 9;
    float acc = cb[d];
#pragma unroll
    for (int k = 0; k < KC; k++) {
        int li = l - (KC - 1) + k;
        if (li >= 0)
            acc = fmaf(g_proj[(size_t)(b * LL + li) * E2 + d], cw[d * KC + k], acc);
    }
    float s = acc / (1.f + __expf(-acc));
    g_h[i] = s;
    __nv_bfloat16 h, lo2; split1(s, h, lo2);
    c_h_h[i] = h; c_h_l[i] = lo2;
}

// ---------------- RMSNorm for dt_in(128), B(16), C(16) per token ----------------
__global__ void rmsnorm_kernel(const float* __restrict__ dt_w,
                               const float* __restrict__ b_w,
                               const float* __restrict__ c_w) {
    int t = blockIdx.x;
    int tid = threadIdx.x;              // 128 threads
    const float* row = g_ssm + (size_t)t * NSSM;

    float x = row[tid];
    float ss = x * x;
#pragma unroll
    for (int o = 16; o > 0; o >>= 1) ss += __shfl_xor_sync(0xffffffffu, ss, o);
    __shared__ float wsum[4];
    if ((tid & 31) == 0) wsum[tid >> 5] = ss;
    __syncthreads();
    float tot = wsum[0] + wsum[1] + wsum[2] + wsum[3];
    float scale = rsqrtf(tot * (1.f / RR) + 1e-6f);
    float o1 = x * scale * dt_w[tid];
    __nv_bfloat16 h, lo2; split1(o1, h, lo2);
    c_dtin_h[(size_t)t * RR + tid] = h;
    c_dtin_l[(size_t)t * RR + tid] = lo2;

    if (tid < 32) {
        int grp = tid >> 4;
        int n = tid & 15;
        float v = row[RR + grp * NN + n];
        float vs = v * v;
#pragma unroll
        for (int o = 8; o > 0; o >>= 1) vs += __shfl_xor_sync(0xffffffffu, vs, o);
        float sc = rsqrtf(vs * (1.f / NN) + 1e-6f);
        float w = grp ? c_w[n] : b_w[n];
        float outv = v * sc * w;
        if (grp == 0) g_Bn[(size_t)t * NN + n] = outv;
        else          g_Cn[(size_t)t * NN + n] = outv;
    }
}

// ---------------- dt bias + softplus (in place on g_dt) ----------------
__global__ void softplus_kernel(const float* __restrict__ bias) {
    int i = blockIdx.x * blockDim.x + threadIdx.x;
    if (i >= TT * DI) return;
    float x = g_dt[i] + bias[i & (DI - 1)];
    g_dt[i] = (x > 20.f) ? x : log1pf(__expf(x));
}

// ---------------- selective scan, depth-2 prefetch ----------------
__global__ void scan_kernel(const float* __restrict__ A_log,
                            const float* __restrict__ D_param) {
    const int b  = blockIdx.x >> 6;              // 64 blocks per batch (DI/64)
    const int d  = (blockIdx.x & 63) * 64 + threadIdx.x;
    const int tid = threadIdx.x;

    float Av[NN];
#pragma unroll
    for (int n = 0; n < NN; n++) Av[n] = -__expf(A_log[d * NN + n]);
    float state[NN];
#pragma unroll
    for (int n = 0; n < NN; n++) state[n] = 0.f;
    const float Dv = D_param[d];

    __shared__ float sBC[2][2 * NN];

    float dtv[2], hv[2], gv[2], bc[2];

    auto issue = [&](int slot, int l) {
        int t = b * LL + l;
        dtv[slot] = g_dt[(size_t)t * DI + d];
        hv[slot]  = g_h [(size_t)t * DI + d];
        gv[slot]  = g_proj[(size_t)t * E2 + DI + d];
        if (tid < 32)
            bc[slot] = (tid < NN) ? g_Bn[(size_t)t * NN + tid]
                                  : g_Cn[(size_t)t * NN + (tid - NN)];
    };

    issue(0, 0);
    issue(1, 1);
    if (tid < 32) { sBC[0][tid] = bc[0]; sBC[1][tid] = bc[1]; }
    __syncthreads();

    for (int l = 0; l < LL; l++) {
        const int s = l & 1;
        const float cdt = dtv[s], ch = hv[s], cg = gv[s];
        const bool pf = (l + 2 < LL);
        if (pf) issue(s, l + 2);

        const float dh = cdt * ch;
        float yv = 0.f;
#pragma unroll
        for (int n = 0; n < NN; n++) {
            float dA = __expf(cdt * Av[n]);
            state[n] = fmaf(state[n], dA, dh * sBC[s][n]);
            yv = fmaf(state[n], sBC[s][NN + n], yv);
        }
        float sg = cg / (1.f + __expf(-cg));
        int t = b * LL + l;
        float yo = (yv + ch * Dv) * sg;
        __nv_bfloat16 h, lo2; split1(yo, h, lo2);
        c_y_h[(size_t)t * DI + d] = h;
        c_y_l[(size_t)t * DI + d] = lo2;

        __syncthreads();
        if (pf && tid < 32) sBC[s][tid] = bc[s];
    }
}

// ---------------- launch ----------------
extern "C" void kernel_launch(void* const* d_in, const int* in_sizes, int n_in,
                              void* d_out, int out_size) {
    const float* hs        = (const float*)d_in[0];
    const float* in_proj_w = (const float*)d_in[1];
    const float* conv_w    = (const float*)d_in[2];
    const float* conv_b    = (const float*)d_in[3];
    const float* x_proj_w  = (const float*)d_in[4];
    const float* dt_ln_w   = (const float*)d_in[5];
    const float* b_ln_w    = (const float*)d_in[6];
    const float* c_ln_w    = (const float*)d_in[7];
    const float* dt_proj_w = (const float*)d_in[8];
    const float* dt_proj_b = (const float*)d_in[9];
    const float* A_log     = (const float*)d_in[10];
    const float* D_param   = (const float*)d_in[11];
    const float* out_proj_w= (const float*)d_in[12];
    float* out = (float*)d_out;

    cudaFuncSetAttribute(tc_gemm, cudaFuncAttributeMaxDynamicSharedMemorySize, GEMM_SMEM);

    float *p_proj, *p_part, *p_dt;
    cudaGetSymbolAddress((void**)&p_proj, g_proj);
    cudaGetSymbolAddress((void**)&p_part, g_ssm_part);
    cudaGetSymbolAddress((void**)&p_dt,   g_dt);
    __nv_bfloat16 *hs_h, *hs_l, *inw_h, *inw_l, *h_h, *h_l, *xw_h, *xw_l;
    __nv_bfloat16 *dtin_h, *dtin_l, *dtw_h, *dtw_l, *y_h, *y_l, *ow_h, *ow_l;
    cudaGetSymbolAddress((void**)&hs_h, c_hs_h);   cudaGetSymbolAddress((void**)&hs_l, c_hs_l);
    cudaGetSymbolAddress((void**)&inw_h, c_inw_h); cudaGetSymbolAddress((void**)&inw_l, c_inw_l);
    cudaGetSymbolAddress((void**)&h_h, c_h_h);     cudaGetSymbolAddress((void**)&h_l, c_h_l);
    cudaGetSymbolAddress((void**)&xw_h, c_xw_h);   cudaGetSymbolAddress((void**)&xw_l, c_xw_l);
    cudaGetSymbolAddress((void**)&dtin_h, c_dtin_h); cudaGetSymbolAddress((void**)&dtin_l, c_dtin_l);
    cudaGetSymbolAddress((void**)&dtw_h, c_dtw_h); cudaGetSymbolAddress((void**)&dtw_l, c_dtw_l);
    cudaGetSymbolAddress((void**)&y_h, c_y_h);     cudaGetSymbolAddress((void**)&y_l, c_y_l);
    cudaGetSymbolAddress((void**)&ow_h, c_ow_h);   cudaGetSymbolAddress((void**)&ow_l, c_ow_l);

    // 0) split fp32 inputs to bf16 hi/lo (weights + hidden_states)
    cvt_split_kernel<<<(TT*HH/4 + 255)/256, 256>>>(hs, hs_h, hs_l, TT*HH/4);
    cvt_split_kernel<<<((size_t)E2*HH/4 + 255)/256, 256>>>(in_proj_w, inw_h, inw_l, E2*HH/4);
    cvt_split_kernel<<<(NSSM*DI/4 + 255)/256, 256>>>(x_proj_w, xw_h, xw_l, NSSM*DI/4);
    cvt_split_kernel<<<(DI*RR/4 + 255)/256, 256>>>(dt_proj_w, dtw_h, dtw_l, DI*RR/4);
    cvt_split_kernel<<<((size_t)HH*DI/4 + 255)/256, 256>>>(out_proj_w, ow_h, ow_l, HH*DI/4);

    // 1) in_proj: [1024,2048] x [8192,2048]^T -> g_proj
    tc_gemm<<<dim3(E2/128, TT/128, 1), 256, GEMM_SMEM>>>(hs_h, hs_l, inw_h, inw_l,
                                                         p_proj, E2, HH, 1, 0);

    // 2) depthwise conv + silu -> g_h (+ split)
    conv_silu_kernel<<<(TT*DI + 255)/256, 256>>>(conv_w, conv_b);

    // 3) x_proj split-K x8: [1024,4096] x [160,4096]^T -> partials -> reduce
    tc_gemm<<<dim3((NSSM + 127)/128, TT/128, XSPLIT), 256, GEMM_SMEM>>>(
        h_h, h_l, xw_h, xw_l, p_part, NSSM, DI, XSPLIT, (size_t)TT * NSSM);
    reduce_ssm_kernel<<<(TT*NSSM + 255)/256, 256>>>();

    // 4) rmsnorms -> c_dtin (split), g_Bn, g_Cn
    rmsnorm_kernel<<<TT, 128>>>(dt_ln_w, b_ln_w, c_ln_w);

    // 5) dt_proj: [1024,128] x [4096,128]^T -> g_dt, then bias+softplus
    tc_gemm<<<dim3(DI/128, TT/128, 1), 256, GEMM_SMEM>>>(dtin_h, dtin_l, dtw_h, dtw_l,
                                                         p_dt, DI, RR, 1, 0);
    softplus_kernel<<<(TT*DI + 255)/256, 256>>>(dt_proj_b);

    // 6) selective scan + D skip + gate silu -> c_y (split)
    scan_kernel<<<BB * (DI/64), 64>>>(A_log, D_param);

    // 7) out_proj: [1024,4096] x [2048,4096]^T -> out
    tc_gemm<<<dim3(HH/128, TT/128, 1), 256, GEMM_SMEM>>>(y_h, y_l, ow_h, ow_l,
                                                         out, HH, DI, 1, 0);
}

// round 6
// speedup vs baseline: 2.1153x; 1.0018x over previous
#include <cuda_runtime.h>
#include <cuda_bf16.h>
#include <math.h>
#include <stdint.h>

// ---------------- problem constants ----------------
#define BB 2
#define LL 512
#define HH 2048
#define DI 4096
#define NN 16
#define KC 4
#define RR 128
#define TT (BB*LL)           // 1024 tokens
#define E2 (2*DI)            // 8192
#define NSSM (RR + 2*NN)     // 160
#define XSPLIT 8             // split-K chunks for x_proj

// ---------------- fp32 scratch ----------------
__device__ float g_proj[TT * E2];     // in_proj output [T, 8192] (h | gate)
__device__ float g_h[TT * DI];        // post conv+silu fp32 (for scan)
__device__ float g_ssm_part[XSPLIT * TT * NSSM];
__device__ float g_Bn[TT * NN];
__device__ float g_Cn[TT * NN];
__device__ float g_dt[TT * DI];       // dt after proj (+bias, softplus fused in GEMM)

// ---------------- bf16 hi/lo split operands ----------------
__device__ __nv_bfloat16 c_hs_h[TT * HH],  c_hs_l[TT * HH];
__device__ __nv_bfloat16 c_inw_h[E2 * HH], c_inw_l[E2 * HH];
__device__ __nv_bfloat16 c_h_h[TT * DI],   c_h_l[TT * DI];
__device__ __nv_bfloat16 c_xw_h[NSSM * DI], c_xw_l[NSSM * DI];
__device__ __nv_bfloat16 c_dtin_h[TT * RR], c_dtin_l[TT * RR];
__device__ __nv_bfloat16 c_dtw_h[DI * RR],  c_dtw_l[DI * RR];
__device__ __nv_bfloat16 c_y_h[TT * DI],    c_y_l[TT * DI];
__device__ __nv_bfloat16 c_ow_h[HH * DI],   c_ow_l[HH * DI];

// ---------------- helpers ----------------
__device__ __forceinline__ uint32_t smem_u32(const void* p) {
    uint32_t a;
    asm("{ .reg .u64 t; cvta.to.shared.u64 t, %1; cvt.u32.u64 %0, t; }" : "=r"(a) : "l"(p));
    return a;
}
__device__ __forceinline__ void split1(float f, __nv_bfloat16& h, __nv_bfloat16& l) {
    h = __float2bfloat16(f);
    l = __float2bfloat16(f - __bfloat162float(h));
}
__device__ __forceinline__ void cp16(uint32_t dst, const void* src, bool pred) {
    int sz = pred ? 16 : 0;
    asm volatile("cp.async.cg.shared.global [%0], [%1], 16, %2;"
                 :: "r"(dst), "l"(src), "r"(sz) : "memory");
}
__device__ __forceinline__ void cp_commit() {
    asm volatile("cp.async.commit_group;" ::: "memory");
}
__device__ __forceinline__ void cp_wait2() {
    asm volatile("cp.async.wait_group 2;" ::: "memory");
}

#define MMA_BF16(d, a, b)                                                     \
  asm volatile("mma.sync.aligned.m16n8k16.row.col.f32.bf16.bf16.f32 "        \
               "{%0,%1,%2,%3}, {%4,%5,%6,%7}, {%8,%9}, {%0,%1,%2,%3};"       \
               : "+f"(d[0]), "+f"(d[1]), "+f"(d[2]), "+f"(d[3])              \
               : "r"(a[0]), "r"(a[1]), "r"(a[2]), "r"(a[3]),                 \
                 "r"(b[0]), "r"(b[1]))

#define LDSM4(r0, r1, r2, r3, addr)                                           \
  asm volatile("ldmatrix.sync.aligned.m8n8.x4.shared.b16 {%0,%1,%2,%3}, [%4];"\
               : "=r"(r0), "=r"(r1), "=r"(r2), "=r"(r3) : "r"(addr))

__device__ __forceinline__ uint32_t swz64(uint32_t off) {
    return off ^ ((off >> 3) & 0x30);   // SW64: conflict-free 64B rows
}

// ---------------- fp32 -> bf16 hi/lo conversion ----------------
__global__ void cvt_split_kernel(const float* __restrict__ src,
                                 __nv_bfloat16* __restrict__ hi,
                                 __nv_bfloat16* __restrict__ lo, int n4) {
    int i = blockIdx.x * blockDim.x + threadIdx.x;
    if (i >= n4) return;
    float4 v = ((const float4*)src)[i];
    __nv_bfloat16 h[4], l[4];
    split1(v.x, h[0], l[0]); split1(v.y, h[1], l[1]);
    split1(v.z, h[2], l[2]); split1(v.w, h[3], l[3]);
    ((uint2*)hi)[i] = *(uint2*)h;
    ((uint2*)lo)[i] = *(uint2*)l;
}

// ================= mma.sync NT GEMM, 2 CTAs/SM =================
// C[M,Nn] = A[M,Kk] * W[Nn,Kk]^T, operands pre-split bf16 hi/lo.
// 3-term AhBh + AlBh + AhBl, term-major (16 independent MMAs per term).
// Optional split-K (blockIdx.z) and fused bias+softplus epilogue.
#define OPB (128 * 64)          // bytes per operand per stage (128 rows x 64B)
#define STG (4 * OPB)           // Ah|Al|Bh|Bl = 32 KB
#define NSTAGE 3
#define GEMM_SMEM (NSTAGE * STG)

__global__ __launch_bounds__(256, 2)
void tc_gemm(const __nv_bfloat16* __restrict__ Ah, const __nv_bfloat16* __restrict__ Al,
             const __nv_bfloat16* __restrict__ Wh, const __nv_bfloat16* __restrict__ Wl,
             float* __restrict__ C, int Nn, int Kk, int nchunk, size_t zstride,
             const float* __restrict__ epi_bias) {
    extern __shared__ __align__(1024) char dsm[];
    const uint32_t sbase = smem_u32(dsm);

    const int tid = threadIdx.x;
    const int lane = tid & 31;
    const int wid = tid >> 5;
    const int bm = blockIdx.y * 128;
    const int bn = blockIdx.x * 128;
    const int wm = (wid >> 2) * 64;
    const int wn = (wid & 3) * 32;
    const int qk = (lane & 3) * 2;
    const int lr = lane >> 2;

    const int chunkK = Kk / nchunk;
    const int kbase = blockIdx.z * chunkK;
    C += (size_t)blockIdx.z * zstride;

    const __nv_bfloat16* srcs[4] = { Ah, Al, Wh, Wl };

    auto load_stage = [&](int s, int kc) {
        const int k0 = kbase + kc * 32;
        const uint32_t stg = sbase + s * STG;
#pragma unroll
        for (int t = 0; t < 4; t++) {
            const __nv_bfloat16* sp = srcs[t];
            const int r0 = (t < 2) ? bm : bn;
            const bool isB = (t >= 2);
#pragma unroll
            for (int i = 0; i < 2; i++) {
                int idx = i * 256 + tid;         // 0..511
                int row = idx >> 2, c = idx & 3;
                int gr = r0 + row;
                bool ok = (!isB) || (gr < Nn);
                uint32_t dst = stg + t * OPB + swz64((uint32_t)(row * 64 + c * 16));
                cp16(dst, sp + (size_t)gr * Kk + k0 + c * 8, ok);
            }
        }
    };

    float acc[4][4][4];
#pragma unroll
    for (int mt = 0; mt < 4; mt++)
#pragma unroll
        for (int nt = 0; nt < 4; nt++)
#pragma unroll
            for (int j = 0; j < 4; j++) acc[mt][nt][j] = 0.f;

    const int nk = chunkK / 32;

#pragma unroll
    for (int s = 0; s < NSTAGE; s++) { load_stage(s, s); cp_commit(); }

    const int rA = lane & 15;           // ldmatrix row within 16
    const int cHi = lane >> 4;          // ldmatrix chunk select

    for (int kc = 0; kc < nk; kc++) {
        const int s = kc % NSTAGE;
        cp_wait2();
        __syncthreads();

        const uint32_t stg = sbase + s * STG;
#pragma unroll
        for (int ks = 0; ks < 2; ks++) {
            const int c0 = ks * 2 + cHi;
            // term 1: Ah x Bh
            uint32_t ah[4][4], bh[4][2];
#pragma unroll
            for (int mt = 0; mt < 4; mt++) {
                uint32_t off = swz64((uint32_t)((wm + mt * 16 + rA) * 64 + c0 * 16));
                LDSM4(ah[mt][0], ah[mt][1], ah[mt][2], ah[mt][3], stg + off);
            }
#pragma unroll
            for (int p = 0; p < 2; p++) {
                uint32_t off = swz64((uint32_t)((wn + p * 16 + rA) * 64 + c0 * 16));
                uint32_t r0, r1, r2, r3;
                LDSM4(r0, r1, r2, r3, stg + 2 * OPB + off);
                bh[2*p][0] = r0; bh[2*p+1][0] = r1; bh[2*p][1] = r2; bh[2*p+1][1] = r3;
            }
#pragma unroll
            for (int mt = 0; mt < 4; mt++)
#pragma unroll
                for (int nt = 0; nt < 4; nt++)
                    MMA_BF16(acc[mt][nt], ah[mt], bh[nt]);

            // term 2: Al x Bh (al replaces nothing yet; ah still live for term 3)
            {
                uint32_t al[4][4];
#pragma unroll
                for (int mt = 0; mt < 4; mt++) {
                    uint32_t off = swz64((uint32_t)((wm + mt * 16 + rA) * 64 + c0 * 16));
                    LDSM4(al[mt][0], al[mt][1], al[mt][2], al[mt][3], stg + OPB + off);
                }
#pragma unroll
                for (int mt = 0; mt < 4; mt++)
#pragma unroll
                    for (int nt = 0; nt < 4; nt++)
                        MMA_BF16(acc[mt][nt], al[mt], bh[nt]);
            }

            // term 3: Ah x Bl (bh dead, bl replaces it)
            {
                uint32_t bl[4][2];
#pragma unroll
                for (int p = 0; p < 2; p++) {
                    uint32_t off = swz64((uint32_t)((wn + p * 16 + rA) * 64 + c0 * 16));
                    uint32_t r0, r1, r2, r3;
                    LDSM4(r0, r1, r2, r3, stg + 3 * OPB + off);
                    bl[2*p][0] = r0; bl[2*p+1][0] = r1; bl[2*p][1] = r2; bl[2*p+1][1] = r3;
                }
#pragma unroll
                for (int mt = 0; mt < 4; mt++)
#pragma unroll
                    for (int nt = 0; nt < 4; nt++)
                        MMA_BF16(acc[mt][nt], ah[mt], bl[nt]);
            }
        }
        __syncthreads();
        int kn = kc + NSTAGE;
        if (kn < nk) load_stage(s, kn);
        cp_commit();
    }

    // epilogue (optionally fused bias + softplus)
    const bool do_sp = (epi_bias != nullptr);
#pragma unroll
    for (int mt = 0; mt < 4; mt++) {
        int r = bm + wm + mt * 16 + lr;
#pragma unroll
        for (int nt = 0; nt < 4; nt++) {
            int c = bn + wn + nt * 8 + qk;
            if (c < Nn) {
                float v[4] = {acc[mt][nt][0], acc[mt][nt][1], acc[mt][nt][2], acc[mt][nt][3]};
                if (do_sp) {
                    float b0 = epi_bias[c], b1 = epi_bias[c + 1];
                    float x0 = v[0] + b0, x1 = v[1] + b1, x2 = v[2] + b0, x3 = v[3] + b1;
                    v[0] = (x0 > 20.f) ? x0 : log1pf(__expf(x0));
                    v[1] = (x1 > 20.f) ? x1 : log1pf(__expf(x1));
                    v[2] = (x2 > 20.f) ? x2 : log1pf(__expf(x2));
                    v[3] = (x3 > 20.f) ? x3 : log1pf(__expf(x3));
                }
                *(float2*)&C[(size_t)r * Nn + c] = make_float2(v[0], v[1]);
                *(float2*)&C[(size_t)(r + 8) * Nn + c] = make_float2(v[2], v[3]);
            }
        }
    }
}

// ---------------- depthwise causal conv(K=4) + bias + SiLU (+ bf16 split out) ------
__global__ void conv_silu_kernel(const float* __restrict__ cw, const float* __restrict__ cb) {
    int i = blockIdx.x * blockDim.x + threadIdx.x;
    if (i >= TT * DI) return;
    int d = i & (DI - 1);
    int t = i >> 12;
    int l = t & (LL - 1);
    int b = t >> 9;
    float acc = cb[d];
#pragma unroll
    for (int k = 0; k < KC; k++) {
        int li = l - (KC - 1) + k;
        if (li >= 0)
            acc = fmaf(g_proj[(size_t)(b * LL + li) * E2 + d], cw[d * KC + k], acc);
    }
    float s = acc / (1.f + __expf(-acc));
    g_h[i] = s;
    __nv_bfloat16 h, lo2; split1(s, h, lo2);
    c_h_h[i] = h; c_h_l[i] = lo2;
}

// ---------------- RMSNorm (reads split-K partials directly) ----------------
__global__ void rmsnorm_kernel(const float* __restrict__ dt_w,
                               const float* __restrict__ b_w,
                               const float* __restrict__ c_w) {
    int t = blockIdx.x;
    int tid = threadIdx.x;              // 128 threads

    float x = 0.f;
#pragma unroll
    for (int z = 0; z < XSPLIT; z++)
        x += g_ssm_part[(size_t)z * TT * NSSM + (size_t)t * NSSM + tid];

    float ss = x * x;
#pragma unroll
    for (int o = 16; o > 0; o >>= 1) ss += __shfl_xor_sync(0xffffffffu, ss, o);
    __shared__ float wsum[4];
    if ((tid & 31) == 0) wsum[tid >> 5] = ss;
    __syncthreads();
    float tot = wsum[0] + wsum[1] + wsum[2] + wsum[3];
    float scale = rsqrtf(tot * (1.f / RR) + 1e-6f);
    float o1 = x * scale * dt_w[tid];
    __nv_bfloat16 h, lo2; split1(o1, h, lo2);
    c_dtin_h[(size_t)t * RR + tid] = h;
    c_dtin_l[(size_t)t * RR + tid] = lo2;

    if (tid < 32) {
        int grp = tid >> 4;
        int n = tid & 15;
        float v = 0.f;
#pragma unroll
        for (int z = 0; z < XSPLIT; z++)
            v += g_ssm_part[(size_t)z * TT * NSSM + (size_t)t * NSSM + RR + grp * NN + n];
        float vs = v * v;
#pragma unroll
        for (int o = 8; o > 0; o >>= 1) vs += __shfl_xor_sync(0xffffffffu, vs, o);
        float sc = rsqrtf(vs * (1.f / NN) + 1e-6f);
        float w = grp ? c_w[n] : b_w[n];
        float outv = v * sc * w;
        if (grp == 0) g_Bn[(size_t)t * NN + n] = outv;
        else          g_Cn[(size_t)t * NN + n] = outv;
    }
}

// ---------------- selective scan, depth-2 prefetch ----------------
__global__ void scan_kernel(const float* __restrict__ A_log,
                            const float* __restrict__ D_param) {
    const int b  = blockIdx.x >> 6;              // 64 blocks per batch (DI/64)
    const int d  = (blockIdx.x & 63) * 64 + threadIdx.x;
    const int tid = threadIdx.x;

    float Av[NN];
#pragma unroll
    for (int n = 0; n < NN; n++) Av[n] = -__expf(A_log[d * NN + n]);
    float state[NN];
#pragma unroll
    for (int n = 0; n < NN; n++) state[n] = 0.f;
    const float Dv = D_param[d];

    __shared__ float sBC[2][2 * NN];

    float dtv[2], hv[2], gv[2], bc[2];

    auto issue = [&](int slot, int l) {
        int t = b * LL + l;
        dtv[slot] = g_dt[(size_t)t * DI + d];
        hv[slot]  = g_h [(size_t)t * DI + d];
        gv[slot]  = g_proj[(size_t)t * E2 + DI + d];
        if (tid < 32)
            bc[slot] = (tid < NN) ? g_Bn[(size_t)t * NN + tid]
                                  : g_Cn[(size_t)t * NN + (tid - NN)];
    };

    issue(0, 0);
    issue(1, 1);
    if (tid < 32) { sBC[0][tid] = bc[0]; sBC[1][tid] = bc[1]; }
    __syncthreads();

    for (int l = 0; l < LL; l++) {
        const int s = l & 1;
        const float cdt = dtv[s], ch = hv[s], cg = gv[s];
        const bool pf = (l + 2 < LL);
        if (pf) issue(s, l + 2);

        const float dh = cdt * ch;
        float yv = 0.f;
#pragma unroll
        for (int n = 0; n < NN; n++) {
            float dA = __expf(cdt * Av[n]);
            state[n] = fmaf(state[n], dA, dh * sBC[s][n]);
            yv = fmaf(state[n], sBC[s][NN + n], yv);
        }
        float sg = cg / (1.f + __expf(-cg));
        int t = b * LL + l;
        float yo = (yv + ch * Dv) * sg;
        __nv_bfloat16 h, lo2; split1(yo, h, lo2);
        c_y_h[(size_t)t * DI + d] = h;
        c_y_l[(size_t)t * DI + d] = lo2;

        __syncthreads();
        if (pf && tid < 32) sBC[s][tid] = bc[s];
    }
}

// ---------------- launch ----------------
extern "C" void kernel_launch(void* const* d_in, const int* in_sizes, int n_in,
                              void* d_out, int out_size) {
    const float* hs        = (const float*)d_in[0];
    const float* in_proj_w = (const float*)d_in[1];
    const float* conv_w    = (const float*)d_in[2];
    const float* conv_b    = (const float*)d_in[3];
    const float* x_proj_w  = (const float*)d_in[4];
    const float* dt_ln_w   = (const float*)d_in[5];
    const float* b_ln_w    = (const float*)d_in[6];
    const float* c_ln_w    = (const float*)d_in[7];
    const float* dt_proj_w = (const float*)d_in[8];
    const float* dt_proj_b = (const float*)d_in[9];
    const float* A_log     = (const float*)d_in[10];
    const float* D_param   = (const float*)d_in[11];
    const float* out_proj_w= (const float*)d_in[12];
    float* out = (float*)d_out;

    cudaFuncSetAttribute(tc_gemm, cudaFuncAttributeMaxDynamicSharedMemorySize, GEMM_SMEM);

    float *p_proj, *p_part, *p_dt;
    cudaGetSymbolAddress((void**)&p_proj, g_proj);
    cudaGetSymbolAddress((void**)&p_part, g_ssm_part);
    cudaGetSymbolAddress((void**)&p_dt,   g_dt);
    __nv_bfloat16 *hs_h, *hs_l, *inw_h, *inw_l, *h_h, *h_l, *xw_h, *xw_l;
    __nv_bfloat16 *dtin_h, *dtin_l, *dtw_h, *dtw_l, *y_h, *y_l, *ow_h, *ow_l;
    cudaGetSymbolAddress((void**)&hs_h, c_hs_h);   cudaGetSymbolAddress((void**)&hs_l, c_hs_l);
    cudaGetSymbolAddress((void**)&inw_h, c_inw_h); cudaGetSymbolAddress((void**)&inw_l, c_inw_l);
    cudaGetSymbolAddress((void**)&h_h, c_h_h);     cudaGetSymbolAddress((void**)&h_l, c_h_l);
    cudaGetSymbolAddress((void**)&xw_h, c_xw_h);   cudaGetSymbolAddress((void**)&xw_l, c_xw_l);
    cudaGetSymbolAddress((void**)&dtin_h, c_dtin_h); cudaGetSymbolAddress((void**)&dtin_l, c_dtin_l);
    cudaGetSymbolAddress((void**)&dtw_h, c_dtw_h); cudaGetSymbolAddress((void**)&dtw_l, c_dtw_l);
    cudaGetSymbolAddress((void**)&y_h, c_y_h);     cudaGetSymbolAddress((void**)&y_l, c_y_l);
    cudaGetSymbolAddress((void**)&ow_h, c_ow_h);   cudaGetSymbolAddress((void**)&ow_l, c_ow_l);

    // 0) split fp32 inputs to bf16 hi/lo (weights + hidden_states)
    cvt_split_kernel<<<(TT*HH/4 + 255)/256, 256>>>(hs, hs_h, hs_l, TT*HH/4);
    cvt_split_kernel<<<((size_t)E2*HH/4 + 255)/256, 256>>>(in_proj_w, inw_h, inw_l, E2*HH/4);
    cvt_split_kernel<<<(NSSM*DI/4 + 255)/256, 256>>>(x_proj_w, xw_h, xw_l, NSSM*DI/4);
    cvt_split_kernel<<<(DI*RR/4 + 255)/256, 256>>>(dt_proj_w, dtw_h, dtw_l, DI*RR/4);
    cvt_split_kernel<<<((size_t)HH*DI/4 + 255)/256, 256>>>(out_proj_w, ow_h, ow_l, HH*DI/4);

    // 1) in_proj: [1024,2048] x [8192,2048]^T -> g_proj
    tc_gemm<<<dim3(E2/128, TT/128, 1), 256, GEMM_SMEM>>>(hs_h, hs_l, inw_h, inw_l,
                                                         p_proj, E2, HH, 1, 0, nullptr);

    // 2) depthwise conv + silu -> g_h (+ split)
    conv_silu_kernel<<<(TT*DI + 255)/256, 256>>>(conv_w, conv_b);

    // 3) x_proj split-K x8: [1024,4096] x [160,4096]^T -> partials
    tc_gemm<<<dim3((NSSM + 127)/128, TT/128, XSPLIT), 256, GEMM_SMEM>>>(
        h_h, h_l, xw_h, xw_l, p_part, NSSM, DI, XSPLIT, (size_t)TT * NSSM, nullptr);

    // 4) rmsnorms (fused split-K reduce) -> c_dtin (split), g_Bn, g_Cn
    rmsnorm_kernel<<<TT, 128>>>(dt_ln_w, b_ln_w, c_ln_w);

    // 5) dt_proj: [1024,128] x [4096,128]^T -> g_dt, bias+softplus fused in epilogue
    tc_gemm<<<dim3(DI/128, TT/128, 1), 256, GEMM_SMEM>>>(dtin_h, dtin_l, dtw_h, dtw_l,
                                                         p_dt, DI, RR, 1, 0, dt_proj_b);

    // 6) selective scan + D skip + gate silu -> c_y (split)
    scan_kernel<<<BB * (DI/64), 64>>>(A_log, D_param);

    // 7) out_proj: [1024,4096] x [2048,4096]^T -> out
    tc_gemm<<<dim3(HH/128, TT/128, 1), 256, GEMM_SMEM>>>(y_h, y_l, ow_h, ow_l,
                                                         out, HH, DI, 1, 0, nullptr);
}

// round 7
// speedup vs baseline: 2.2139x; 1.0466x over previous
#include <cuda_runtime.h>
#include <cuda_bf16.h>
#include <math.h>
#include <stdint.h>

// ---------------- problem constants ----------------
#define BB 2
#define LL 512
#define HH 2048
#define DI 4096
#define NN 16
#define KC 4
#define RR 128
#define TT (BB*LL)           // 1024 tokens
#define E2 (2*DI)            // 8192
#define NSSM (RR + 2*NN)     // 160
#define XSPLIT 8             // split-K chunks for x_proj

// ---------------- fp32 scratch ----------------
__device__ float g_proj[TT * E2];     // in_proj output [T, 8192] (h | gate)
__device__ float g_h[TT * DI];        // post conv+silu fp32 (for scan)
__device__ float g_ssm_part[XSPLIT * TT * NSSM];
__device__ float g_Bn[TT * NN];
__device__ float g_Cn[TT * NN];
__device__ float g_dt[TT * DI];       // dt after proj (+bias, softplus fused in GEMM)

// ---------------- bf16 hi/lo split operands ----------------
__device__ __nv_bfloat16 c_hs_h[TT * HH],  c_hs_l[TT * HH];
__device__ __nv_bfloat16 c_inw_h[E2 * HH], c_inw_l[E2 * HH];
__device__ __nv_bfloat16 c_h_h[TT * DI],   c_h_l[TT * DI];
__device__ __nv_bfloat16 c_xw_h[NSSM * DI], c_xw_l[NSSM * DI];
__device__ __nv_bfloat16 c_dtin_h[TT * RR], c_dtin_l[TT * RR];
__device__ __nv_bfloat16 c_dtw_h[DI * RR],  c_dtw_l[DI * RR];
__device__ __nv_bfloat16 c_y_h[TT * DI],    c_y_l[TT * DI];
__device__ __nv_bfloat16 c_ow_h[HH * DI],   c_ow_l[HH * DI];

// ---------------- helpers ----------------
__device__ __forceinline__ uint32_t smem_u32(const void* p) {
    uint32_t a;
    asm("{ .reg .u64 t; cvta.to.shared.u64 t, %1; cvt.u32.u64 %0, t; }" : "=r"(a) : "l"(p));
    return a;
}
__device__ __forceinline__ void split1(float f, __nv_bfloat16& h, __nv_bfloat16& l) {
    h = __float2bfloat16(f);
    l = __float2bfloat16(f - __bfloat162float(h));
}
__device__ __forceinline__ void cp16(uint32_t dst, const void* src, bool pred) {
    int sz = pred ? 16 : 0;
    asm volatile("cp.async.cg.shared.global [%0], [%1], 16, %2;"
                 :: "r"(dst), "l"(src), "r"(sz) : "memory");
}
__device__ __forceinline__ void cp_commit() {
    asm volatile("cp.async.commit_group;" ::: "memory");
}
__device__ __forceinline__ void cp_wait1() {
    asm volatile("cp.async.wait_group 1;" ::: "memory");
}

#define MMA_BF16(d, a, b)                                                     \
  asm volatile("mma.sync.aligned.m16n8k16.row.col.f32.bf16.bf16.f32 "        \
               "{%0,%1,%2,%3}, {%4,%5,%6,%7}, {%8,%9}, {%0,%1,%2,%3};"       \
               : "+f"(d[0]), "+f"(d[1]), "+f"(d[2]), "+f"(d[3])              \
               : "r"(a[0]), "r"(a[1]), "r"(a[2]), "r"(a[3]),                 \
                 "r"(b[0]), "r"(b[1]))

#define LDSM4(r0, r1, r2, r3, addr)                                           \
  asm volatile("ldmatrix.sync.aligned.m8n8.x4.shared.b16 {%0,%1,%2,%3}, [%4];"\
               : "=r"(r0), "=r"(r1), "=r"(r2), "=r"(r3) : "r"(addr))

__device__ __forceinline__ uint32_t swz128(uint32_t off) {
    return off ^ ((off >> 3) & 0x70);   // SW128: conflict-free 128B rows
}

// ---------------- fp32 -> bf16 hi/lo conversion (x4 ILP) ----------------
__global__ void cvt_split_kernel(const float* __restrict__ src,
                                 __nv_bfloat16* __restrict__ hi,
                                 __nv_bfloat16* __restrict__ lo, int n4) {
    const int stride = gridDim.x * blockDim.x;
    const int i0 = blockIdx.x * blockDim.x + threadIdx.x;
    float4 v[4];
    int idx[4];
    bool ok[4];
#pragma unroll
    for (int j = 0; j < 4; j++) {
        idx[j] = i0 + j * stride;
        ok[j] = idx[j] < n4;
        if (ok[j]) v[j] = ((const float4*)src)[idx[j]];
    }
#pragma unroll
    for (int j = 0; j < 4; j++) {
        if (!ok[j]) continue;
        __nv_bfloat16 h[4], l[4];
        split1(v[j].x, h[0], l[0]); split1(v[j].y, h[1], l[1]);
        split1(v[j].z, h[2], l[2]); split1(v[j].w, h[3], l[3]);
        ((uint2*)hi)[idx[j]] = *(uint2*)h;
        ((uint2*)lo)[idx[j]] = *(uint2*)l;
    }
}
static inline int cvt_grid(int n4) { return (n4 + 4 * 256 - 1) / (4 * 256); }

// ================= mma.sync NT GEMM: BK=64, 2-stage, 1 CTA/SM =================
// C[M,Nn] = A[M,Kk] * W[Nn,Kk]^T, operands pre-split bf16 hi/lo.
// 3-term AhBh + AlBh + AhBl, term-major. Optional split-K and fused softplus.
#define OPB (128 * 128)         // bytes per operand per stage (128 rows x 128B)
#define STG (4 * OPB)           // Ah|Al|Bh|Bl = 64 KB
#define NSTAGE 2
#define GEMM_SMEM (NSTAGE * STG)  // 128 KB

__global__ __launch_bounds__(256)
void tc_gemm(const __nv_bfloat16* __restrict__ Ah, const __nv_bfloat16* __restrict__ Al,
             const __nv_bfloat16* __restrict__ Wh, const __nv_bfloat16* __restrict__ Wl,
             float* __restrict__ C, int Nn, int Kk, int nchunk, size_t zstride,
             const float* __restrict__ epi_bias) {
    extern __shared__ __align__(1024) char dsm[];
    const uint32_t sbase = smem_u32(dsm);

    const int tid = threadIdx.x;
    const int lane = tid & 31;
    const int wid = tid >> 5;
    const int bm = blockIdx.y * 128;
    const int bn = blockIdx.x * 128;
    const int wm = (wid >> 2) * 64;
    const int wn = (wid & 3) * 32;
    const int qk = (lane & 3) * 2;
    const int lr = lane >> 2;

    const int chunkK = Kk / nchunk;
    const int kbase = blockIdx.z * chunkK;
    C += (size_t)blockIdx.z * zstride;

    const __nv_bfloat16* srcs[4] = { Ah, Al, Wh, Wl };

    // one stage = 64 bf16 columns (128B per row)
    auto load_stage = [&](int s, int kc) {
        const int k0 = kbase + kc * 64;
        const uint32_t stg = sbase + s * STG;
#pragma unroll
        for (int t = 0; t < 4; t++) {
            const __nv_bfloat16* sp = srcs[t];
            const int r0 = (t < 2) ? bm : bn;
            const bool isB = (t >= 2);
#pragma unroll
            for (int i = 0; i < 4; i++) {
                int idx = i * 256 + tid;         // 0..1023
                int row = idx >> 3, c = idx & 7;
                int gr = r0 + row;
                bool ok = (!isB) || (gr < Nn);
                uint32_t dst = stg + t * OPB + swz128((uint32_t)(row * 128 + c * 16));
                cp16(dst, sp + (size_t)gr * Kk + k0 + c * 8, ok);
            }
        }
    };

    float acc[4][4][4];
#pragma unroll
    for (int mt = 0; mt < 4; mt++)
#pragma unroll
        for (int nt = 0; nt < 4; nt++)
#pragma unroll
            for (int j = 0; j < 4; j++) acc[mt][nt][j] = 0.f;

    const int nk = chunkK / 64;

    load_stage(0, 0); cp_commit();
    if (nk > 1) load_stage(1, 1);
    cp_commit();

    const int rA = lane & 15;           // ldmatrix row within 16
    const int cHi = lane >> 4;          // ldmatrix chunk select (0/1)

    for (int kc = 0; kc < nk; kc++) {
        const int s = kc & 1;
        cp_wait1();
        __syncthreads();

        const uint32_t stg = sbase + s * STG;
#pragma unroll
        for (int ks = 0; ks < 4; ks++) {
            const int c0 = ks * 2 + cHi;    // 16B chunk index 0..7
            // term 1: Ah x Bh
            uint32_t ah[4][4], bh[4][2];
#pragma unroll
            for (int mt = 0; mt < 4; mt++) {
                uint32_t off = swz128((uint32_t)((wm + mt * 16 + rA) * 128 + c0 * 16));
                LDSM4(ah[mt][0], ah[mt][1], ah[mt][2], ah[mt][3], stg + off);
            }
#pragma unroll
            for (int p = 0; p < 2; p++) {
                uint32_t off = swz128((uint32_t)((wn + p * 16 + rA) * 128 + c0 * 16));
                uint32_t r0, r1, r2, r3;
                LDSM4(r0, r1, r2, r3, stg + 2 * OPB + off);
                bh[2*p][0] = r0; bh[2*p+1][0] = r1; bh[2*p][1] = r2; bh[2*p+1][1] = r3;
            }
#pragma unroll
            for (int mt = 0; mt < 4; mt++)
#pragma unroll
                for (int nt = 0; nt < 4; nt++)
                    MMA_BF16(acc[mt][nt], ah[mt], bh[nt]);

            // term 2: Al x Bh
            {
                uint32_t al[4][4];
#pragma unroll
                for (int mt = 0; mt < 4; mt++) {
                    uint32_t off = swz128((uint32_t)((wm + mt * 16 + rA) * 128 + c0 * 16));
                    LDSM4(al[mt][0], al[mt][1], al[mt][2], al[mt][3], stg + OPB + off);
                }
#pragma unroll
                for (int mt = 0; mt < 4; mt++)
#pragma unroll
                    for (int nt = 0; nt < 4; nt++)
                        MMA_BF16(acc[mt][nt], al[mt], bh[nt]);
            }

            // term 3: Ah x Bl
            {
                uint32_t bl[4][2];
#pragma unroll
                for (int p = 0; p < 2; p++) {
                    uint32_t off = swz128((uint32_t)((wn + p * 16 + rA) * 128 + c0 * 16));
                    uint32_t r0, r1, r2, r3;
                    LDSM4(r0, r1, r2, r3, stg + 3 * OPB + off);
                    bl[2*p][0] = r0; bl[2*p+1][0] = r1; bl[2*p][1] = r2; bl[2*p+1][1] = r3;
                }
#pragma unroll
                for (int mt = 0; mt < 4; mt++)
#pragma unroll
                    for (int nt = 0; nt < 4; nt++)
                        MMA_BF16(acc[mt][nt], ah[mt], bl[nt]);
            }
        }
        __syncthreads();
        int kn = kc + NSTAGE;
        if (kn < nk) load_stage(s, kn);
        cp_commit();
    }

    // epilogue (optionally fused bias + softplus)
    const bool do_sp = (epi_bias != nullptr);
#pragma unroll
    for (int mt = 0; mt < 4; mt++) {
        int r = bm + wm + mt * 16 + lr;
#pragma unroll
        for (int nt = 0; nt < 4; nt++) {
            int c = bn + wn + nt * 8 + qk;
            if (c < Nn) {
                float v[4] = {acc[mt][nt][0], acc[mt][nt][1], acc[mt][nt][2], acc[mt][nt][3]};
                if (do_sp) {
                    float b0 = epi_bias[c], b1 = epi_bias[c + 1];
                    float x0 = v[0] + b0, x1 = v[1] + b1, x2 = v[2] + b0, x3 = v[3] + b1;
                    v[0] = (x0 > 20.f) ? x0 : log1pf(__expf(x0));
                    v[1] = (x1 > 20.f) ? x1 : log1pf(__expf(x1));
                    v[2] = (x2 > 20.f) ? x2 : log1pf(__expf(x2));
                    v[3] = (x3 > 20.f) ? x3 : log1pf(__expf(x3));
                }
                *(float2*)&C[(size_t)r * Nn + c] = make_float2(v[0], v[1]);
                *(float2*)&C[(size_t)(r + 8) * Nn + c] = make_float2(v[2], v[3]);
            }
        }
    }
}

// ---------------- depthwise causal conv(K=4) + bias + SiLU (+ bf16 split out) ------
__global__ void conv_silu_kernel(const float* __restrict__ cw, const float* __restrict__ cb) {
    int i = blockIdx.x * blockDim.x + threadIdx.x;
    if (i >= TT * DI) return;
    int d = i & (DI - 1);
    int t = i >> 12;
    int l = t & (LL - 1);
    int b = t >> 9;
    float acc = cb[d];
#pragma unroll
    for (int k = 0; k < KC; k++) {
        int li = l - (KC - 1) + k;
        if (li >= 0)
            acc = fmaf(g_proj[(size_t)(b * LL + li) * E2 + d], cw[d * KC + k], acc);
    }
    float s = acc / (1.f + __expf(-acc));
    g_h[i] = s;
    __nv_bfloat16 h, lo2; split1(s, h, lo2);
    c_h_h[i] = h; c_h_l[i] = lo2;
}

// ---------------- RMSNorm (reads split-K partials directly) ----------------
__global__ void rmsnorm_kernel(const float* __restrict__ dt_w,
                               const float* __restrict__ b_w,
                               const float* __restrict__ c_w) {
    int t = blockIdx.x;
    int tid = threadIdx.x;              // 128 threads

    float x = 0.f;
#pragma unroll
    for (int z = 0; z < XSPLIT; z++)
        x += g_ssm_part[(size_t)z * TT * NSSM + (size_t)t * NSSM + tid];

    float ss = x * x;
#pragma unroll
    for (int o = 16; o > 0; o >>= 1) ss += __shfl_xor_sync(0xffffffffu, ss, o);
    __shared__ float wsum[4];
    if ((tid & 31) == 0) wsum[tid >> 5] = ss;
    __syncthreads();
    float tot = wsum[0] + wsum[1] + wsum[2] + wsum[3];
    float scale = rsqrtf(tot * (1.f / RR) + 1e-6f);
    float o1 = x * scale * dt_w[tid];
    __nv_bfloat16 h, lo2; split1(o1, h, lo2);
    c_dtin_h[(size_t)t * RR + tid] = h;
    c_dtin_l[(size_t)t * RR + tid] = lo2;

    if (tid < 32) {
        int grp = tid >> 4;
        int n = tid & 15;
        float v = 0.f;
#pragma unroll
        for (int z = 0; z < XSPLIT; z++)
            v += g_ssm_part[(size_t)z * TT * NSSM + (size_t)t * NSSM + RR + grp * NN + n];
        float vs = v * v;
#pragma unroll
        for (int o = 8; o > 0; o >>= 1) vs += __shfl_xor_sync(0xffffffffu, vs, o);
        float sc = rsqrtf(vs * (1.f / NN) + 1e-6f);
        float w = grp ? c_w[n] : b_w[n];
        float outv = v * sc * w;
        if (grp == 0) g_Bn[(size_t)t * NN + n] = outv;
        else          g_Cn[(size_t)t * NN + n] = outv;
    }
}

// ---------------- selective scan, depth-2 prefetch ----------------
__global__ void scan_kernel(const float* __restrict__ A_log,
                            const float* __restrict__ D_param) {
    const int b  = blockIdx.x >> 6;              // 64 blocks per batch (DI/64)
    const int d  = (blockIdx.x & 63) * 64 + threadIdx.x;
    const int tid = threadIdx.x;

    float Av[NN];
#pragma unroll
    for (int n = 0; n < NN; n++) Av[n] = -__expf(A_log[d * NN + n]);
    float state[NN];
#pragma unroll
    for (int n = 0; n < NN; n++) state[n] = 0.f;
    const float Dv = D_param[d];

    __shared__ float sBC[2][2 * NN];

    float dtv[2], hv[2], gv[2], bc[2];

    auto issue = [&](int slot, int l) {
        int t = b * LL + l;
        dtv[slot] = g_dt[(size_t)t * DI + d];
        hv[slot]  = g_h [(size_t)t * DI + d];
        gv[slot]  = g_proj[(size_t)t * E2 + DI + d];
        if (tid < 32)
            bc[slot] = (tid < NN) ? g_Bn[(size_t)t * NN + tid]
                                  : g_Cn[(size_t)t * NN + (tid - NN)];
    };

    issue(0, 0);
    issue(1, 1);
    if (tid < 32) { sBC[0][tid] = bc[0]; sBC[1][tid] = bc[1]; }
    __syncthreads();

    for (int l = 0; l < LL; l++) {
        const int s = l & 1;
        const float cdt = dtv[s], ch = hv[s], cg = gv[s];
        const bool pf = (l + 2 < LL);
        if (pf) issue(s, l + 2);

        const float dh = cdt * ch;
        float yv = 0.f;
#pragma unroll
        for (int n = 0; n < NN; n++) {
            float dA = __expf(cdt * Av[n]);
            state[n] = fmaf(state[n], dA, dh * sBC[s][n]);
            yv = fmaf(state[n], sBC[s][NN + n], yv);
        }
        float sg = cg / (1.f + __expf(-cg));
        int t = b * LL + l;
        float yo = (yv + ch * Dv) * sg;
        __nv_bfloat16 h, lo2; split1(yo, h, lo2);
        c_y_h[(size_t)t * DI + d] = h;
        c_y_l[(size_t)t * DI + d] = lo2;

        __syncthreads();
        if (pf && tid < 32) sBC[s][tid] = bc[s];
    }
}

// ---------------- launch ----------------
extern "C" void kernel_launch(void* const* d_in, const int* in_sizes, int n_in,
                              void* d_out, int out_size) {
    const float* hs        = (const float*)d_in[0];
    const float* in_proj_w = (const float*)d_in[1];
    const float* conv_w    = (const float*)d_in[2];
    const float* conv_b    = (const float*)d_in[3];
    const float* x_proj_w  = (const float*)d_in[4];
    const float* dt_ln_w   = (const float*)d_in[5];
    const float* b_ln_w    = (const float*)d_in[6];
    const float* c_ln_w    = (const float*)d_in[7];
    const float* dt_proj_w = (const float*)d_in[8];
    const float* dt_proj_b = (const float*)d_in[9];
    const float* A_log     = (const float*)d_in[10];
    const float* D_param   = (const float*)d_in[11];
    const float* out_proj_w= (const float*)d_in[12];
    float* out = (float*)d_out;

    cudaFuncSetAttribute(tc_gemm, cudaFuncAttributeMaxDynamicSharedMemorySize, GEMM_SMEM);

    float *p_proj, *p_part, *p_dt;
    cudaGetSymbolAddress((void**)&p_proj, g_proj);
    cudaGetSymbolAddress((void**)&p_part, g_ssm_part);
    cudaGetSymbolAddress((void**)&p_dt,   g_dt);
    __nv_bfloat16 *hs_h, *hs_l, *inw_h, *inw_l, *h_h, *h_l, *xw_h, *xw_l;
    __nv_bfloat16 *dtin_h, *dtin_l, *dtw_h, *dtw_l, *y_h, *y_l, *ow_h, *ow_l;
    cudaGetSymbolAddress((void**)&hs_h, c_hs_h);   cudaGetSymbolAddress((void**)&hs_l, c_hs_l);
    cudaGetSymbolAddress((void**)&inw_h, c_inw_h); cudaGetSymbolAddress((void**)&inw_l, c_inw_l);
    cudaGetSymbolAddress((void**)&h_h, c_h_h);     cudaGetSymbolAddress((void**)&h_l, c_h_l);
    cudaGetSymbolAddress((void**)&xw_h, c_xw_h);   cudaGetSymbolAddress((void**)&xw_l, c_xw_l);
    cudaGetSymbolAddress((void**)&dtin_h, c_dtin_h); cudaGetSymbolAddress((void**)&dtin_l, c_dtin_l);
    cudaGetSymbolAddress((void**)&dtw_h, c_dtw_h); cudaGetSymbolAddress((void**)&dtw_l, c_dtw_l);
    cudaGetSymbolAddress((void**)&y_h, c_y_h);     cudaGetSymbolAddress((void**)&y_l, c_y_l);
    cudaGetSymbolAddress((void**)&ow_h, c_ow_h);   cudaGetSymbolAddress((void**)&ow_l, c_ow_l);

    // 0,1,2) splits needed by in_proj + x_proj
    cvt_split_kernel<<<cvt_grid(TT*HH/4), 256>>>(hs, hs_h, hs_l, TT*HH/4);
    cvt_split_kernel<<<cvt_grid(E2*HH/4), 256>>>(in_proj_w, inw_h, inw_l, E2*HH/4);
    cvt_split_kernel<<<cvt_grid(NSSM*DI/4), 256>>>(x_proj_w, xw_h, xw_l, NSSM*DI/4);

    // 3) in_proj GEMM (profiled slot)
    tc_gemm<<<dim3(E2/128, TT/128, 1), 256, GEMM_SMEM>>>(hs_h, hs_l, inw_h, inw_l,
                                                         p_proj, E2, HH, 1, 0, nullptr);

    // 4) depthwise conv + silu -> g_h (+ split)
    conv_silu_kernel<<<(TT*DI + 255)/256, 256>>>(conv_w, conv_b);

    // 5) x_proj split-K x8 (alternate profiled slot)
    tc_gemm<<<dim3((NSSM + 127)/128, TT/128, XSPLIT), 256, GEMM_SMEM>>>(
        h_h, h_l, xw_h, xw_l, p_part, NSSM, DI, XSPLIT, (size_t)TT * NSSM, nullptr);

    // 6) dt_proj_w split
    cvt_split_kernel<<<cvt_grid(DI*RR/4), 256>>>(dt_proj_w, dtw_h, dtw_l, DI*RR/4);

    // 7) rmsnorms (fused split-K reduce)
    rmsnorm_kernel<<<TT, 128>>>(dt_ln_w, b_ln_w, c_ln_w);

    // 8) dt_proj GEMM, bias+softplus fused
    tc_gemm<<<dim3(DI/128, TT/128, 1), 256, GEMM_SMEM>>>(dtin_h, dtin_l, dtw_h, dtw_l,
                                                         p_dt, DI, RR, 1, 0, dt_proj_b);

    // 9) selective scan + D skip + gate silu -> c_y (split)
    scan_kernel<<<BB * (DI/64), 64>>>(A_log, D_param);

    // 10) out_proj_w split
    cvt_split_kernel<<<cvt_grid(HH*DI/4), 256>>>(out_proj_w, ow_h, ow_l, HH*DI/4);

    // 11) out_proj GEMM
    tc_gemm<<<dim3(HH/128, TT/128, 1), 256, GEMM_SMEM>>>(y_h, y_l, ow_h, ow_l,
                                                         out, HH, DI, 1, 0, nullptr);
}

// round 8
// speedup vs baseline: 2.2179x; 1.0018x over previous
#include <cuda_runtime.h>
#include <cuda_bf16.h>
#include <math.h>
#include <stdint.h>

// ---------------- problem constants ----------------
#define BB 2
#define LL 512
#define HH 2048
#define DI 4096
#define NN 16
#define KC 4
#define RR 128
#define TT (BB*LL)           // 1024 tokens
#define E2 (2*DI)            // 8192
#define NSSM (RR + 2*NN)     // 160
#define XSPLIT 8             // split-K chunks for x_proj

// ---------------- fp32 scratch ----------------
__device__ float g_proj[TT * E2];     // in_proj output [T, 8192] (h | gate)
__device__ float g_h[TT * DI];        // post conv+silu fp32 (for scan)
__device__ float g_ssm_part[XSPLIT * TT * NSSM];
__device__ float g_Bn[TT * NN];
__device__ float g_Cn[TT * NN];
__device__ float g_dt[TT * DI];       // dt after proj (+bias, softplus fused in GEMM)

// ---------------- bf16 hi/lo split operands ----------------
__device__ __nv_bfloat16 c_hs_h[TT * HH],  c_hs_l[TT * HH];
__device__ __nv_bfloat16 c_inw_h[E2 * HH], c_inw_l[E2 * HH];
__device__ __nv_bfloat16 c_h_h[TT * DI],   c_h_l[TT * DI];
__device__ __nv_bfloat16 c_xw_h[NSSM * DI], c_xw_l[NSSM * DI];
__device__ __nv_bfloat16 c_dtin_h[TT * RR], c_dtin_l[TT * RR];
__device__ __nv_bfloat16 c_dtw_h[DI * RR],  c_dtw_l[DI * RR];
__device__ __nv_bfloat16 c_y_h[TT * DI],    c_y_l[TT * DI];
__device__ __nv_bfloat16 c_ow_h[HH * DI],   c_ow_l[HH * DI];

// ---------------- helpers ----------------
__device__ __forceinline__ uint32_t smem_u32(const void* p) {
    uint32_t a;
    asm("{ .reg .u64 t; cvta.to.shared.u64 t, %1; cvt.u32.u64 %0, t; }" : "=r"(a) : "l"(p));
    return a;
}
__device__ __forceinline__ void split1(float f, __nv_bfloat16& h, __nv_bfloat16& l) {
    h = __float2bfloat16(f);
    l = __float2bfloat16(f - __bfloat162float(h));
}
__device__ __forceinline__ void cp16(uint32_t dst, const void* src, bool pred) {
    int sz = pred ? 16 : 0;
    asm volatile("cp.async.cg.shared.global [%0], [%1], 16, %2;"
                 :: "r"(dst), "l"(src), "r"(sz) : "memory");
}
__device__ __forceinline__ void cp_commit() {
    asm volatile("cp.async.commit_group;" ::: "memory");
}
__device__ __forceinline__ void cp_wait1() {
    asm volatile("cp.async.wait_group 1;" ::: "memory");
}

#define MMA_BF16(d, a, b)                                                     \
  asm volatile("mma.sync.aligned.m16n8k16.row.col.f32.bf16.bf16.f32 "        \
               "{%0,%1,%2,%3}, {%4,%5,%6,%7}, {%8,%9}, {%0,%1,%2,%3};"       \
               : "+f"(d[0]), "+f"(d[1]), "+f"(d[2]), "+f"(d[3])              \
               : "r"(a[0]), "r"(a[1]), "r"(a[2]), "r"(a[3]),                 \
                 "r"(b[0]), "r"(b[1]))

#define LDSM4(r0, r1, r2, r3, addr)                                           \
  asm volatile("ldmatrix.sync.aligned.m8n8.x4.shared.b16 {%0,%1,%2,%3}, [%4];"\
               : "=r"(r0), "=r"(r1), "=r"(r2), "=r"(r3) : "r"(addr))

__device__ __forceinline__ uint32_t swz128(uint32_t off) {
    return off ^ ((off >> 3) & 0x70);   // SW128: conflict-free 128B rows
}

// ---------------- fp32 -> bf16 hi/lo, full-width 16B stores, x2 group ILP ----------
__global__ void cvt_split_kernel(const float* __restrict__ src,
                                 __nv_bfloat16* __restrict__ hi,
                                 __nv_bfloat16* __restrict__ lo, int n8) {
    const int stride = gridDim.x * blockDim.x;
    const int i0 = blockIdx.x * blockDim.x + threadIdx.x;
    float4 a[2], b[2];
    int k[2];
    bool ok[2];
#pragma unroll
    for (int j = 0; j < 2; j++) {
        k[j] = i0 + j * stride;
        ok[j] = k[j] < n8;
        if (ok[j]) {
            a[j] = ((const float4*)src)[2 * k[j]];
            b[j] = ((const float4*)src)[2 * k[j] + 1];
        }
    }
#pragma unroll
    for (int j = 0; j < 2; j++) {
        if (!ok[j]) continue;
        __nv_bfloat16 h[8], l[8];
        split1(a[j].x, h[0], l[0]); split1(a[j].y, h[1], l[1]);
        split1(a[j].z, h[2], l[2]); split1(a[j].w, h[3], l[3]);
        split1(b[j].x, h[4], l[4]); split1(b[j].y, h[5], l[5]);
        split1(b[j].z, h[6], l[6]); split1(b[j].w, h[7], l[7]);
        ((uint4*)hi)[k[j]] = *(uint4*)h;
        ((uint4*)lo)[k[j]] = *(uint4*)l;
    }
}
static inline int cvt_grid8(int n8) { return (n8 + 2 * 256 - 1) / (2 * 256); }

// ================= mma.sync NT GEMM: BK=64, 2-stage, hoisted swizzle =================
#define OPB (128 * 128)         // bytes per operand per stage (128 rows x 128B)
#define STG (4 * OPB)           // Ah|Al|Bh|Bl = 64 KB
#define NSTAGE 2
#define GEMM_SMEM (NSTAGE * STG)  // 128 KB

__global__ __launch_bounds__(256)
void tc_gemm(const __nv_bfloat16* __restrict__ Ah, const __nv_bfloat16* __restrict__ Al,
             const __nv_bfloat16* __restrict__ Wh, const __nv_bfloat16* __restrict__ Wl,
             float* __restrict__ C, int Nn, int Kk, int nchunk, size_t zstride,
             const float* __restrict__ epi_bias) {
    extern __shared__ __align__(1024) char dsm[];
    const uint32_t sbase = smem_u32(dsm);

    const int tid = threadIdx.x;
    const int lane = tid & 31;
    const int wid = tid >> 5;
    const int bm = blockIdx.y * 128;
    const int bn = blockIdx.x * 128;
    const int wm = (wid >> 2) * 64;
    const int wn = (wid & 3) * 32;
    const int qk = (lane & 3) * 2;
    const int lr = lane >> 2;

    const int chunkK = Kk / nchunk;
    const int kbase = blockIdx.z * chunkK;
    C += (size_t)blockIdx.z * zstride;

    const __nv_bfloat16* srcs[4] = { Ah, Al, Wh, Wl };

    auto load_stage = [&](int s, int kc) {
        const int k0 = kbase + kc * 64;
        const uint32_t stg = sbase + s * STG;
#pragma unroll
        for (int t = 0; t < 4; t++) {
            const __nv_bfloat16* sp = srcs[t];
            const int r0 = (t < 2) ? bm : bn;
            const bool isB = (t >= 2);
#pragma unroll
            for (int i = 0; i < 4; i++) {
                int idx = i * 256 + tid;         // 0..1023
                int row = idx >> 3, c = idx & 7;
                int gr = r0 + row;
                bool ok = (!isB) || (gr < Nn);
                uint32_t dst = stg + t * OPB + swz128((uint32_t)(row * 128 + c * 16));
                cp16(dst, sp + (size_t)gr * Kk + k0 + c * 8, ok);
            }
        }
    };

    float acc[4][4][4];
#pragma unroll
    for (int mt = 0; mt < 4; mt++)
#pragma unroll
        for (int nt = 0; nt < 4; nt++)
#pragma unroll
            for (int j = 0; j < 4; j++) acc[mt][nt][j] = 0.f;

    const int nk = chunkK / 64;

    load_stage(0, 0); cp_commit();
    if (nk > 1) load_stage(1, 1);
    cp_commit();

    const int rA = lane & 15;           // ldmatrix row within 16
    const int cHi = lane >> 4;          // ldmatrix chunk select (0/1)

    // hoisted swizzled fragment offsets (loop-invariant):
    // full addr = stg [+ tOPB] + (base ^ (ks*32)); XOR valid because ks*32 sits in
    // bits 5-6 which hold (c0*16 ^ rowxor) after swizzle, disjoint from row field.
    uint32_t aOff[4], bOff[2];
#pragma unroll
    for (int mt = 0; mt < 4; mt++)
        aOff[mt] = swz128((uint32_t)((wm + mt * 16 + rA) * 128)) ^ (uint32_t)(cHi * 16);
#pragma unroll
    for (int p = 0; p < 2; p++)
        bOff[p] = swz128((uint32_t)((wn + p * 16 + rA) * 128)) ^ (uint32_t)(cHi * 16);

    for (int kc = 0; kc < nk; kc++) {
        const int s = kc & 1;
        cp_wait1();
        __syncthreads();

        const uint32_t stg = sbase + s * STG;
#pragma unroll
        for (int ks = 0; ks < 4; ks++) {
            const uint32_t kx = (uint32_t)(ks * 32);
            // term 1: Ah x Bh
            uint32_t ah[4][4], bh[4][2];
#pragma unroll
            for (int mt = 0; mt < 4; mt++)
                LDSM4(ah[mt][0], ah[mt][1], ah[mt][2], ah[mt][3], stg + (aOff[mt] ^ kx));
#pragma unroll
            for (int p = 0; p < 2; p++) {
                uint32_t r0, r1, r2, r3;
                LDSM4(r0, r1, r2, r3, stg + 2 * OPB + (bOff[p] ^ kx));
                bh[2*p][0] = r0; bh[2*p+1][0] = r1; bh[2*p][1] = r2; bh[2*p+1][1] = r3;
            }
#pragma unroll
            for (int mt = 0; mt < 4; mt++)
#pragma unroll
                for (int nt = 0; nt < 4; nt++)
                    MMA_BF16(acc[mt][nt], ah[mt], bh[nt]);

            // term 2: Al x Bh
            {
                uint32_t al[4][4];
#pragma unroll
                for (int mt = 0; mt < 4; mt++)
                    LDSM4(al[mt][0], al[mt][1], al[mt][2], al[mt][3],
                          stg + OPB + (aOff[mt] ^ kx));
#pragma unroll
                for (int mt = 0; mt < 4; mt++)
#pragma unroll
                    for (int nt = 0; nt < 4; nt++)
                        MMA_BF16(acc[mt][nt], al[mt], bh[nt]);
            }

            // term 3: Ah x Bl
            {
                uint32_t bl[4][2];
#pragma unroll
                for (int p = 0; p < 2; p++) {
                    uint32_t r0, r1, r2, r3;
                    LDSM4(r0, r1, r2, r3, stg + 3 * OPB + (bOff[p] ^ kx));
                    bl[2*p][0] = r0; bl[2*p+1][0] = r1; bl[2*p][1] = r2; bl[2*p+1][1] = r3;
                }
#pragma unroll
                for (int mt = 0; mt < 4; mt++)
#pragma unroll
                    for (int nt = 0; nt < 4; nt++)
                        MMA_BF16(acc[mt][nt], ah[mt], bl[nt]);
            }
        }
        __syncthreads();
        int kn = kc + NSTAGE;
        if (kn < nk) load_stage(s, kn);
        cp_commit();
    }

    // epilogue (optionally fused bias + softplus)
    const bool do_sp = (epi_bias != nullptr);
#pragma unroll
    for (int mt = 0; mt < 4; mt++) {
        int r = bm + wm + mt * 16 + lr;
#pragma unroll
        for (int nt = 0; nt < 4; nt++) {
            int c = bn + wn + nt * 8 + qk;
            if (c < Nn) {
                float v[4] = {acc[mt][nt][0], acc[mt][nt][1], acc[mt][nt][2], acc[mt][nt][3]};
                if (do_sp) {
                    float b0 = epi_bias[c], b1 = epi_bias[c + 1];
                    float x0 = v[0] + b0, x1 = v[1] + b1, x2 = v[2] + b0, x3 = v[3] + b1;
                    v[0] = (x0 > 20.f) ? x0 : log1pf(__expf(x0));
                    v[1] = (x1 > 20.f) ? x1 : log1pf(__expf(x1));
                    v[2] = (x2 > 20.f) ? x2 : log1pf(__expf(x2));
                    v[3] = (x3 > 20.f) ? x3 : log1pf(__expf(x3));
                }
                *(float2*)&C[(size_t)r * Nn + c] = make_float2(v[0], v[1]);
                *(float2*)&C[(size_t)(r + 8) * Nn + c] = make_float2(v[2], v[3]);
            }
        }
    }
}

// ---------------- depthwise causal conv(K=4) + bias + SiLU (+ bf16 split out) ------
__global__ void conv_silu_kernel(const float* __restrict__ cw, const float* __restrict__ cb) {
    int i = blockIdx.x * blockDim.x + threadIdx.x;
    if (i >= TT * DI) return;
    int d = i & (DI - 1);
    int t = i >> 12;
    int l = t & (LL - 1);
    int b = t >> 9;
    float acc = cb[d];
#pragma unroll
    for (int k = 0; k < KC; k++) {
        int li = l - (KC - 1) + k;
        if (li >= 0)
            acc = fmaf(g_proj[(size_t)(b * LL + li) * E2 + d], cw[d * KC + k], acc);
    }
    float s = acc / (1.f + __expf(-acc));
    g_h[i] = s;
    __nv_bfloat16 h, lo2; split1(s, h, lo2);
    c_h_h[i] = h; c_h_l[i] = lo2;
}

// ---------------- RMSNorm (reads split-K partials directly) ----------------
__global__ void rmsnorm_kernel(const float* __restrict__ dt_w,
                               const float* __restrict__ b_w,
                               const float* __restrict__ c_w) {
    int t = blockIdx.x;
    int tid = threadIdx.x;              // 128 threads

    float x = 0.f;
#pragma unroll
    for (int z = 0; z < XSPLIT; z++)
        x += g_ssm_part[(size_t)z * TT * NSSM + (size_t)t * NSSM + tid];

    float ss = x * x;
#pragma unroll
    for (int o = 16; o > 0; o >>= 1) ss += __shfl_xor_sync(0xffffffffu, ss, o);
    __shared__ float wsum[4];
    if ((tid & 31) == 0) wsum[tid >> 5] = ss;
    __syncthreads();
    float tot = wsum[0] + wsum[1] + wsum[2] + wsum[3];
    float scale = rsqrtf(tot * (1.f / RR) + 1e-6f);
    float o1 = x * scale * dt_w[tid];
    __nv_bfloat16 h, lo2; split1(o1, h, lo2);
    c_dtin_h[(size_t)t * RR + tid] = h;
    c_dtin_l[(size_t)t * RR + tid] = lo2;

    if (tid < 32) {
        int grp = tid >> 4;
        int n = tid & 15;
        float v = 0.f;
#pragma unroll
        for (int z = 0; z < XSPLIT; z++)
            v += g_ssm_part[(size_t)z * TT * NSSM + (size_t)t * NSSM + RR + grp * NN + n];
        float vs = v * v;
#pragma unroll
        for (int o = 8; o > 0; o >>= 1) vs += __shfl_xor_sync(0xffffffffu, vs, o);
        float sc = rsqrtf(vs * (1.f / NN) + 1e-6f);
        float w = grp ? c_w[n] : b_w[n];
        float outv = v * sc * w;
        if (grp == 0) g_Bn[(size_t)t * NN + n] = outv;
        else          g_Cn[(size_t)t * NN + n] = outv;
    }
}

// ---------------- selective scan, depth-2 prefetch ----------------
__global__ void scan_kernel(const float* __restrict__ A_log,
                            const float* __restrict__ D_param) {
    const int b  = blockIdx.x >> 6;              // 64 blocks per batch (DI/64)
    const int d  = (blockIdx.x & 63) * 64 + threadIdx.x;
    const int tid = threadIdx.x;

    float Av[NN];
#pragma unroll
    for (int n = 0; n < NN; n++) Av[n] = -__expf(A_log[d * NN + n]);
    float state[NN];
#pragma unroll
    for (int n = 0; n < NN; n++) state[n] = 0.f;
    const float Dv = D_param[d];

    __shared__ float sBC[2][2 * NN];

    float dtv[2], hv[2], gv[2], bc[2];

    auto issue = [&](int slot, int l) {
        int t = b * LL + l;
        dtv[slot] = g_dt[(size_t)t * DI + d];
        hv[slot]  = g_h [(size_t)t * DI + d];
        gv[slot]  = g_proj[(size_t)t * E2 + DI + d];
        if (tid < 32)
            bc[slot] = (tid < NN) ? g_Bn[(size_t)t * NN + tid]
                                  : g_Cn[(size_t)t * NN + (tid - NN)];
    };

    issue(0, 0);
    issue(1, 1);
    if (tid < 32) { sBC[0][tid] = bc[0]; sBC[1][tid] = bc[1]; }
    __syncthreads();

    for (int l = 0; l < LL; l++) {
        const int s = l & 1;
        const float cdt = dtv[s], ch = hv[s], cg = gv[s];
        const bool pf = (l + 2 < LL);
        if (pf) issue(s, l + 2);

        const float dh = cdt * ch;
        float yv = 0.f;
#pragma unroll
        for (int n = 0; n < NN; n++) {
            float dA = __expf(cdt * Av[n]);
            state[n] = fmaf(state[n], dA, dh * sBC[s][n]);
            yv = fmaf(state[n], sBC[s][NN + n], yv);
        }
        float sg = cg / (1.f + __expf(-cg));
        int t = b * LL + l;
        float yo = (yv + ch * Dv) * sg;
        __nv_bfloat16 h, lo2; split1(yo, h, lo2);
        c_y_h[(size_t)t * DI + d] = h;
        c_y_l[(size_t)t * DI + d] = lo2;

        __syncthreads();
        if (pf && tid < 32) sBC[s][tid] = bc[s];
    }
}

// ---------------- launch ----------------
extern "C" void kernel_launch(void* const* d_in, const int* in_sizes, int n_in,
                              void* d_out, int out_size) {
    const float* hs        = (const float*)d_in[0];
    const float* in_proj_w = (const float*)d_in[1];
    const float* conv_w    = (const float*)d_in[2];
    const float* conv_b    = (const float*)d_in[3];
    const float* x_proj_w  = (const float*)d_in[4];
    const float* dt_ln_w   = (const float*)d_in[5];
    const float* b_ln_w    = (const float*)d_in[6];
    const float* c_ln_w    = (const float*)d_in[7];
    const float* dt_proj_w = (const float*)d_in[8];
    const float* dt_proj_b = (const float*)d_in[9];
    const float* A_log     = (const float*)d_in[10];
    const float* D_param   = (const float*)d_in[11];
    const float* out_proj_w= (const float*)d_in[12];
    float* out = (float*)d_out;

    cudaFuncSetAttribute(tc_gemm, cudaFuncAttributeMaxDynamicSharedMemorySize, GEMM_SMEM);

    float *p_proj, *p_part, *p_dt;
    cudaGetSymbolAddress((void**)&p_proj, g_proj);
    cudaGetSymbolAddress((void**)&p_part, g_ssm_part);
    cudaGetSymbolAddress((void**)&p_dt,   g_dt);
    __nv_bfloat16 *hs_h, *hs_l, *inw_h, *inw_l, *h_h, *h_l, *xw_h, *xw_l;
    __nv_bfloat16 *dtin_h, *dtin_l, *dtw_h, *dtw_l, *y_h, *y_l, *ow_h, *ow_l;
    cudaGetSymbolAddress((void**)&hs_h, c_hs_h);   cudaGetSymbolAddress((void**)&hs_l, c_hs_l);
    cudaGetSymbolAddress((void**)&inw_h, c_inw_h); cudaGetSymbolAddress((void**)&inw_l, c_inw_l);
    cudaGetSymbolAddress((void**)&h_h, c_h_h);     cudaGetSymbolAddress((void**)&h_l, c_h_l);
    cudaGetSymbolAddress((void**)&xw_h, c_xw_h);   cudaGetSymbolAddress((void**)&xw_l, c_xw_l);
    cudaGetSymbolAddress((void**)&dtin_h, c_dtin_h); cudaGetSymbolAddress((void**)&dtin_l, c_dtin_l);
    cudaGetSymbolAddress((void**)&dtw_h, c_dtw_h); cudaGetSymbolAddress((void**)&dtw_l, c_dtw_l);
    cudaGetSymbolAddress((void**)&y_h, c_y_h);     cudaGetSymbolAddress((void**)&y_l, c_y_l);
    cudaGetSymbolAddress((void**)&ow_h, c_ow_h);   cudaGetSymbolAddress((void**)&ow_l, c_ow_l);

    // 0,1,2) splits needed by in_proj + x_proj
    cvt_split_kernel<<<cvt_grid8(TT*HH/8), 256>>>(hs, hs_h, hs_l, TT*HH/8);
    cvt_split_kernel<<<cvt_grid8(E2*HH/8), 256>>>(in_proj_w, inw_h, inw_l, E2*HH/8);
    cvt_split_kernel<<<cvt_grid8(NSSM*DI/8), 256>>>(x_proj_w, xw_h, xw_l, NSSM*DI/8);

    // 3) in_proj GEMM
    tc_gemm<<<dim3(E2/128, TT/128, 1), 256, GEMM_SMEM>>>(hs_h, hs_l, inw_h, inw_l,
                                                         p_proj, E2, HH, 1, 0, nullptr);

    // 4) depthwise conv + silu -> g_h (+ split)
    conv_silu_kernel<<<(TT*DI + 255)/256, 256>>>(conv_w, conv_b);

    // 5) x_proj split-K x8
    tc_gemm<<<dim3((NSSM + 127)/128, TT/128, XSPLIT), 256, GEMM_SMEM>>>(
        h_h, h_l, xw_h, xw_l, p_part, NSSM, DI, XSPLIT, (size_t)TT * NSSM, nullptr);

    // 6) dt_proj_w split
    cvt_split_kernel<<<cvt_grid8(DI*RR/8), 256>>>(dt_proj_w, dtw_h, dtw_l, DI*RR/8);

    // 7) rmsnorms (fused split-K reduce)
    rmsnorm_kernel<<<TT, 128>>>(dt_ln_w, b_ln_w, c_ln_w);

    // 8) dt_proj GEMM, bias+softplus fused
    tc_gemm<<<dim3(DI/128, TT/128, 1), 256, GEMM_SMEM>>>(dtin_h, dtin_l, dtw_h, dtw_l,
                                                         p_dt, DI, RR, 1, 0, dt_proj_b);

    // 9) selective scan + D skip + gate silu -> c_y (split)
    scan_kernel<<<BB * (DI/64), 64>>>(A_log, D_param);

    // 10) out_proj_w split
    cvt_split_kernel<<<cvt_grid8(HH*DI/8), 256>>>(out_proj_w, ow_h, ow_l, HH*DI/8);

    // 11) out_proj GEMM
    tc_gemm<<<dim3(HH/128, TT/128, 1), 256, GEMM_SMEM>>>(y_h, y_l, ow_h, ow_l,
                                                         out, HH, DI, 1, 0, nullptr);
}

// round 9
// speedup vs baseline: 2.2400x; 1.0100x over previous
#include <cuda_runtime.h>
#include <cuda_bf16.h>
#include <math.h>
#include <stdint.h>

// ---------------- problem constants ----------------
#define BB 2
#define LL 512
#define HH 2048
#define DI 4096
#define NN 16
#define KC 4
#define RR 128
#define TT (BB*LL)           // 1024 tokens
#define E2 (2*DI)            // 8192
#define NSSM (RR + 2*NN)     // 160
#define XSPLIT 8             // split-K chunks for x_proj

// ---------------- fp32 scratch ----------------
__device__ float g_proj[TT * E2];     // in_proj output [T, 8192] (h | gate)
__device__ float g_h[TT * DI];        // post conv+silu fp32 (for scan)
__device__ float g_ssm_part[XSPLIT * TT * NSSM];
__device__ float g_Bn[TT * NN];
__device__ float g_Cn[TT * NN];
__device__ float g_dt[TT * DI];       // dt after proj (+bias, softplus fused in GEMM)

// ---------------- bf16 hi/lo split operands ----------------
__device__ __nv_bfloat16 c_hs_h[TT * HH],  c_hs_l[TT * HH];
__device__ __nv_bfloat16 c_inw_h[E2 * HH], c_inw_l[E2 * HH];
__device__ __nv_bfloat16 c_h_h[TT * DI],   c_h_l[TT * DI];
__device__ __nv_bfloat16 c_xw_h[NSSM * DI], c_xw_l[NSSM * DI];
__device__ __nv_bfloat16 c_dtin_h[TT * RR], c_dtin_l[TT * RR];
__device__ __nv_bfloat16 c_dtw_h[DI * RR],  c_dtw_l[DI * RR];
__device__ __nv_bfloat16 c_y_h[TT * DI],    c_y_l[TT * DI];
__device__ __nv_bfloat16 c_ow_h[HH * DI],   c_ow_l[HH * DI];

// ---------------- helpers ----------------
__device__ __forceinline__ uint32_t smem_u32(const void* p) {
    uint32_t a;
    asm("{ .reg .u64 t; cvta.to.shared.u64 t, %1; cvt.u32.u64 %0, t; }" : "=r"(a) : "l"(p));
    return a;
}
__device__ __forceinline__ void split1(float f, __nv_bfloat16& h, __nv_bfloat16& l) {
    h = __float2bfloat16(f);
    l = __float2bfloat16(f - __bfloat162float(h));
}
__device__ __forceinline__ void cp16(uint32_t dst, const void* src, bool pred) {
    int sz = pred ? 16 : 0;
    asm volatile("cp.async.cg.shared.global [%0], [%1], 16, %2;"
                 :: "r"(dst), "l"(src), "r"(sz) : "memory");
}
__device__ __forceinline__ void cp_commit() {
    asm volatile("cp.async.commit_group;" ::: "memory");
}
__device__ __forceinline__ void cp_wait1() {
    asm volatile("cp.async.wait_group 1;" ::: "memory");
}

#define MMA_BF16(d, a, b)                                                     \
  asm volatile("mma.sync.aligned.m16n8k16.row.col.f32.bf16.bf16.f32 "        \
               "{%0,%1,%2,%3}, {%4,%5,%6,%7}, {%8,%9}, {%0,%1,%2,%3};"       \
               : "+f"(d[0]), "+f"(d[1]), "+f"(d[2]), "+f"(d[3])              \
               : "r"(a[0]), "r"(a[1]), "r"(a[2]), "r"(a[3]),                 \
                 "r"(b[0]), "r"(b[1]))

#define LDSM4(r0, r1, r2, r3, addr)                                           \
  asm volatile("ldmatrix.sync.aligned.m8n8.x4.shared.b16 {%0,%1,%2,%3}, [%4];"\
               : "=r"(r0), "=r"(r1), "=r"(r2), "=r"(r3) : "r"(addr))

__device__ __forceinline__ uint32_t swz128(uint32_t off) {
    return off ^ ((off >> 3) & 0x70);   // SW128: conflict-free 128B rows
}

// ---------------- fp32 -> bf16 hi/lo, full-width 16B stores, x2 group ILP ----------
__global__ void cvt_split_kernel(const float* __restrict__ src,
                                 __nv_bfloat16* __restrict__ hi,
                                 __nv_bfloat16* __restrict__ lo, int n8) {
    const int stride = gridDim.x * blockDim.x;
    const int i0 = blockIdx.x * blockDim.x + threadIdx.x;
    float4 a[2], b[2];
    int k[2];
    bool ok[2];
#pragma unroll
    for (int j = 0; j < 2; j++) {
        k[j] = i0 + j * stride;
        ok[j] = k[j] < n8;
        if (ok[j]) {
            a[j] = ((const float4*)src)[2 * k[j]];
            b[j] = ((const float4*)src)[2 * k[j] + 1];
        }
    }
#pragma unroll
    for (int j = 0; j < 2; j++) {
        if (!ok[j]) continue;
        __nv_bfloat16 h[8], l[8];
        split1(a[j].x, h[0], l[0]); split1(a[j].y, h[1], l[1]);
        split1(a[j].z, h[2], l[2]); split1(a[j].w, h[3], l[3]);
        split1(b[j].x, h[4], l[4]); split1(b[j].y, h[5], l[5]);
        split1(b[j].z, h[6], l[6]); split1(b[j].w, h[7], l[7]);
        ((uint4*)hi)[k[j]] = *(uint4*)h;
        ((uint4*)lo)[k[j]] = *(uint4*)l;
    }
}
static inline int cvt_grid8(int n8) { return (n8 + 2 * 256 - 1) / (2 * 256); }

// ========== mma.sync NT GEMM: 512 threads, 16 warps (32x32 tiles), BK=64 ==========
#define OPB (128 * 128)         // bytes per operand per stage (128 rows x 128B)
#define STG (4 * OPB)           // Ah|Al|Bh|Bl = 64 KB
#define NSTAGE 2
#define GEMM_SMEM (NSTAGE * STG)  // 128 KB
#define GTHREADS 512

__global__ __launch_bounds__(GTHREADS)
void tc_gemm(const __nv_bfloat16* __restrict__ Ah, const __nv_bfloat16* __restrict__ Al,
             const __nv_bfloat16* __restrict__ Wh, const __nv_bfloat16* __restrict__ Wl,
             float* __restrict__ C, int Nn, int Kk, int nchunk, size_t zstride,
             const float* __restrict__ epi_bias) {
    extern __shared__ __align__(1024) char dsm[];
    const uint32_t sbase = smem_u32(dsm);

    const int tid = threadIdx.x;
    const int lane = tid & 31;
    const int wid = tid >> 5;           // 0..15
    const int bm = blockIdx.y * 128;
    const int bn = blockIdx.x * 128;
    const int wm = (wid >> 2) * 32;     // 4 warp rows of 32
    const int wn = (wid & 3) * 32;      // 4 warp cols of 32
    const int qk = (lane & 3) * 2;
    const int lr = lane >> 2;

    const int chunkK = Kk / nchunk;
    const int kbase = blockIdx.z * chunkK;
    C += (size_t)blockIdx.z * zstride;

    const __nv_bfloat16* srcs[4] = { Ah, Al, Wh, Wl };

    auto load_stage = [&](int s, int kc) {
        const int k0 = kbase + kc * 64;
        const uint32_t stg = sbase + s * STG;
#pragma unroll
        for (int t = 0; t < 4; t++) {
            const __nv_bfloat16* sp = srcs[t];
            const int r0 = (t < 2) ? bm : bn;
            const bool isB = (t >= 2);
#pragma unroll
            for (int i = 0; i < 2; i++) {
                int idx = i * GTHREADS + tid;    // 0..1023
                int row = idx >> 3, c = idx & 7;
                int gr = r0 + row;
                bool ok = (!isB) || (gr < Nn);
                uint32_t dst = stg + t * OPB + swz128((uint32_t)(row * 128 + c * 16));
                cp16(dst, sp + (size_t)gr * Kk + k0 + c * 8, ok);
            }
        }
    };

    float acc[2][4][4];
#pragma unroll
    for (int mt = 0; mt < 2; mt++)
#pragma unroll
        for (int nt = 0; nt < 4; nt++)
#pragma unroll
            for (int j = 0; j < 4; j++) acc[mt][nt][j] = 0.f;

    const int nk = chunkK / 64;

    load_stage(0, 0); cp_commit();
    if (nk > 1) load_stage(1, 1);
    cp_commit();

    const int rA = lane & 15;           // ldmatrix row within 16
    const int cHi = lane >> 4;          // ldmatrix chunk select (0/1)

    // hoisted swizzled fragment offsets; ks*32 XORs into disjoint bits
    uint32_t aOff[2], bOff[2];
#pragma unroll
    for (int mt = 0; mt < 2; mt++)
        aOff[mt] = swz128((uint32_t)((wm + mt * 16 + rA) * 128)) ^ (uint32_t)(cHi * 16);
#pragma unroll
    for (int p = 0; p < 2; p++)
        bOff[p] = swz128((uint32_t)((wn + p * 16 + rA) * 128)) ^ (uint32_t)(cHi * 16);

    for (int kc = 0; kc < nk; kc++) {
        const int s = kc & 1;
        cp_wait1();
        __syncthreads();

        const uint32_t stg = sbase + s * STG;
#pragma unroll
        for (int ks = 0; ks < 4; ks++) {
            const uint32_t kx = (uint32_t)(ks * 32);
            // term 1: Ah x Bh
            uint32_t ah[2][4], bh[4][2];
#pragma unroll
            for (int mt = 0; mt < 2; mt++)
                LDSM4(ah[mt][0], ah[mt][1], ah[mt][2], ah[mt][3], stg + (aOff[mt] ^ kx));
#pragma unroll
            for (int p = 0; p < 2; p++) {
                uint32_t r0, r1, r2, r3;
                LDSM4(r0, r1, r2, r3, stg + 2 * OPB + (bOff[p] ^ kx));
                bh[2*p][0] = r0; bh[2*p+1][0] = r1; bh[2*p][1] = r2; bh[2*p+1][1] = r3;
            }
#pragma unroll
            for (int mt = 0; mt < 2; mt++)
#pragma unroll
                for (int nt = 0; nt < 4; nt++)
                    MMA_BF16(acc[mt][nt], ah[mt], bh[nt]);

            // term 2: Al x Bh
            {
                uint32_t al[2][4];
#pragma unroll
                for (int mt = 0; mt < 2; mt++)
                    LDSM4(al[mt][0], al[mt][1], al[mt][2], al[mt][3],
                          stg + OPB + (aOff[mt] ^ kx));
#pragma unroll
                for (int mt = 0; mt < 2; mt++)
#pragma unroll
                    for (int nt = 0; nt < 4; nt++)
                        MMA_BF16(acc[mt][nt], al[mt], bh[nt]);
            }

            // term 3: Ah x Bl
            {
                uint32_t bl[4][2];
#pragma unroll
                for (int p = 0; p < 2; p++) {
                    uint32_t r0, r1, r2, r3;
                    LDSM4(r0, r1, r2, r3, stg + 3 * OPB + (bOff[p] ^ kx));
                    bl[2*p][0] = r0; bl[2*p+1][0] = r1; bl[2*p][1] = r2; bl[2*p+1][1] = r3;
                }
#pragma unroll
                for (int mt = 0; mt < 2; mt++)
#pragma unroll
                    for (int nt = 0; nt < 4; nt++)
                        MMA_BF16(acc[mt][nt], ah[mt], bl[nt]);
            }
        }
        __syncthreads();
        int kn = kc + NSTAGE;
        if (kn < nk) load_stage(s, kn);
        cp_commit();
    }

    // epilogue (optionally fused bias + softplus)
    const bool do_sp = (epi_bias != nullptr);
#pragma unroll
    for (int mt = 0; mt < 2; mt++) {
        int r = bm + wm + mt * 16 + lr;
#pragma unroll
        for (int nt = 0; nt < 4; nt++) {
            int c = bn + wn + nt * 8 + qk;
            if (c < Nn) {
                float v[4] = {acc[mt][nt][0], acc[mt][nt][1], acc[mt][nt][2], acc[mt][nt][3]};
                if (do_sp) {
                    float b0 = epi_bias[c], b1 = epi_bias[c + 1];
                    float x0 = v[0] + b0, x1 = v[1] + b1, x2 = v[2] + b0, x3 = v[3] + b1;
                    v[0] = (x0 > 20.f) ? x0 : log1pf(__expf(x0));
                    v[1] = (x1 > 20.f) ? x1 : log1pf(__expf(x1));
                    v[2] = (x2 > 20.f) ? x2 : log1pf(__expf(x2));
                    v[3] = (x3 > 20.f) ? x3 : log1pf(__expf(x3));
                }
                *(float2*)&C[(size_t)r * Nn + c] = make_float2(v[0], v[1]);
                *(float2*)&C[(size_t)(r + 8) * Nn + c] = make_float2(v[2], v[3]);
            }
        }
    }
}

// ---------------- depthwise causal conv(K=4) + bias + SiLU (+ bf16 split out) ------
__global__ void conv_silu_kernel(const float* __restrict__ cw, const float* __restrict__ cb) {
    int i = blockIdx.x * blockDim.x + threadIdx.x;
    if (i >= TT * DI) return;
    int d = i & (DI - 1);
    int t = i >> 12;
    int l = t & (LL - 1);
    int b = t >> 9;
    float acc = cb[d];
#pragma unroll
    for (int k = 0; k < KC; k++) {
        int li = l - (KC - 1) + k;
        if (li >= 0)
            acc = fmaf(g_proj[(size_t)(b * LL + li) * E2 + d], cw[d * KC + k], acc);
    }
    float s = acc / (1.f + __expf(-acc));
    g_h[i] = s;
    __nv_bfloat16 h, lo2; split1(s, h, lo2);
    c_h_h[i] = h; c_h_l[i] = lo2;
}

// ---------------- RMSNorm (reads split-K partials directly) ----------------
__global__ void rmsnorm_kernel(const float* __restrict__ dt_w,
                               const float* __restrict__ b_w,
                               const float* __restrict__ c_w) {
    int t = blockIdx.x;
    int tid = threadIdx.x;              // 128 threads

    float x = 0.f;
#pragma unroll
    for (int z = 0; z < XSPLIT; z++)
        x += g_ssm_part[(size_t)z * TT * NSSM + (size_t)t * NSSM + tid];

    float ss = x * x;
#pragma unroll
    for (int o = 16; o > 0; o >>= 1) ss += __shfl_xor_sync(0xffffffffu, ss, o);
    __shared__ float wsum[4];
    if ((tid & 31) == 0) wsum[tid >> 5] = ss;
    __syncthreads();
    float tot = wsum[0] + wsum[1] + wsum[2] + wsum[3];
    float scale = rsqrtf(tot * (1.f / RR) + 1e-6f);
    float o1 = x * scale * dt_w[tid];
    __nv_bfloat16 h, lo2; split1(o1, h, lo2);
    c_dtin_h[(size_t)t * RR + tid] = h;
    c_dtin_l[(size_t)t * RR + tid] = lo2;

    if (tid < 32) {
        int grp = tid >> 4;
        int n = tid & 15;
        float v = 0.f;
#pragma unroll
        for (int z = 0; z < XSPLIT; z++)
            v += g_ssm_part[(size_t)z * TT * NSSM + (size_t)t * NSSM + RR + grp * NN + n];
        float vs = v * v;
#pragma unroll
        for (int o = 8; o > 0; o >>= 1) vs += __shfl_xor_sync(0xffffffffu, vs, o);
        float sc = rsqrtf(vs * (1.f / NN) + 1e-6f);
        float w = grp ? c_w[n] : b_w[n];
        float outv = v * sc * w;
        if (grp == 0) g_Bn[(size_t)t * NN + n] = outv;
        else          g_Cn[(size_t)t * NN + n] = outv;
    }
}

// ---------------- selective scan, depth-2 prefetch ----------------
__global__ void scan_kernel(const float* __restrict__ A_log,
                            const float* __restrict__ D_param) {
    const int b  = blockIdx.x >> 6;              // 64 blocks per batch (DI/64)
    const int d  = (blockIdx.x & 63) * 64 + threadIdx.x;
    const int tid = threadIdx.x;

    float Av[NN];
#pragma unroll
    for (int n = 0; n < NN; n++) Av[n] = -__expf(A_log[d * NN + n]);
    float state[NN];
#pragma unroll
    for (int n = 0; n < NN; n++) state[n] = 0.f;
    const float Dv = D_param[d];

    __shared__ float sBC[2][2 * NN];

    float dtv[2], hv[2], gv[2], bc[2];

    auto issue = [&](int slot, int l) {
        int t = b * LL + l;
        dtv[slot] = g_dt[(size_t)t * DI + d];
        hv[slot]  = g_h [(size_t)t * DI + d];
        gv[slot]  = g_proj[(size_t)t * E2 + DI + d];
        if (tid < 32)
            bc[slot] = (tid < NN) ? g_Bn[(size_t)t * NN + tid]
                                  : g_Cn[(size_t)t * NN + (tid - NN)];
    };

    issue(0, 0);
    issue(1, 1);
    if (tid < 32) { sBC[0][tid] = bc[0]; sBC[1][tid] = bc[1]; }
    __syncthreads();

    for (int l = 0; l < LL; l++) {
        const int s = l & 1;
        const float cdt = dtv[s], ch = hv[s], cg = gv[s];
        const bool pf = (l + 2 < LL);
        if (pf) issue(s, l + 2);

        const float dh = cdt * ch;
        float yv = 0.f;
#pragma unroll
        for (int n = 0; n < NN; n++) {
            float dA = __expf(cdt * Av[n]);
            state[n] = fmaf(state[n], dA, dh * sBC[s][n]);
            yv = fmaf(state[n], sBC[s][NN + n], yv);
        }
        float sg = cg / (1.f + __expf(-cg));
        int t = b * LL + l;
        float yo = (yv + ch * Dv) * sg;
        __nv_bfloat16 h, lo2; split1(yo, h, lo2);
        c_y_h[(size_t)t * DI + d] = h;
        c_y_l[(size_t)t * DI + d] = lo2;

        __syncthreads();
        if (pf && tid < 32) sBC[s][tid] = bc[s];
    }
}

// ---------------- launch ----------------
extern "C" void kernel_launch(void* const* d_in, const int* in_sizes, int n_in,
                              void* d_out, int out_size) {
    const float* hs        = (const float*)d_in[0];
    const float* in_proj_w = (const float*)d_in[1];
    const float* conv_w    = (const float*)d_in[2];
    const float* conv_b    = (const float*)d_in[3];
    const float* x_proj_w  = (const float*)d_in[4];
    const float* dt_ln_w   = (const float*)d_in[5];
    const float* b_ln_w    = (const float*)d_in[6];
    const float* c_ln_w    = (const float*)d_in[7];
    const float* dt_proj_w = (const float*)d_in[8];
    const float* dt_proj_b = (const float*)d_in[9];
    const float* A_log     = (const float*)d_in[10];
    const float* D_param   = (const float*)d_in[11];
    const float* out_proj_w= (const float*)d_in[12];
    float* out = (float*)d_out;

    cudaFuncSetAttribute(tc_gemm, cudaFuncAttributeMaxDynamicSharedMemorySize, GEMM_SMEM);

    float *p_proj, *p_part, *p_dt;
    cudaGetSymbolAddress((void**)&p_proj, g_proj);
    cudaGetSymbolAddress((void**)&p_part, g_ssm_part);
    cudaGetSymbolAddress((void**)&p_dt,   g_dt);
    __nv_bfloat16 *hs_h, *hs_l, *inw_h, *inw_l, *h_h, *h_l, *xw_h, *xw_l;
    __nv_bfloat16 *dtin_h, *dtin_l, *dtw_h, *dtw_l, *y_h, *y_l, *ow_h, *ow_l;
    cudaGetSymbolAddress((void**)&hs_h, c_hs_h);   cudaGetSymbolAddress((void**)&hs_l, c_hs_l);
    cudaGetSymbolAddress((void**)&inw_h, c_inw_h); cudaGetSymbolAddress((void**)&inw_l, c_inw_l);
    cudaGetSymbolAddress((void**)&h_h, c_h_h);     cudaGetSymbolAddress((void**)&h_l, c_h_l);
    cudaGetSymbolAddress((void**)&xw_h, c_xw_h);   cudaGetSymbolAddress((void**)&xw_l, c_xw_l);
    cudaGetSymbolAddress((void**)&dtin_h, c_dtin_h); cudaGetSymbolAddress((void**)&dtin_l, c_dtin_l);
    cudaGetSymbolAddress((void**)&dtw_h, c_dtw_h); cudaGetSymbolAddress((void**)&dtw_l, c_dtw_l);
    cudaGetSymbolAddress((void**)&y_h, c_y_h);     cudaGetSymbolAddress((void**)&y_l, c_y_l);
    cudaGetSymbolAddress((void**)&ow_h, c_ow_h);   cudaGetSymbolAddress((void**)&ow_l, c_ow_l);

    // 0,1,2) splits needed by in_proj + x_proj
    cvt_split_kernel<<<cvt_grid8(TT*HH/8), 256>>>(hs, hs_h, hs_l, TT*HH/8);
    cvt_split_kernel<<<cvt_grid8(E2*HH/8), 256>>>(in_proj_w, inw_h, inw_l, E2*HH/8);
    cvt_split_kernel<<<cvt_grid8(NSSM*DI/8), 256>>>(x_proj_w, xw_h, xw_l, NSSM*DI/8);

    // 3) in_proj GEMM
    tc_gemm<<<dim3(E2/128, TT/128, 1), GTHREADS, GEMM_SMEM>>>(hs_h, hs_l, inw_h, inw_l,
                                                              p_proj, E2, HH, 1, 0, nullptr);

    // 4) depthwise conv + silu -> g_h (+ split)
    conv_silu_kernel<<<(TT*DI + 255)/256, 256>>>(conv_w, conv_b);

    // 5) x_proj split-K x8
    tc_gemm<<<dim3((NSSM + 127)/128, TT/128, XSPLIT), GTHREADS, GEMM_SMEM>>>(
        h_h, h_l, xw_h, xw_l, p_part, NSSM, DI, XSPLIT, (size_t)TT * NSSM, nullptr);

    // 6) dt_proj_w split
    cvt_split_kernel<<<cvt_grid8(DI*RR/8), 256>>>(dt_proj_w, dtw_h, dtw_l, DI*RR/8);

    // 7) rmsnorms (fused split-K reduce)
    rmsnorm_kernel<<<TT, 128>>>(dt_ln_w, b_ln_w, c_ln_w);

    // 8) dt_proj GEMM, bias+softplus fused
    tc_gemm<<<dim3(DI/128, TT/128, 1), GTHREADS, GEMM_SMEM>>>(dtin_h, dtin_l, dtw_h, dtw_l,
                                                              p_dt, DI, RR, 1, 0, dt_proj_b);

    // 9) selective scan + D skip + gate silu -> c_y (split)
    scan_kernel<<<BB * (DI/64), 64>>>(A_log, D_param);

    // 10) out_proj_w split
    cvt_split_kernel<<<cvt_grid8(HH*DI/8), 256>>>(out_proj_w, ow_h, ow_l, HH*DI/8);

    // 11) out_proj GEMM
    tc_gemm<<<dim3(HH/128, TT/128, 1), GTHREADS, GEMM_SMEM>>>(y_h, y_l, ow_h, ow_l,
                                                              out, HH, DI, 1, 0, nullptr);
}

// round 10
// speedup vs baseline: 3.6157x; 1.6141x over previous
#include <cuda_runtime.h>
#include <cuda_bf16.h>
#include <math.h>
#include <stdint.h>

// ---------------- problem constants ----------------
#define BB 2
#define LL 512
#define HH 2048
#define DI 4096
#define NN 16
#define KC 4
#define RR 128
#define TT (BB*LL)           // 1024 tokens
#define E2 (2*DI)            // 8192
#define NSSM (RR + 2*NN)     // 160
#define XSPLIT 8             // split-K chunks for x_proj
#define CC 8                 // scan chunks
#define CLEN (LL / CC)       // 64 steps per chunk
#define DBLK (DI / 64)       // 64 d-blocks of 64 channels

// ---------------- fp32 scratch ----------------
__device__ float g_proj[TT * E2];     // in_proj output [T, 8192] (h | gate)
__device__ float g_h[TT * DI];        // post conv+silu fp32 (for scan)
__device__ float g_ssm_part[XSPLIT * TT * NSSM];
__device__ float g_Bn[TT * NN];
__device__ float g_Cn[TT * NN];
__device__ float g_dt[TT * DI];       // dt after proj (+bias, softplus fused in GEMM)
// chunked-scan summaries: layout [b][c][d][n]
__device__ float g_scP[BB * CC * DI * NN];
__device__ float g_scS[BB * CC * DI * NN];
__device__ float g_scI[BB * CC * DI * NN];

// ---------------- bf16 hi/lo split operands ----------------
__device__ __nv_bfloat16 c_hs_h[TT * HH],  c_hs_l[TT * HH];
__device__ __nv_bfloat16 c_inw_h[E2 * HH], c_inw_l[E2 * HH];
__device__ __nv_bfloat16 c_h_h[TT * DI],   c_h_l[TT * DI];
__device__ __nv_bfloat16 c_xw_h[NSSM * DI], c_xw_l[NSSM * DI];
__device__ __nv_bfloat16 c_dtin_h[TT * RR], c_dtin_l[TT * RR];
__device__ __nv_bfloat16 c_dtw_h[DI * RR],  c_dtw_l[DI * RR];
__device__ __nv_bfloat16 c_y_h[TT * DI],    c_y_l[TT * DI];
__device__ __nv_bfloat16 c_ow_h[HH * DI],   c_ow_l[HH * DI];

// ---------------- helpers ----------------
__device__ __forceinline__ uint32_t smem_u32(const void* p) {
    uint32_t a;
    asm("{ .reg .u64 t; cvta.to.shared.u64 t, %1; cvt.u32.u64 %0, t; }" : "=r"(a) : "l"(p));
    return a;
}
__device__ __forceinline__ void split1(float f, __nv_bfloat16& h, __nv_bfloat16& l) {
    h = __float2bfloat16(f);
    l = __float2bfloat16(f - __bfloat162float(h));
}
__device__ __forceinline__ void cp16(uint32_t dst, const void* src, bool pred) {
    int sz = pred ? 16 : 0;
    asm volatile("cp.async.cg.shared.global [%0], [%1], 16, %2;"
                 :: "r"(dst), "l"(src), "r"(sz) : "memory");
}
__device__ __forceinline__ void cp_commit() {
    asm volatile("cp.async.commit_group;" ::: "memory");
}
__device__ __forceinline__ void cp_wait1() {
    asm volatile("cp.async.wait_group 1;" ::: "memory");
}

#define MMA_BF16(d, a, b)                                                     \
  asm volatile("mma.sync.aligned.m16n8k16.row.col.f32.bf16.bf16.f32 "        \
               "{%0,%1,%2,%3}, {%4,%5,%6,%7}, {%8,%9}, {%0,%1,%2,%3};"       \
               : "+f"(d[0]), "+f"(d[1]), "+f"(d[2]), "+f"(d[3])              \
               : "r"(a[0]), "r"(a[1]), "r"(a[2]), "r"(a[3]),                 \
                 "r"(b[0]), "r"(b[1]))

#define LDSM4(r0, r1, r2, r3, addr)                                           \
  asm volatile("ldmatrix.sync.aligned.m8n8.x4.shared.b16 {%0,%1,%2,%3}, [%4];"\
               : "=r"(r0), "=r"(r1), "=r"(r2), "=r"(r3) : "r"(addr))

__device__ __forceinline__ uint32_t swz128(uint32_t off) {
    return off ^ ((off >> 3) & 0x70);   // SW128: conflict-free 128B rows
}

// ---------------- fp32 -> bf16 hi/lo, full-width 16B stores, x2 group ILP ----------
__global__ void cvt_split_kernel(const float* __restrict__ src,
                                 __nv_bfloat16* __restrict__ hi,
                                 __nv_bfloat16* __restrict__ lo, int n8) {
    const int stride = gridDim.x * blockDim.x;
    const int i0 = blockIdx.x * blockDim.x + threadIdx.x;
    float4 a[2], b[2];
    int k[2];
    bool ok[2];
#pragma unroll
    for (int j = 0; j < 2; j++) {
        k[j] = i0 + j * stride;
        ok[j] = k[j] < n8;
        if (ok[j]) {
            a[j] = ((const float4*)src)[2 * k[j]];
            b[j] = ((const float4*)src)[2 * k[j] + 1];
        }
    }
#pragma unroll
    for (int j = 0; j < 2; j++) {
        if (!ok[j]) continue;
        __nv_bfloat16 h[8], l[8];
        split1(a[j].x, h[0], l[0]); split1(a[j].y, h[1], l[1]);
        split1(a[j].z, h[2], l[2]); split1(a[j].w, h[3], l[3]);
        split1(b[j].x, h[4], l[4]); split1(b[j].y, h[5], l[5]);
        split1(b[j].z, h[6], l[6]); split1(b[j].w, h[7], l[7]);
        ((uint4*)hi)[k[j]] = *(uint4*)h;
        ((uint4*)lo)[k[j]] = *(uint4*)l;
    }
}
static inline int cvt_grid8(int n8) { return (n8 + 2 * 256 - 1) / (2 * 256); }

// ========== mma.sync NT GEMM: 512 threads, 16 warps (32x32 tiles), BK=64 ==========
#define OPB (128 * 128)         // bytes per operand per stage (128 rows x 128B)
#define STG (4 * OPB)           // Ah|Al|Bh|Bl = 64 KB
#define NSTAGE 2
#define GEMM_SMEM (NSTAGE * STG)  // 128 KB
#define GTHREADS 512

__global__ __launch_bounds__(GTHREADS)
void tc_gemm(const __nv_bfloat16* __restrict__ Ah, const __nv_bfloat16* __restrict__ Al,
             const __nv_bfloat16* __restrict__ Wh, const __nv_bfloat16* __restrict__ Wl,
             float* __restrict__ C, int Nn, int Kk, int nchunk, size_t zstride,
             const float* __restrict__ epi_bias) {
    extern __shared__ __align__(1024) char dsm[];
    const uint32_t sbase = smem_u32(dsm);

    const int tid = threadIdx.x;
    const int lane = tid & 31;
    const int wid = tid >> 5;           // 0..15
    const int bm = blockIdx.y * 128;
    const int bn = blockIdx.x * 128;
    const int wm = (wid >> 2) * 32;     // 4 warp rows of 32
    const int wn = (wid & 3) * 32;      // 4 warp cols of 32
    const int qk = (lane & 3) * 2;
    const int lr = lane >> 2;

    const int chunkK = Kk / nchunk;
    const int kbase = blockIdx.z * chunkK;
    C += (size_t)blockIdx.z * zstride;

    const __nv_bfloat16* srcs[4] = { Ah, Al, Wh, Wl };

    auto load_stage = [&](int s, int kc) {
        const int k0 = kbase + kc * 64;
        const uint32_t stg = sbase + s * STG;
#pragma unroll
        for (int t = 0; t < 4; t++) {
            const __nv_bfloat16* sp = srcs[t];
            const int r0 = (t < 2) ? bm : bn;
            const bool isB = (t >= 2);
#pragma unroll
            for (int i = 0; i < 2; i++) {
                int idx = i * GTHREADS + tid;    // 0..1023
                int row = idx >> 3, c = idx & 7;
                int gr = r0 + row;
                bool ok = (!isB) || (gr < Nn);
                uint32_t dst = stg + t * OPB + swz128((uint32_t)(row * 128 + c * 16));
                cp16(dst, sp + (size_t)gr * Kk + k0 + c * 8, ok);
            }
        }
    };

    float acc[2][4][4];
#pragma unroll
    for (int mt = 0; mt < 2; mt++)
#pragma unroll
        for (int nt = 0; nt < 4; nt++)
#pragma unroll
            for (int j = 0; j < 4; j++) acc[mt][nt][j] = 0.f;

    const int nk = chunkK / 64;

    load_stage(0, 0); cp_commit();
    if (nk > 1) load_stage(1, 1);
    cp_commit();

    const int rA = lane & 15;           // ldmatrix row within 16
    const int cHi = lane >> 4;          // ldmatrix chunk select (0/1)

    uint32_t aOff[2], bOff[2];
#pragma unroll
    for (int mt = 0; mt < 2; mt++)
        aOff[mt] = swz128((uint32_t)((wm + mt * 16 + rA) * 128)) ^ (uint32_t)(cHi * 16);
#pragma unroll
    for (int p = 0; p < 2; p++)
        bOff[p] = swz128((uint32_t)((wn + p * 16 + rA) * 128)) ^ (uint32_t)(cHi * 16);

    for (int kc = 0; kc < nk; kc++) {
        const int s = kc & 1;
        cp_wait1();
        __syncthreads();

        const uint32_t stg = sbase + s * STG;
#pragma unroll
        for (int ks = 0; ks < 4; ks++) {
            const uint32_t kx = (uint32_t)(ks * 32);
            uint32_t ah[2][4], bh[4][2];
#pragma unroll
            for (int mt = 0; mt < 2; mt++)
                LDSM4(ah[mt][0], ah[mt][1], ah[mt][2], ah[mt][3], stg + (aOff[mt] ^ kx));
#pragma unroll
            for (int p = 0; p < 2; p++) {
                uint32_t r0, r1, r2, r3;
                LDSM4(r0, r1, r2, r3, stg + 2 * OPB + (bOff[p] ^ kx));
                bh[2*p][0] = r0; bh[2*p+1][0] = r1; bh[2*p][1] = r2; bh[2*p+1][1] = r3;
            }
#pragma unroll
            for (int mt = 0; mt < 2; mt++)
#pragma unroll
                for (int nt = 0; nt < 4; nt++)
                    MMA_BF16(acc[mt][nt], ah[mt], bh[nt]);

            {
                uint32_t al[2][4];
#pragma unroll
                for (int mt = 0; mt < 2; mt++)
                    LDSM4(al[mt][0], al[mt][1], al[mt][2], al[mt][3],
                          stg + OPB + (aOff[mt] ^ kx));
#pragma unroll
                for (int mt = 0; mt < 2; mt++)
#pragma unroll
                    for (int nt = 0; nt < 4; nt++)
                        MMA_BF16(acc[mt][nt], al[mt], bh[nt]);
            }

            {
                uint32_t bl[4][2];
#pragma unroll
                for (int p = 0; p < 2; p++) {
                    uint32_t r0, r1, r2, r3;
                    LDSM4(r0, r1, r2, r3, stg + 3 * OPB + (bOff[p] ^ kx));
                    bl[2*p][0] = r0; bl[2*p+1][0] = r1; bl[2*p][1] = r2; bl[2*p+1][1] = r3;
                }
#pragma unroll
                for (int mt = 0; mt < 2; mt++)
#pragma unroll
                    for (int nt = 0; nt < 4; nt++)
                        MMA_BF16(acc[mt][nt], ah[mt], bl[nt]);
            }
        }
        __syncthreads();
        int kn = kc + NSTAGE;
        if (kn < nk) load_stage(s, kn);
        cp_commit();
    }

    const bool do_sp = (epi_bias != nullptr);
#pragma unroll
    for (int mt = 0; mt < 2; mt++) {
        int r = bm + wm + mt * 16 + lr;
#pragma unroll
        for (int nt = 0; nt < 4; nt++) {
            int c = bn + wn + nt * 8 + qk;
            if (c < Nn) {
                float v[4] = {acc[mt][nt][0], acc[mt][nt][1], acc[mt][nt][2], acc[mt][nt][3]};
                if (do_sp) {
                    float b0 = epi_bias[c], b1 = epi_bias[c + 1];
                    float x0 = v[0] + b0, x1 = v[1] + b1, x2 = v[2] + b0, x3 = v[3] + b1;
                    v[0] = (x0 > 20.f) ? x0 : log1pf(__expf(x0));
                    v[1] = (x1 > 20.f) ? x1 : log1pf(__expf(x1));
                    v[2] = (x2 > 20.f) ? x2 : log1pf(__expf(x2));
                    v[3] = (x3 > 20.f) ? x3 : log1pf(__expf(x3));
                }
                *(float2*)&C[(size_t)r * Nn + c] = make_float2(v[0], v[1]);
                *(float2*)&C[(size_t)(r + 8) * Nn + c] = make_float2(v[2], v[3]);
            }
        }
    }
}

// ---------------- depthwise causal conv(K=4) + bias + SiLU (+ bf16 split out) ------
__global__ void conv_silu_kernel(const float* __restrict__ cw, const float* __restrict__ cb) {
    int i = blockIdx.x * blockDim.x + threadIdx.x;
    if (i >= TT * DI) return;
    int d = i & (DI - 1);
    int t = i >> 12;
    int l = t & (LL - 1);
    int b = t >> 9;
    float acc = cb[d];
#pragma unroll
    for (int k = 0; k < KC; k++) {
        int li = l - (KC - 1) + k;
        if (li >= 0)
            acc = fmaf(g_proj[(size_t)(b * LL + li) * E2 + d], cw[d * KC + k], acc);
    }
    float s = acc / (1.f + __expf(-acc));
    g_h[i] = s;
    __nv_bfloat16 h, lo2; split1(s, h, lo2);
    c_h_h[i] = h; c_h_l[i] = lo2;
}

// ---------------- RMSNorm (reads split-K partials directly) ----------------
__global__ void rmsnorm_kernel(const float* __restrict__ dt_w,
                               const float* __restrict__ b_w,
                               const float* __restrict__ c_w) {
    int t = blockIdx.x;
    int tid = threadIdx.x;              // 128 threads

    float x = 0.f;
#pragma unroll
    for (int z = 0; z < XSPLIT; z++)
        x += g_ssm_part[(size_t)z * TT * NSSM + (size_t)t * NSSM + tid];

    float ss = x * x;
#pragma unroll
    for (int o = 16; o > 0; o >>= 1) ss += __shfl_xor_sync(0xffffffffu, ss, o);
    __shared__ float wsum[4];
    if ((tid & 31) == 0) wsum[tid >> 5] = ss;
    __syncthreads();
    float tot = wsum[0] + wsum[1] + wsum[2] + wsum[3];
    float scale = rsqrtf(tot * (1.f / RR) + 1e-6f);
    float o1 = x * scale * dt_w[tid];
    __nv_bfloat16 h, lo2; split1(o1, h, lo2);
    c_dtin_h[(size_t)t * RR + tid] = h;
    c_dtin_l[(size_t)t * RR + tid] = lo2;

    if (tid < 32) {
        int grp = tid >> 4;
        int n = tid & 15;
        float v = 0.f;
#pragma unroll
        for (int z = 0; z < XSPLIT; z++)
            v += g_ssm_part[(size_t)z * TT * NSSM + (size_t)t * NSSM + RR + grp * NN + n];
        float vs = v * v;
#pragma unroll
        for (int o = 8; o > 0; o >>= 1) vs += __shfl_xor_sync(0xffffffffu, vs, o);
        float sc = rsqrtf(vs * (1.f / NN) + 1e-6f);
        float w = grp ? c_w[n] : b_w[n];
        float outv = v * sc * w;
        if (grp == 0) g_Bn[(size_t)t * NN + n] = outv;
        else          g_Cn[(size_t)t * NN + n] = outv;
    }
}

// ================= chunked parallel scan =================
// pass 1: per (b, chunk, d-block): local scan from 0, emit P = prod(dA), S = final state
__global__ void scan_pass1(const float* __restrict__ A_log) {
    int bx = blockIdx.x;
    int db = bx % DBLK; int tmp = bx / DBLK;
    int c = tmp % CC;   int b = tmp / CC;
    int d = db * 64 + threadIdx.x;

    float Av[NN];
#pragma unroll
    for (int n = 0; n < NN; n++) Av[n] = -__expf(A_log[d * NN + n]);
    float st[NN], P[NN];
#pragma unroll
    for (int n = 0; n < NN; n++) { st[n] = 0.f; P[n] = 1.f; }

    const int l0 = c * CLEN;
    for (int l = l0; l < l0 + CLEN; l++) {
        int t = b * LL + l;
        float dtv = g_dt[(size_t)t * DI + d];
        float hv  = g_h [(size_t)t * DI + d];
        const float4* Bp = (const float4*)(g_Bn + (size_t)t * NN);
        float4 B4[4] = { Bp[0], Bp[1], Bp[2], Bp[3] };
        const float* Bv = (const float*)B4;
        float dh = dtv * hv;
#pragma unroll
        for (int n = 0; n < NN; n++) {
            float dA = __expf(dtv * Av[n]);
            st[n] = fmaf(st[n], dA, dh * Bv[n]);
            P[n] *= dA;
        }
    }
    size_t base = ((size_t)(b * CC + c) * DI + d) * NN;
#pragma unroll
    for (int n = 0; n < NN; n += 4) {
        *(float4*)&g_scP[base + n] = make_float4(P[n], P[n+1], P[n+2], P[n+3]);
        *(float4*)&g_scS[base + n] = make_float4(st[n], st[n+1], st[n+2], st[n+3]);
    }
}

// combine: serial over CC chunks per channel; writes per-chunk initial states
__global__ void scan_combine() {
    int bx = blockIdx.x;                 // BB*DBLK blocks
    int db = bx % DBLK; int b = bx / DBLK;
    int d = db * 64 + threadIdx.x;

    float s[NN];
#pragma unroll
    for (int n = 0; n < NN; n++) s[n] = 0.f;

    for (int c = 0; c < CC; c++) {
        size_t base = ((size_t)(b * CC + c) * DI + d) * NN;
#pragma unroll
        for (int n = 0; n < NN; n += 4)
            *(float4*)&g_scI[base + n] = make_float4(s[n], s[n+1], s[n+2], s[n+3]);
        float P[NN], S[NN];
#pragma unroll
        for (int n = 0; n < NN; n += 4) {
            float4 p4 = *(const float4*)&g_scP[base + n];
            float4 s4 = *(const float4*)&g_scS[base + n];
            P[n] = p4.x; P[n+1] = p4.y; P[n+2] = p4.z; P[n+3] = p4.w;
            S[n] = s4.x; S[n+1] = s4.y; S[n+2] = s4.z; S[n+3] = s4.w;
        }
#pragma unroll
        for (int n = 0; n < NN; n++) s[n] = fmaf(P[n], s[n], S[n]);
    }
}

// pass 2: rerun chunk from correct init, produce y + D-skip + gate silu
__global__ void scan_pass2(const float* __restrict__ A_log,
                           const float* __restrict__ D_param) {
    int bx = blockIdx.x;
    int db = bx % DBLK; int tmp = bx / DBLK;
    int c = tmp % CC;   int b = tmp / CC;
    int d = db * 64 + threadIdx.x;

    float Av[NN];
#pragma unroll
    for (int n = 0; n < NN; n++) Av[n] = -__expf(A_log[d * NN + n]);
    float st[NN];
    {
        size_t base = ((size_t)(b * CC + c) * DI + d) * NN;
#pragma unroll
        for (int n = 0; n < NN; n += 4) {
            float4 v = *(const float4*)&g_scI[base + n];
            st[n] = v.x; st[n+1] = v.y; st[n+2] = v.z; st[n+3] = v.w;
        }
    }
    const float Dv = D_param[d];

    const int l0 = c * CLEN;
    for (int l = l0; l < l0 + CLEN; l++) {
        int t = b * LL + l;
        float dtv = g_dt[(size_t)t * DI + d];
        float hv  = g_h [(size_t)t * DI + d];
        float gv  = g_proj[(size_t)t * E2 + DI + d];
        const float4* Bp = (const float4*)(g_Bn + (size_t)t * NN);
        const float4* Cp = (const float4*)(g_Cn + (size_t)t * NN);
        float4 B4[4] = { Bp[0], Bp[1], Bp[2], Bp[3] };
        float4 C4[4] = { Cp[0], Cp[1], Cp[2], Cp[3] };
        const float* Bv = (const float*)B4;
        const float* Cv = (const float*)C4;
        float dh = dtv * hv;
        float yv = 0.f;
#pragma unroll
        for (int n = 0; n < NN; n++) {
            float dA = __expf(dtv * Av[n]);
            st[n] = fmaf(st[n], dA, dh * Bv[n]);
            yv = fmaf(st[n], Cv[n], yv);
        }
        float sg = gv / (1.f + __expf(-gv));
        float yo = (yv + hv * Dv) * sg;
        __nv_bfloat16 h, lo2; split1(yo, h, lo2);
        c_y_h[(size_t)t * DI + d] = h;
        c_y_l[(size_t)t * DI + d] = lo2;
    }
}

// ---------------- launch ----------------
extern "C" void kernel_launch(void* const* d_in, const int* in_sizes, int n_in,
                              void* d_out, int out_size) {
    const float* hs        = (const float*)d_in[0];
    const float* in_proj_w = (const float*)d_in[1];
    const float* conv_w    = (const float*)d_in[2];
    const float* conv_b    = (const float*)d_in[3];
    const float* x_proj_w  = (const float*)d_in[4];
    const float* dt_ln_w   = (const float*)d_in[5];
    const float* b_ln_w    = (const float*)d_in[6];
    const float* c_ln_w    = (const float*)d_in[7];
    const float* dt_proj_w = (const float*)d_in[8];
    const float* dt_proj_b = (const float*)d_in[9];
    const float* A_log     = (const float*)d_in[10];
    const float* D_param   = (const float*)d_in[11];
    const float* out_proj_w= (const float*)d_in[12];
    float* out = (float*)d_out;

    cudaFuncSetAttribute(tc_gemm, cudaFuncAttributeMaxDynamicSharedMemorySize, GEMM_SMEM);

    float *p_proj, *p_part, *p_dt;
    cudaGetSymbolAddress((void**)&p_proj, g_proj);
    cudaGetSymbolAddress((void**)&p_part, g_ssm_part);
    cudaGetSymbolAddress((void**)&p_dt,   g_dt);
    __nv_bfloat16 *hs_h, *hs_l, *inw_h, *inw_l, *h_h, *h_l, *xw_h, *xw_l;
    __nv_bfloat16 *dtin_h, *dtin_l, *dtw_h, *dtw_l, *y_h, *y_l, *ow_h, *ow_l;
    cudaGetSymbolAddress((void**)&hs_h, c_hs_h);   cudaGetSymbolAddress((void**)&hs_l, c_hs_l);
    cudaGetSymbolAddress((void**)&inw_h, c_inw_h); cudaGetSymbolAddress((void**)&inw_l, c_inw_l);
    cudaGetSymbolAddress((void**)&h_h, c_h_h);     cudaGetSymbolAddress((void**)&h_l, c_h_l);
    cudaGetSymbolAddress((void**)&xw_h, c_xw_h);   cudaGetSymbolAddress((void**)&xw_l, c_xw_l);
    cudaGetSymbolAddress((void**)&dtin_h, c_dtin_h); cudaGetSymbolAddress((void**)&dtin_l, c_dtin_l);
    cudaGetSymbolAddress((void**)&dtw_h, c_dtw_h); cudaGetSymbolAddress((void**)&dtw_l, c_dtw_l);
    cudaGetSymbolAddress((void**)&y_h, c_y_h);     cudaGetSymbolAddress((void**)&y_l, c_y_l);
    cudaGetSymbolAddress((void**)&ow_h, c_ow_h);   cudaGetSymbolAddress((void**)&ow_l, c_ow_l);

    // splits needed by in_proj + x_proj
    cvt_split_kernel<<<cvt_grid8(TT*HH/8), 256>>>(hs, hs_h, hs_l, TT*HH/8);
    cvt_split_kernel<<<cvt_grid8(E2*HH/8), 256>>>(in_proj_w, inw_h, inw_l, E2*HH/8);
    cvt_split_kernel<<<cvt_grid8(NSSM*DI/8), 256>>>(x_proj_w, xw_h, xw_l, NSSM*DI/8);

    // in_proj GEMM
    tc_gemm<<<dim3(E2/128, TT/128, 1), GTHREADS, GEMM_SMEM>>>(hs_h, hs_l, inw_h, inw_l,
                                                              p_proj, E2, HH, 1, 0, nullptr);

    // depthwise conv + silu -> g_h (+ split)
    conv_silu_kernel<<<(TT*DI + 255)/256, 256>>>(conv_w, conv_b);

    // x_proj split-K x8
    tc_gemm<<<dim3((NSSM + 127)/128, TT/128, XSPLIT), GTHREADS, GEMM_SMEM>>>(
        h_h, h_l, xw_h, xw_l, p_part, NSSM, DI, XSPLIT, (size_t)TT * NSSM, nullptr);

    // dt_proj_w split
    cvt_split_kernel<<<cvt_grid8(DI*RR/8), 256>>>(dt_proj_w, dtw_h, dtw_l, DI*RR/8);

    // rmsnorms (fused split-K reduce)
    rmsnorm_kernel<<<TT, 128>>>(dt_ln_w, b_ln_w, c_ln_w);

    // dt_proj GEMM, bias+softplus fused
    tc_gemm<<<dim3(DI/128, TT/128, 1), GTHREADS, GEMM_SMEM>>>(dtin_h, dtin_l, dtw_h, dtw_l,
                                                              p_dt, DI, RR, 1, 0, dt_proj_b);

    // chunked scan: pass1 -> combine -> pass2
    scan_pass1<<<BB * CC * DBLK, 64>>>(A_log);
    scan_combine<<<BB * DBLK, 64>>>();
    scan_pass2<<<BB * CC * DBLK, 64>>>(A_log, D_param);

    // out_proj_w split
    cvt_split_kernel<<<cvt_grid8(HH*DI/8), 256>>>(out_proj_w, ow_h, ow_l, HH*DI/8);

    // out_proj GEMM
    tc_gemm<<<dim3(HH/128, TT/128, 1), GTHREADS, GEMM_SMEM>>>(y_h, y_l, ow_h, ow_l,
                                                              out, HH, DI, 1, 0, nullptr);
}

// round 11
// speedup vs baseline: 3.9720x; 1.0986x over previous
#include <cuda_runtime.h>
#include <cuda_bf16.h>
#include <math.h>
#include <stdint.h>

// ---------------- problem constants ----------------
#define BB 2
#define LL 512
#define HH 2048
#define DI 4096
#define NN 16
#define KC 4
#define RR 128
#define TT (BB*LL)           // 1024 tokens
#define E2 (2*DI)            // 8192
#define NSSM (RR + 2*NN)     // 160
#define XSPLIT 8             // split-K chunks for x_proj
#define CC 8                 // scan chunks
#define CLEN (LL / CC)       // 64 steps per chunk
#define DBLK (DI / 64)       // 64 d-blocks of 64 channels

// ---------------- fp32 scratch ----------------
__device__ float g_proj[TT * E2];     // in_proj output [T, 8192] (h | gate)
__device__ float g_h[TT * DI];        // post conv+silu fp32 (for scan)
__device__ float g_ssm_part[XSPLIT * TT * NSSM];
__device__ float g_Bn[TT * NN];
__device__ float g_Cn[TT * NN];
__device__ float g_dt[TT * DI];       // dt after proj (+bias, softplus fused in GEMM)
// chunked-scan summaries: layout [b][c][d][n]
__device__ float g_scP[BB * CC * DI * NN];
__device__ float g_scS[BB * CC * DI * NN];
__device__ float g_scI[BB * CC * DI * NN];

// ---------------- bf16 hi/lo split operands ----------------
__device__ __nv_bfloat16 c_hs_h[TT * HH],  c_hs_l[TT * HH];
__device__ __nv_bfloat16 c_inw_h[E2 * HH], c_inw_l[E2 * HH];
__device__ __nv_bfloat16 c_h_h[TT * DI],   c_h_l[TT * DI];
__device__ __nv_bfloat16 c_xw_h[NSSM * DI], c_xw_l[NSSM * DI];
__device__ __nv_bfloat16 c_dtin_h[TT * RR], c_dtin_l[TT * RR];
__device__ __nv_bfloat16 c_dtw_h[DI * RR],  c_dtw_l[DI * RR];
__device__ __nv_bfloat16 c_y_h[TT * DI],    c_y_l[TT * DI];
__device__ __nv_bfloat16 c_ow_h[HH * DI],   c_ow_l[HH * DI];

// ---------------- helpers ----------------
__device__ __forceinline__ uint32_t smem_u32(const void* p) {
    uint32_t a;
    asm("{ .reg .u64 t; cvta.to.shared.u64 t, %1; cvt.u32.u64 %0, t; }" : "=r"(a) : "l"(p));
    return a;
}
__device__ __forceinline__ void split1(float f, __nv_bfloat16& h, __nv_bfloat16& l) {
    h = __float2bfloat16(f);
    l = __float2bfloat16(f - __bfloat162float(h));
}
__device__ __forceinline__ void cp16(uint32_t dst, const void* src, bool pred) {
    int sz = pred ? 16 : 0;
    asm volatile("cp.async.cg.shared.global [%0], [%1], 16, %2;"
                 :: "r"(dst), "l"(src), "r"(sz) : "memory");
}
__device__ __forceinline__ void cp_commit() {
    asm volatile("cp.async.commit_group;" ::: "memory");
}
__device__ __forceinline__ void cp_wait1() {
    asm volatile("cp.async.wait_group 1;" ::: "memory");
}

#define MMA_BF16(d, a, b)                                                     \
  asm volatile("mma.sync.aligned.m16n8k16.row.col.f32.bf16.bf16.f32 "        \
               "{%0,%1,%2,%3}, {%4,%5,%6,%7}, {%8,%9}, {%0,%1,%2,%3};"       \
               : "+f"(d[0]), "+f"(d[1]), "+f"(d[2]), "+f"(d[3])              \
               : "r"(a[0]), "r"(a[1]), "r"(a[2]), "r"(a[3]),                 \
                 "r"(b[0]), "r"(b[1]))

#define LDSM4(r0, r1, r2, r3, addr)                                           \
  asm volatile("ldmatrix.sync.aligned.m8n8.x4.shared.b16 {%0,%1,%2,%3}, [%4];"\
               : "=r"(r0), "=r"(r1), "=r"(r2), "=r"(r3) : "r"(addr))

__device__ __forceinline__ uint32_t swz128(uint32_t off) {
    return off ^ ((off >> 3) & 0x70);   // SW128: conflict-free 128B rows
}

// ---------------- fp32 -> bf16 hi/lo, full-width 16B stores, x2 group ILP ----------
__global__ void cvt_split_kernel(const float* __restrict__ src,
                                 __nv_bfloat16* __restrict__ hi,
                                 __nv_bfloat16* __restrict__ lo, int n8) {
    const int stride = gridDim.x * blockDim.x;
    const int i0 = blockIdx.x * blockDim.x + threadIdx.x;
    float4 a[2], b[2];
    int k[2];
    bool ok[2];
#pragma unroll
    for (int j = 0; j < 2; j++) {
        k[j] = i0 + j * stride;
        ok[j] = k[j] < n8;
        if (ok[j]) {
            a[j] = ((const float4*)src)[2 * k[j]];
            b[j] = ((const float4*)src)[2 * k[j] + 1];
        }
    }
#pragma unroll
    for (int j = 0; j < 2; j++) {
        if (!ok[j]) continue;
        __nv_bfloat16 h[8], l[8];
        split1(a[j].x, h[0], l[0]); split1(a[j].y, h[1], l[1]);
        split1(a[j].z, h[2], l[2]); split1(a[j].w, h[3], l[3]);
        split1(b[j].x, h[4], l[4]); split1(b[j].y, h[5], l[5]);
        split1(b[j].z, h[6], l[6]); split1(b[j].w, h[7], l[7]);
        ((uint4*)hi)[k[j]] = *(uint4*)h;
        ((uint4*)lo)[k[j]] = *(uint4*)l;
    }
}
static inline int cvt_grid8(int n8) { return (n8 + 2 * 256 - 1) / (2 * 256); }

// ==== mma.sync NT GEMM: 128x64 tile, 256 threads (8 warps, 32x32), 2 CTAs/SM ====
#define APB (128 * 128)         // bytes per A operand per stage (128 rows x 128B)
#define BPB (64 * 128)          // bytes per B operand per stage (64 rows x 128B)
#define STG (2 * APB + 2 * BPB) // Ah|Al|Bh|Bl = 48 KB
#define OFF_AL APB
#define OFF_BH (2 * APB)
#define OFF_BL (2 * APB + BPB)
#define NSTAGE 2
#define GEMM_SMEM (NSTAGE * STG)  // 96 KB -> 2 CTAs/SM
#define GTHREADS 256

__global__ __launch_bounds__(GTHREADS, 2)
void tc_gemm(const __nv_bfloat16* __restrict__ Ah, const __nv_bfloat16* __restrict__ Al,
             const __nv_bfloat16* __restrict__ Wh, const __nv_bfloat16* __restrict__ Wl,
             float* __restrict__ C, int Nn, int Kk, int nchunk, size_t zstride,
             const float* __restrict__ epi_bias) {
    extern __shared__ __align__(1024) char dsm[];
    const uint32_t sbase = smem_u32(dsm);

    const int tid = threadIdx.x;
    const int lane = tid & 31;
    const int wid = tid >> 5;           // 0..7
    const int bm = blockIdx.y * 128;
    const int bn = blockIdx.x * 64;
    const int wm = (wid >> 1) * 32;     // 4 warp rows of 32
    const int wn = (wid & 1) * 32;      // 2 warp cols of 32
    const int qk = (lane & 3) * 2;
    const int lr = lane >> 2;

    const int chunkK = Kk / nchunk;
    const int kbase = blockIdx.z * chunkK;
    C += (size_t)blockIdx.z * zstride;

    auto load_stage = [&](int s, int kc) {
        const int k0 = kbase + kc * 64;
        const uint32_t stg = sbase + s * STG;
        // A operands: 128 rows x 8 chunks = 1024 -> 4 iters of 256
#pragma unroll
        for (int t = 0; t < 2; t++) {
            const __nv_bfloat16* sp = (t == 0) ? Ah : Al;
#pragma unroll
            for (int i = 0; i < 4; i++) {
                int idx = i * GTHREADS + tid;
                int row = idx >> 3, c = idx & 7;
                uint32_t dst = stg + t * APB + swz128((uint32_t)(row * 128 + c * 16));
                cp16(dst, sp + (size_t)(bm + row) * Kk + k0 + c * 8, true);
            }
        }
        // B operands: 64 rows x 8 chunks = 512 -> 2 iters of 256
#pragma unroll
        for (int t = 0; t < 2; t++) {
            const __nv_bfloat16* sp = (t == 0) ? Wh : Wl;
#pragma unroll
            for (int i = 0; i < 2; i++) {
                int idx = i * GTHREADS + tid;
                int row = idx >> 3, c = idx & 7;
                int gr = bn + row;
                bool ok = (gr < Nn);
                uint32_t dst = stg + OFF_BH + t * BPB + swz128((uint32_t)(row * 128 + c * 16));
                cp16(dst, sp + (size_t)gr * Kk + k0 + c * 8, ok);
            }
        }
    };

    float acc[2][4][4];
#pragma unroll
    for (int mt = 0; mt < 2; mt++)
#pragma unroll
        for (int nt = 0; nt < 4; nt++)
#pragma unroll
            for (int j = 0; j < 4; j++) acc[mt][nt][j] = 0.f;

    const int nk = chunkK / 64;

    load_stage(0, 0); cp_commit();
    if (nk > 1) load_stage(1, 1);
    cp_commit();

    const int rA = lane & 15;           // ldmatrix row within 16
    const int cHi = lane >> 4;          // ldmatrix chunk select (0/1)

    uint32_t aOff[2], bOff[2];
#pragma unroll
    for (int mt = 0; mt < 2; mt++)
        aOff[mt] = swz128((uint32_t)((wm + mt * 16 + rA) * 128)) ^ (uint32_t)(cHi * 16);
#pragma unroll
    for (int p = 0; p < 2; p++)
        bOff[p] = swz128((uint32_t)((wn + p * 16 + rA) * 128)) ^ (uint32_t)(cHi * 16);

    for (int kc = 0; kc < nk; kc++) {
        const int s = kc & 1;
        cp_wait1();
        __syncthreads();

        const uint32_t stg = sbase + s * STG;
#pragma unroll
        for (int ks = 0; ks < 4; ks++) {
            const uint32_t kx = (uint32_t)(ks * 32);
            // term 1: Ah x Bh
            uint32_t ah[2][4], bh[4][2];
#pragma unroll
            for (int mt = 0; mt < 2; mt++)
                LDSM4(ah[mt][0], ah[mt][1], ah[mt][2], ah[mt][3], stg + (aOff[mt] ^ kx));
#pragma unroll
            for (int p = 0; p < 2; p++) {
                uint32_t r0, r1, r2, r3;
                LDSM4(r0, r1, r2, r3, stg + OFF_BH + (bOff[p] ^ kx));
                bh[2*p][0] = r0; bh[2*p+1][0] = r1; bh[2*p][1] = r2; bh[2*p+1][1] = r3;
            }
#pragma unroll
            for (int mt = 0; mt < 2; mt++)
#pragma unroll
                for (int nt = 0; nt < 4; nt++)
                    MMA_BF16(acc[mt][nt], ah[mt], bh[nt]);

            // term 2: Al x Bh
            {
                uint32_t al[2][4];
#pragma unroll
                for (int mt = 0; mt < 2; mt++)
                    LDSM4(al[mt][0], al[mt][1], al[mt][2], al[mt][3],
                          stg + OFF_AL + (aOff[mt] ^ kx));
#pragma unroll
                for (int mt = 0; mt < 2; mt++)
#pragma unroll
                    for (int nt = 0; nt < 4; nt++)
                        MMA_BF16(acc[mt][nt], al[mt], bh[nt]);
            }

            // term 3: Ah x Bl
            {
                uint32_t bl[4][2];
#pragma unroll
                for (int p = 0; p < 2; p++) {
                    uint32_t r0, r1, r2, r3;
                    LDSM4(r0, r1, r2, r3, stg + OFF_BL + (bOff[p] ^ kx));
                    bl[2*p][0] = r0; bl[2*p+1][0] = r1; bl[2*p][1] = r2; bl[2*p+1][1] = r3;
                }
#pragma unroll
                for (int mt = 0; mt < 2; mt++)
#pragma unroll
                    for (int nt = 0; nt < 4; nt++)
                        MMA_BF16(acc[mt][nt], ah[mt], bl[nt]);
            }
        }
        __syncthreads();
        int kn = kc + NSTAGE;
        if (kn < nk) load_stage(s, kn);
        cp_commit();
    }

    const bool do_sp = (epi_bias != nullptr);
#pragma unroll
    for (int mt = 0; mt < 2; mt++) {
        int r = bm + wm + mt * 16 + lr;
#pragma unroll
        for (int nt = 0; nt < 4; nt++) {
            int c = bn + wn + nt * 8 + qk;
            if (c < Nn) {
                float v[4] = {acc[mt][nt][0], acc[mt][nt][1], acc[mt][nt][2], acc[mt][nt][3]};
                if (do_sp) {
                    float b0 = epi_bias[c], b1 = epi_bias[c + 1];
                    float x0 = v[0] + b0, x1 = v[1] + b1, x2 = v[2] + b0, x3 = v[3] + b1;
                    v[0] = (x0 > 20.f) ? x0 : log1pf(__expf(x0));
                    v[1] = (x1 > 20.f) ? x1 : log1pf(__expf(x1));
                    v[2] = (x2 > 20.f) ? x2 : log1pf(__expf(x2));
                    v[3] = (x3 > 20.f) ? x3 : log1pf(__expf(x3));
                }
                *(float2*)&C[(size_t)r * Nn + c] = make_float2(v[0], v[1]);
                *(float2*)&C[(size_t)(r + 8) * Nn + c] = make_float2(v[2], v[3]);
            }
        }
    }
}

// ---------------- depthwise causal conv(K=4) + bias + SiLU (+ bf16 split out) ------
__global__ void conv_silu_kernel(const float* __restrict__ cw, const float* __restrict__ cb) {
    int i = blockIdx.x * blockDim.x + threadIdx.x;
    if (i >= TT * DI) return;
    int d = i & (DI - 1);
    int t = i >> 12;
    int l = t & (LL - 1);
    int b = t >> 9;
    float acc = cb[d];
#pragma unroll
    for (int k = 0; k < KC; k++) {
        int li = l - (KC - 1) + k;
        if (li >= 0)
            acc = fmaf(g_proj[(size_t)(b * LL + li) * E2 + d], cw[d * KC + k], acc);
    }
    float s = acc / (1.f + __expf(-acc));
    g_h[i] = s;
    __nv_bfloat16 h, lo2; split1(s, h, lo2);
    c_h_h[i] = h; c_h_l[i] = lo2;
}

// ---------------- RMSNorm (reads split-K partials directly) ----------------
__global__ void rmsnorm_kernel(const float* __restrict__ dt_w,
                               const float* __restrict__ b_w,
                               const float* __restrict__ c_w) {
    int t = blockIdx.x;
    int tid = threadIdx.x;              // 128 threads

    float x = 0.f;
#pragma unroll
    for (int z = 0; z < XSPLIT; z++)
        x += g_ssm_part[(size_t)z * TT * NSSM + (size_t)t * NSSM + tid];

    float ss = x * x;
#pragma unroll
    for (int o = 16; o > 0; o >>= 1) ss += __shfl_xor_sync(0xffffffffu, ss, o);
    __shared__ float wsum[4];
    if ((tid & 31) == 0) wsum[tid >> 5] = ss;
    __syncthreads();
    float tot = wsum[0] + wsum[1] + wsum[2] + wsum[3];
    float scale = rsqrtf(tot * (1.f / RR) + 1e-6f);
    float o1 = x * scale * dt_w[tid];
    __nv_bfloat16 h, lo2; split1(o1, h, lo2);
    c_dtin_h[(size_t)t * RR + tid] = h;
    c_dtin_l[(size_t)t * RR + tid] = lo2;

    if (tid < 32) {
        int grp = tid >> 4;
        int n = tid & 15;
        float v = 0.f;
#pragma unroll
        for (int z = 0; z < XSPLIT; z++)
            v += g_ssm_part[(size_t)z * TT * NSSM + (size_t)t * NSSM + RR + grp * NN + n];
        float vs = v * v;
#pragma unroll
        for (int o = 8; o > 0; o >>= 1) vs += __shfl_xor_sync(0xffffffffu, vs, o);
        float sc = rsqrtf(vs * (1.f / NN) + 1e-6f);
        float w = grp ? c_w[n] : b_w[n];
        float outv = v * sc * w;
        if (grp == 0) g_Bn[(size_t)t * NN + n] = outv;
        else          g_Cn[(size_t)t * NN + n] = outv;
    }
}

// ================= chunked parallel scan =================
__global__ void scan_pass1(const float* __restrict__ A_log) {
    int bx = blockIdx.x;
    int db = bx % DBLK; int tmp = bx / DBLK;
    int c = tmp % CC;   int b = tmp / CC;
    int d = db * 64 + threadIdx.x;

    float Av[NN];
#pragma unroll
    for (int n = 0; n < NN; n++) Av[n] = -__expf(A_log[d * NN + n]);
    float st[NN], P[NN];
#pragma unroll
    for (int n = 0; n < NN; n++) { st[n] = 0.f; P[n] = 1.f; }

    const int l0 = c * CLEN;
    for (int l = l0; l < l0 + CLEN; l++) {
        int t = b * LL + l;
        float dtv = g_dt[(size_t)t * DI + d];
        float hv  = g_h [(size_t)t * DI + d];
        const float4* Bp = (const float4*)(g_Bn + (size_t)t * NN);
        float4 B4[4] = { Bp[0], Bp[1], Bp[2], Bp[3] };
        const float* Bv = (const float*)B4;
        float dh = dtv * hv;
#pragma unroll
        for (int n = 0; n < NN; n++) {
            float dA = __expf(dtv * Av[n]);
            st[n] = fmaf(st[n], dA, dh * Bv[n]);
            P[n] *= dA;
        }
    }
    size_t base = ((size_t)(b * CC + c) * DI + d) * NN;
#pragma unroll
    for (int n = 0; n < NN; n += 4) {
        *(float4*)&g_scP[base + n] = make_float4(P[n], P[n+1], P[n+2], P[n+3]);
        *(float4*)&g_scS[base + n] = make_float4(st[n], st[n+1], st[n+2], st[n+3]);
    }
}

__global__ void scan_combine() {
    int bx = blockIdx.x;                 // BB*DBLK blocks
    int db = bx % DBLK; int b = bx / DBLK;
    int d = db * 64 + threadIdx.x;

    float s[NN];
#pragma unroll
    for (int n = 0; n < NN; n++) s[n] = 0.f;

    for (int c = 0; c < CC; c++) {
        size_t base = ((size_t)(b * CC + c) * DI + d) * NN;
#pragma unroll
        for (int n = 0; n < NN; n += 4)
            *(float4*)&g_scI[base + n] = make_float4(s[n], s[n+1], s[n+2], s[n+3]);
        float P[NN], S[NN];
#pragma unroll
        for (int n = 0; n < NN; n += 4) {
            float4 p4 = *(const float4*)&g_scP[base + n];
            float4 s4 = *(const float4*)&g_scS[base + n];
            P[n] = p4.x; P[n+1] = p4.y; P[n+2] = p4.z; P[n+3] = p4.w;
            S[n] = s4.x; S[n+1] = s4.y; S[n+2] = s4.z; S[n+3] = s4.w;
        }
#pragma unroll
        for (int n = 0; n < NN; n++) s[n] = fmaf(P[n], s[n], S[n]);
    }
}

__global__ void scan_pass2(const float* __restrict__ A_log,
                           const float* __restrict__ D_param) {
    int bx = blockIdx.x;
    int db = bx % DBLK; int tmp = bx / DBLK;
    int c = tmp % CC;   int b = tmp / CC;
    int d = db * 64 + threadIdx.x;

    float Av[NN];
#pragma unroll
    for (int n = 0; n < NN; n++) Av[n] = -__expf(A_log[d * NN + n]);
    float st[NN];
    {
        size_t base = ((size_t)(b * CC + c) * DI + d) * NN;
#pragma unroll
        for (int n = 0; n < NN; n += 4) {
            float4 v = *(const float4*)&g_scI[base + n];
            st[n] = v.x; st[n+1] = v.y; st[n+2] = v.z; st[n+3] = v.w;
        }
    }
    const float Dv = D_param[d];

    const int l0 = c * CLEN;
    for (int l = l0; l < l0 + CLEN; l++) {
        int t = b * LL + l;
        float dtv = g_dt[(size_t)t * DI + d];
        float hv  = g_h [(size_t)t * DI + d];
        float gv  = g_proj[(size_t)t * E2 + DI + d];
        const float4* Bp = (const float4*)(g_Bn + (size_t)t * NN);
        const float4* Cp = (const float4*)(g_Cn + (size_t)t * NN);
        float4 B4[4] = { Bp[0], Bp[1], Bp[2], Bp[3] };
        float4 C4[4] = { Cp[0], Cp[1], Cp[2], Cp[3] };
        const float* Bv = (const float*)B4;
        const float* Cv = (const float*)C4;
        float dh = dtv * hv;
        float yv = 0.f;
#pragma unroll
        for (int n = 0; n < NN; n++) {
            float dA = __expf(dtv * Av[n]);
            st[n] = fmaf(st[n], dA, dh * Bv[n]);
            yv = fmaf(st[n], Cv[n], yv);
        }
        float sg = gv / (1.f + __expf(-gv));
        float yo = (yv + hv * Dv) * sg;
        __nv_bfloat16 h, lo2; split1(yo, h, lo2);
        c_y_h[(size_t)t * DI + d] = h;
        c_y_l[(size_t)t * DI + d] = lo2;
    }
}

// ---------------- launch ----------------
extern "C" void kernel_launch(void* const* d_in, const int* in_sizes, int n_in,
                              void* d_out, int out_size) {
    const float* hs        = (const float*)d_in[0];
    const float* in_proj_w = (const float*)d_in[1];
    const float* conv_w    = (const float*)d_in[2];
    const float* conv_b    = (const float*)d_in[3];
    const float* x_proj_w  = (const float*)d_in[4];
    const float* dt_ln_w   = (const float*)d_in[5];
    const float* b_ln_w    = (const float*)d_in[6];
    const float* c_ln_w    = (const float*)d_in[7];
    const float* dt_proj_w = (const float*)d_in[8];
    const float* dt_proj_b = (const float*)d_in[9];
    const float* A_log     = (const float*)d_in[10];
    const float* D_param   = (const float*)d_in[11];
    const float* out_proj_w= (const float*)d_in[12];
    float* out = (float*)d_out;

    cudaFuncSetAttribute(tc_gemm, cudaFuncAttributeMaxDynamicSharedMemorySize, GEMM_SMEM);

    float *p_proj, *p_part, *p_dt;
    cudaGetSymbolAddress((void**)&p_proj, g_proj);
    cudaGetSymbolAddress((void**)&p_part, g_ssm_part);
    cudaGetSymbolAddress((void**)&p_dt,   g_dt);
    __nv_bfloat16 *hs_h, *hs_l, *inw_h, *inw_l, *h_h, *h_l, *xw_h, *xw_l;
    __nv_bfloat16 *dtin_h, *dtin_l, *dtw_h, *dtw_l, *y_h, *y_l, *ow_h, *ow_l;
    cudaGetSymbolAddress((void**)&hs_h, c_hs_h);   cudaGetSymbolAddress((void**)&hs_l, c_hs_l);
    cudaGetSymbolAddress((void**)&inw_h, c_inw_h); cudaGetSymbolAddress((void**)&inw_l, c_inw_l);
    cudaGetSymbolAddress((void**)&h_h, c_h_h);     cudaGetSymbolAddress((void**)&h_l, c_h_l);
    cudaGetSymbolAddress((void**)&xw_h, c_xw_h);   cudaGetSymbolAddress((void**)&xw_l, c_xw_l);
    cudaGetSymbolAddress((void**)&dtin_h, c_dtin_h); cudaGetSymbolAddress((void**)&dtin_l, c_dtin_l);
    cudaGetSymbolAddress((void**)&dtw_h, c_dtw_h); cudaGetSymbolAddress((void**)&dtw_l, c_dtw_l);
    cudaGetSymbolAddress((void**)&y_h, c_y_h);     cudaGetSymbolAddress((void**)&y_l, c_y_l);
    cudaGetSymbolAddress((void**)&ow_h, c_ow_h);   cudaGetSymbolAddress((void**)&ow_l, c_ow_l);

    // splits needed by in_proj + x_proj
    cvt_split_kernel<<<cvt_grid8(TT*HH/8), 256>>>(hs, hs_h, hs_l, TT*HH/8);
    cvt_split_kernel<<<cvt_grid8(E2*HH/8), 256>>>(in_proj_w, inw_h, inw_l, E2*HH/8);
    cvt_split_kernel<<<cvt_grid8(NSSM*DI/8), 256>>>(x_proj_w, xw_h, xw_l, NSSM*DI/8);

    // in_proj GEMM
    tc_gemm<<<dim3(E2/64, TT/128, 1), GTHREADS, GEMM_SMEM>>>(hs_h, hs_l, inw_h, inw_l,
                                                             p_proj, E2, HH, 1, 0, nullptr);

    // depthwise conv + silu -> g_h (+ split)
    conv_silu_kernel<<<(TT*DI + 255)/256, 256>>>(conv_w, conv_b);

    // x_proj split-K x8
    tc_gemm<<<dim3((NSSM + 63)/64, TT/128, XSPLIT), GTHREADS, GEMM_SMEM>>>(
        h_h, h_l, xw_h, xw_l, p_part, NSSM, DI, XSPLIT, (size_t)TT * NSSM, nullptr);

    // dt_proj_w split
    cvt_split_kernel<<<cvt_grid8(DI*RR/8), 256>>>(dt_proj_w, dtw_h, dtw_l, DI*RR/8);

    // rmsnorms (fused split-K reduce)
    rmsnorm_kernel<<<TT, 128>>>(dt_ln_w, b_ln_w, c_ln_w);

    // dt_proj GEMM, bias+softplus fused
    tc_gemm<<<dim3(DI/64, TT/128, 1), GTHREADS, GEMM_SMEM>>>(dtin_h, dtin_l, dtw_h, dtw_l,
                                                             p_dt, DI, RR, 1, 0, dt_proj_b);

    // chunked scan: pass1 -> combine -> pass2
    scan_pass1<<<BB * CC * DBLK, 64>>>(A_log);
    scan_combine<<<BB * DBLK, 64>>>();
    scan_pass2<<<BB * CC * DBLK, 64>>>(A_log, D_param);

    // out_proj_w split
    cvt_split_kernel<<<cvt_grid8(HH*DI/8), 256>>>(out_proj_w, ow_h, ow_l, HH*DI/8);

    // out_proj GEMM
    tc_gemm<<<dim3(HH/64, TT/128, 1), GTHREADS, GEMM_SMEM>>>(y_h, y_l, ow_h, ow_l,
                                                             out, HH, DI, 1, 0, nullptr);
}